// round 1
// baseline (speedup 1.0000x reference)
#include <cuda_runtime.h>
#include <math.h>

#define Bc    16
#define Cc    384
#define HEADS 12
#define HIDc  1536
#define Tt    65536          // total tokens = 16*64*64
#define EPSf  1e-5f

// ---------------- scratch (device globals; no allocation) ----------------
__device__ float g_xw [(size_t)Tt * Cc];        // windowed LN1 output; later: proj output
__device__ float g_qkv[(size_t)Tt * 3 * Cc];    // qkv
__device__ float g_at [(size_t)Tt * Cc];        // attention output; later: LN2 output h
__device__ float g_x1 [(size_t)Tt * Cc];        // x + attn branch (residual for the end)
__device__ float g_z1 [(size_t)Tt * HIDc];      // fc1 output (post BN+GELU)
__device__ float g_z2 [(size_t)Tt * HIDc];      // dwconv output (post BN+GELU)

__device__ __forceinline__ float gelu_exact(float v) {
    return 0.5f * v * (1.0f + erff(v * 0.70710678118654752f));
}
__device__ __forceinline__ float warp_sum(float v) {
#pragma unroll
    for (int o = 16; o; o >>= 1) v += __shfl_xor_sync(0xffffffffu, v, o);
    return v;
}

// ---------------- 1) LN1 + roll(-4,-4) + window partition ----------------
// dest row t = win*64 + n ; win = b*64 + wh*8 + ww ; n = i*8 + j
// source pixel: r = (wh*8+i+4)&63 , c = (ww*8+j+4)&63
__global__ void __launch_bounds__(256) ln1_shift_win(
        const float* __restrict__ x, const float* __restrict__ g,
        const float* __restrict__ b, float* __restrict__ xw) {
    int warp = threadIdx.x >> 5, lane = threadIdx.x & 31;
    int t = blockIdx.x * 8 + warp;
    int win = t >> 6, n = t & 63;
    int bi = win >> 6, wim = win & 63;
    int r = (((wim >> 3) << 3) + (n >> 3) + 4) & 63;
    int c = (((wim & 7) << 3) + (n & 7) + 4) & 63;
    const float* row = x + ((size_t)bi * 4096 + r * 64 + c) * Cc;
    float v[12]; float s = 0.f;
#pragma unroll
    for (int k = 0; k < 12; k++) { v[k] = row[lane + 32 * k]; s += v[k]; }
    s = warp_sum(s);
    float mean = s * (1.f / 384.f);
    float q = 0.f;
#pragma unroll
    for (int k = 0; k < 12; k++) { float d = v[k] - mean; q += d * d; }
    q = warp_sum(q);
    float rstd = rsqrtf(q * (1.f / 384.f) + EPSf);
    float* o = xw + (size_t)t * Cc;
#pragma unroll
    for (int k = 0; k < 12; k++) {
        int idx = lane + 32 * k;
        o[idx] = (v[k] - mean) * rstd * g[idx] + b[idx];
    }
}

// ---------------- 5) un-window + roll(+4,+4) + residual + LN2 ----------------
__global__ void __launch_bounds__(256) resid_ln2(
        const float* __restrict__ x, const float* __restrict__ proj,
        const float* __restrict__ g, const float* __restrict__ b,
        float* __restrict__ x1, float* __restrict__ h) {
    int warp = threadIdx.x >> 5, lane = threadIdx.x & 31;
    int t = blockIdx.x * 8 + warp;
    int bi = t >> 12, l = t & 4095;
    int r = l >> 6, c = l & 63;
    int sr = (r - 4) & 63, sc = (c - 4) & 63;
    int win = bi * 64 + ((sr >> 3) << 3) + (sc >> 3);
    int nn = ((sr & 7) << 3) + (sc & 7);
    const float* pr = proj + ((size_t)win * 64 + nn) * Cc;
    const float* xr = x + (size_t)t * Cc;
    float* xo = x1 + (size_t)t * Cc;
    float v[12]; float s = 0.f;
#pragma unroll
    for (int k = 0; k < 12; k++) {
        int idx = lane + 32 * k;
        v[k] = xr[idx] + pr[idx];
        xo[idx] = v[k];
        s += v[k];
    }
    s = warp_sum(s);
    float mean = s * (1.f / 384.f);
    float q = 0.f;
#pragma unroll
    for (int k = 0; k < 12; k++) { float d = v[k] - mean; q += d * d; }
    q = warp_sum(q);
    float rstd = rsqrtf(q * (1.f / 384.f) + EPSf);
    float* o = h + (size_t)t * Cc;
#pragma unroll
    for (int k = 0; k < 12; k++) {
        int idx = lane + 32 * k;
        o[idx] = (v[k] - mean) * rstd * g[idx] + b[idx];
    }
}

// ---------------- 3) windowed attention (one block per window,head) ----------------
__global__ void __launch_bounds__(64) attn_win(
        const float* __restrict__ qkv, const float* __restrict__ rpb,
        float* __restrict__ outp) {
    int win = blockIdx.x, head = blockIdx.y;
    int n = threadIdx.x;
    __shared__ float ks[64][32];
    __shared__ float vsm[64][32];
    __shared__ int labs[64];
    size_t base = ((size_t)win * 64 + n) * (3 * Cc);
    int ho = head * 32;
    const float SC = 0.17677669529663687f;   // 1/sqrt(32)
    float q[32];
#pragma unroll
    for (int d = 0; d < 32; d += 4) {
        float4 a = *(const float4*)(qkv + base + ho + d);
        q[d] = a.x * SC; q[d + 1] = a.y * SC; q[d + 2] = a.z * SC; q[d + 3] = a.w * SC;
        float4 kk = *(const float4*)(qkv + base + Cc + ho + d);
        ks[n][d] = kk.x; ks[n][d + 1] = kk.y; ks[n][d + 2] = kk.z; ks[n][d + 3] = kk.w;
        float4 vv = *(const float4*)(qkv + base + 2 * Cc + ho + d);
        vsm[n][d] = vv.x; vsm[n][d + 1] = vv.y; vsm[n][d + 2] = vv.z; vsm[n][d + 3] = vv.w;
    }
    // shift-mask region label of this token (coords are in the shifted image)
    int wim = win & 63;
    int gr = ((wim >> 3) << 3) + (n >> 3);
    int gc = ((wim & 7) << 3) + (n & 7);
    labs[n] = (gr < 56 ? 0 : (gr < 60 ? 1 : 2)) * 3 + (gc < 56 ? 0 : (gc < 60 ? 1 : 2));
    __syncthreads();

    int cvn = 15 * (n >> 3) + (n & 7);
    int myl = labs[n];
    float s[64];
    float mx = -1e30f;
#pragma unroll
    for (int m = 0; m < 64; m++) {
        float a = 0.f;
#pragma unroll
        for (int d = 0; d < 32; d++) a += q[d] * ks[m][d];
        int mm = 63 - m;
        int cvm = 15 * (mm >> 3) + (mm & 7);
        a += rpb[(cvn + cvm) * HEADS + head];
        a += (labs[m] != myl) ? -100.f : 0.f;
        s[m] = a;
        mx = fmaxf(mx, a);
    }
    float sum = 0.f;
#pragma unroll
    for (int m = 0; m < 64; m++) { float e = __expf(s[m] - mx); s[m] = e; sum += e; }
    float inv = 1.f / sum;
    float* orow = outp + ((size_t)win * 64 + n) * Cc + ho;
#pragma unroll 4
    for (int d = 0; d < 32; d++) {
        float a = 0.f;
#pragma unroll
        for (int m = 0; m < 64; m++) a += s[m] * vsm[m][d];
        orow[d] = a * inv;
    }
}

// ---------------- tiled SGEMM: C[M,N] = A[M,K] @ W[N,K]^T (+ epilogue) ----------------
// MODE 0: +bias    MODE 1: gelu(bn(+bias))    MODE 2: res + gelu(bn(+bias))
template <int MODE>
__global__ void __launch_bounds__(256) sgemm(
        const float* __restrict__ A, const float* __restrict__ Wt,
        float* __restrict__ Co, const float* __restrict__ bias,
        const float* __restrict__ bng, const float* __restrict__ bnb,
        const float* __restrict__ res, int M, int Nn, int K) {
    __shared__ float As[8][128];
    __shared__ float Bs[8][128];
    int tid = threadIdx.x;
    int tm = tid >> 4, tn = tid & 15;
    int arow = tid >> 1, acol = (tid & 1) * 4;
    const float* Ap = A  + ((size_t)(blockIdx.y * 128 + arow)) * K + acol;
    const float* Bp = Wt + ((size_t)(blockIdx.x * 128 + arow)) * K + acol;
    float acc[8][8];
#pragma unroll
    for (int i = 0; i < 8; i++)
#pragma unroll
        for (int j = 0; j < 8; j++) acc[i][j] = 0.f;

    for (int k0 = 0; k0 < K; k0 += 8) {
        float4 va = *(const float4*)(Ap + k0);
        float4 vb = *(const float4*)(Bp + k0);
        As[acol][arow] = va.x; As[acol + 1][arow] = va.y;
        As[acol + 2][arow] = va.z; As[acol + 3][arow] = va.w;
        Bs[acol][arow] = vb.x; Bs[acol + 1][arow] = vb.y;
        Bs[acol + 2][arow] = vb.z; Bs[acol + 3][arow] = vb.w;
        __syncthreads();
#pragma unroll
        for (int kk = 0; kk < 8; kk++) {
            float ra[8], rb[8];
#pragma unroll
            for (int i = 0; i < 8; i++) ra[i] = As[kk][tm * 8 + i];
#pragma unroll
            for (int j = 0; j < 8; j++) rb[j] = Bs[kk][tn * 8 + j];
#pragma unroll
            for (int i = 0; i < 8; i++)
#pragma unroll
                for (int j = 0; j < 8; j++) acc[i][j] += ra[i] * rb[j];
        }
        __syncthreads();
    }
    const float IS = rsqrtf(1.0f + EPSf);
#pragma unroll
    for (int i = 0; i < 8; i++) {
        int m = blockIdx.y * 128 + tm * 8 + i;
#pragma unroll
        for (int j = 0; j < 8; j++) {
            int nn = blockIdx.x * 128 + tn * 8 + j;
            float v = acc[i][j] + bias[nn];
            if (MODE >= 1) v = gelu_exact(v * (bng[nn] * IS) + bnb[nn]);
            if (MODE == 2) v += res[(size_t)m * Nn + nn];
            Co[(size_t)m * Nn + nn] = v;
        }
    }
}

// ---------------- 7) NHWC depthwise 3x3 + BN + GELU ----------------
__global__ void __launch_bounds__(256) dwconv_bn_gelu(
        const float* __restrict__ z1, const float* __restrict__ wt,
        const float* __restrict__ wb, const float* __restrict__ bng,
        const float* __restrict__ bnb, float* __restrict__ z2) {
    int idx = blockIdx.x * 256 + threadIdx.x;        // over T * (HID/4)
    int c4 = idx % 384;
    int pix = idx / 384;
    int bi = pix >> 12; int rc = pix & 4095;
    int r = rc >> 6, c = rc & 63;
    int ch = c4 * 4;
    float wr[4][9];
#pragma unroll
    for (int l = 0; l < 4; l++)
#pragma unroll
        for (int k = 0; k < 9; k++) wr[l][k] = wt[(ch + l) * 9 + k];
    float4 acc = make_float4(0.f, 0.f, 0.f, 0.f);
#pragma unroll
    for (int dr = -1; dr <= 1; dr++) {
        int rr = r + dr;
        if (rr < 0 || rr > 63) continue;
#pragma unroll
        for (int dc = -1; dc <= 1; dc++) {
            int cc = c + dc;
            if (cc < 0 || cc > 63) continue;
            float4 v = *(const float4*)(z1 + ((size_t)(bi * 4096 + rr * 64 + cc)) * HIDc + ch);
            int k = (dr + 1) * 3 + (dc + 1);
            acc.x += v.x * wr[0][k];
            acc.y += v.y * wr[1][k];
            acc.z += v.z * wr[2][k];
            acc.w += v.w * wr[3][k];
        }
    }
    const float IS = rsqrtf(1.0f + EPSf);
    float4 o;
    o.x = gelu_exact((acc.x + wb[ch + 0]) * (bng[ch + 0] * IS) + bnb[ch + 0]);
    o.y = gelu_exact((acc.y + wb[ch + 1]) * (bng[ch + 1] * IS) + bnb[ch + 1]);
    o.z = gelu_exact((acc.z + wb[ch + 2]) * (bng[ch + 2] * IS) + bnb[ch + 2]);
    o.w = gelu_exact((acc.w + wb[ch + 3]) * (bng[ch + 3] * IS) + bnb[ch + 3]);
    *(float4*)(z2 + (size_t)pix * HIDc + ch) = o;
}

// ---------------- launcher ----------------
extern "C" void kernel_launch(void* const* d_in, const int* in_sizes, int n_in,
                              void* d_out, int out_size) {
    (void)in_sizes; (void)n_in; (void)out_size;
    const float* x      = (const float*)d_in[0];
    // d_in[1] = H, d_in[2] = W (int scalars, constants here)
    const float* ln1_g  = (const float*)d_in[3];
    const float* ln1_b  = (const float*)d_in[4];
    const float* qkv_w  = (const float*)d_in[5];
    const float* qkv_b  = (const float*)d_in[6];
    const float* rpb    = (const float*)d_in[7];
    const float* proj_w = (const float*)d_in[8];
    const float* proj_b = (const float*)d_in[9];
    const float* ln2_g  = (const float*)d_in[10];
    const float* ln2_b  = (const float*)d_in[11];
    const float* fc1_w  = (const float*)d_in[12];
    const float* fc1_b  = (const float*)d_in[13];
    const float* bn1_g  = (const float*)d_in[14];
    const float* bn1_b  = (const float*)d_in[15];
    const float* dw_w   = (const float*)d_in[16];
    const float* dw_b   = (const float*)d_in[17];
    const float* bn2_g  = (const float*)d_in[18];
    const float* bn2_b  = (const float*)d_in[19];
    const float* fc2_w  = (const float*)d_in[20];
    const float* fc2_b  = (const float*)d_in[21];
    const float* bn3_g  = (const float*)d_in[22];
    const float* bn3_b  = (const float*)d_in[23];
    float* out = (float*)d_out;

    float *xw, *qkvb, *at, *x1, *z1, *z2;
    cudaGetSymbolAddress((void**)&xw,   g_xw);
    cudaGetSymbolAddress((void**)&qkvb, g_qkv);
    cudaGetSymbolAddress((void**)&at,   g_at);
    cudaGetSymbolAddress((void**)&x1,   g_x1);
    cudaGetSymbolAddress((void**)&z1,   g_z1);
    cudaGetSymbolAddress((void**)&z2,   g_z2);

    // 1) LN1 + shift + window
    ln1_shift_win<<<Tt / 8, 256>>>(x, ln1_g, ln1_b, xw);
    // 2) qkv GEMM: [T,384] x [1152,384]^T
    sgemm<0><<<dim3(1152 / 128, Tt / 128), 256>>>(xw, qkv_w, qkvb, qkv_b,
                                                  nullptr, nullptr, nullptr, Tt, 1152, Cc);
    // 3) attention
    attn_win<<<dim3(1024, HEADS), 64>>>(qkvb, rpb, at);
    // 4) proj GEMM (writes into xw, which is free now)
    sgemm<0><<<dim3(384 / 128, Tt / 128), 256>>>(at, proj_w, xw, proj_b,
                                                 nullptr, nullptr, nullptr, Tt, Cc, Cc);
    // 5) un-window + residual + LN2 (h reuses the attention buffer)
    resid_ln2<<<Tt / 8, 256>>>(x, xw, ln2_g, ln2_b, x1, at);
    // 6) fc1 GEMM + BN + GELU
    sgemm<1><<<dim3(HIDc / 128, Tt / 128), 256>>>(at, fc1_w, z1, fc1_b,
                                                  bn1_g, bn1_b, nullptr, Tt, HIDc, Cc);
    // 7) depthwise 3x3 + BN + GELU
    dwconv_bn_gelu<<<(Tt * (HIDc / 4)) / 256, 256>>>(z1, dw_w, dw_b, bn2_g, bn2_b, z2);
    // 8) fc2 GEMM + BN + GELU + residual -> final output
    sgemm<2><<<dim3(384 / 128, Tt / 128), 256>>>(z2, fc2_w, out, fc2_b,
                                                 bn3_g, bn3_b, x1, Tt, Cc, HIDc);
}

// round 2
// speedup vs baseline: 2.2075x; 2.2075x over previous
#include <cuda_runtime.h>
#include <math.h>
#include <mma.h>

using namespace nvcuda;

#define Bc    16
#define Cc    384
#define HEADS 12
#define HIDc  1536
#define Tt    65536          // total tokens = 16*64*64
#define EPSf  1e-5f

#define LDA   40             // 32 k + 8 pad
#define LDC   132            // 128 + 4 pad
#define SMEMB (4 * 128 * LDA * 4)   // 81920 bytes (2 stages x {A,B}); C tile (128*132*4) fits inside

// ---------------- scratch (device globals; no allocation) ----------------
__device__ float g_xw [(size_t)Tt * Cc];        // windowed LN1 output; later: proj output
__device__ float g_qkv[(size_t)Tt * 3 * Cc];    // qkv
__device__ float g_at [(size_t)Tt * Cc];        // attention output; later: LN2 output h
__device__ float g_x1 [(size_t)Tt * Cc];        // x + attn branch (residual for the end)
__device__ float g_z1 [(size_t)Tt * HIDc];      // fc1 output (post BN+GELU)
__device__ float g_z2 [(size_t)Tt * HIDc];      // dwconv output (post BN+GELU)

__device__ __forceinline__ float gelu_exact(float v) {
    return 0.5f * v * (1.0f + erff(v * 0.70710678118654752f));
}
__device__ __forceinline__ float warp_sum(float v) {
#pragma unroll
    for (int o = 16; o; o >>= 1) v += __shfl_xor_sync(0xffffffffu, v, o);
    return v;
}
__device__ __forceinline__ float t32(float x) { return wmma::__float_to_tf32(x); }

// ---------------- 1) LN1 + roll(-4,-4) + window partition ----------------
__global__ void __launch_bounds__(256) ln1_shift_win(
        const float* __restrict__ x, const float* __restrict__ g,
        const float* __restrict__ b, float* __restrict__ xw) {
    int warp = threadIdx.x >> 5, lane = threadIdx.x & 31;
    int t = blockIdx.x * 8 + warp;
    int win = t >> 6, n = t & 63;
    int bi = win >> 6, wim = win & 63;
    int r = (((wim >> 3) << 3) + (n >> 3) + 4) & 63;
    int c = (((wim & 7) << 3) + (n & 7) + 4) & 63;
    const float* row = x + ((size_t)bi * 4096 + r * 64 + c) * Cc;
    float v[12]; float s = 0.f;
#pragma unroll
    for (int k = 0; k < 12; k++) { v[k] = row[lane + 32 * k]; s += v[k]; }
    s = warp_sum(s);
    float mean = s * (1.f / 384.f);
    float q = 0.f;
#pragma unroll
    for (int k = 0; k < 12; k++) { float d = v[k] - mean; q += d * d; }
    q = warp_sum(q);
    float rstd = rsqrtf(q * (1.f / 384.f) + EPSf);
    float* o = xw + (size_t)t * Cc;
#pragma unroll
    for (int k = 0; k < 12; k++) {
        int idx = lane + 32 * k;
        o[idx] = (v[k] - mean) * rstd * g[idx] + b[idx];
    }
}

// ---------------- 5) un-window + roll(+4,+4) + residual + LN2 ----------------
__global__ void __launch_bounds__(256) resid_ln2(
        const float* __restrict__ x, const float* __restrict__ proj,
        const float* __restrict__ g, const float* __restrict__ b,
        float* __restrict__ x1, float* __restrict__ h) {
    int warp = threadIdx.x >> 5, lane = threadIdx.x & 31;
    int t = blockIdx.x * 8 + warp;
    int bi = t >> 12, l = t & 4095;
    int r = l >> 6, c = l & 63;
    int sr = (r - 4) & 63, sc = (c - 4) & 63;
    int win = bi * 64 + ((sr >> 3) << 3) + (sc >> 3);
    int nn = ((sr & 7) << 3) + (sc & 7);
    const float* pr = proj + ((size_t)win * 64 + nn) * Cc;
    const float* xr = x + (size_t)t * Cc;
    float* xo = x1 + (size_t)t * Cc;
    float v[12]; float s = 0.f;
#pragma unroll
    for (int k = 0; k < 12; k++) {
        int idx = lane + 32 * k;
        v[k] = xr[idx] + pr[idx];
        xo[idx] = v[k];
        s += v[k];
    }
    s = warp_sum(s);
    float mean = s * (1.f / 384.f);
    float q = 0.f;
#pragma unroll
    for (int k = 0; k < 12; k++) { float d = v[k] - mean; q += d * d; }
    q = warp_sum(q);
    float rstd = rsqrtf(q * (1.f / 384.f) + EPSf);
    float* o = h + (size_t)t * Cc;
#pragma unroll
    for (int k = 0; k < 12; k++) {
        int idx = lane + 32 * k;
        o[idx] = (v[k] - mean) * rstd * g[idx] + b[idx];
    }
}

// ---------------- 3) windowed attention (one block per window,head) ----------------
__global__ void __launch_bounds__(64) attn_win(
        const float* __restrict__ qkv, const float* __restrict__ rpb,
        float* __restrict__ outp) {
    int win = blockIdx.x, head = blockIdx.y;
    int n = threadIdx.x;
    __shared__ float ks[64][32];
    __shared__ float vsm[64][32];
    __shared__ int labs[64];
    size_t base = ((size_t)win * 64 + n) * (3 * Cc);
    int ho = head * 32;
    const float SC = 0.17677669529663687f;   // 1/sqrt(32)
    float q[32];
#pragma unroll
    for (int d = 0; d < 32; d += 4) {
        float4 a = *(const float4*)(qkv + base + ho + d);
        q[d] = a.x * SC; q[d + 1] = a.y * SC; q[d + 2] = a.z * SC; q[d + 3] = a.w * SC;
        float4 kk = *(const float4*)(qkv + base + Cc + ho + d);
        ks[n][d] = kk.x; ks[n][d + 1] = kk.y; ks[n][d + 2] = kk.z; ks[n][d + 3] = kk.w;
        float4 vv = *(const float4*)(qkv + base + 2 * Cc + ho + d);
        vsm[n][d] = vv.x; vsm[n][d + 1] = vv.y; vsm[n][d + 2] = vv.z; vsm[n][d + 3] = vv.w;
    }
    int wim = win & 63;
    int gr = ((wim >> 3) << 3) + (n >> 3);
    int gc = ((wim & 7) << 3) + (n & 7);
    labs[n] = (gr < 56 ? 0 : (gr < 60 ? 1 : 2)) * 3 + (gc < 56 ? 0 : (gc < 60 ? 1 : 2));
    __syncthreads();

    int cvn = 15 * (n >> 3) + (n & 7);
    int myl = labs[n];
    float s[64];
    float mx = -1e30f;
#pragma unroll
    for (int m = 0; m < 64; m++) {
        float a = 0.f;
#pragma unroll
        for (int d = 0; d < 32; d++) a += q[d] * ks[m][d];
        int mm = 63 - m;
        int cvm = 15 * (mm >> 3) + (mm & 7);
        a += rpb[(cvn + cvm) * HEADS + head];
        a += (labs[m] != myl) ? -100.f : 0.f;
        s[m] = a;
        mx = fmaxf(mx, a);
    }
    float sum = 0.f;
#pragma unroll
    for (int m = 0; m < 64; m++) { float e = __expf(s[m] - mx); s[m] = e; sum += e; }
    float inv = 1.f / sum;
    float* orow = outp + ((size_t)win * 64 + n) * Cc + ho;
#pragma unroll 4
    for (int d = 0; d < 32; d++) {
        float a = 0.f;
#pragma unroll
        for (int m = 0; m < 64; m++) a += s[m] * vsm[m][d];
        orow[d] = a * inv;
    }
}

// ---------------- TF32 tensor-core GEMM: C[M,N] = A[M,K] @ W[N,K]^T (+ epilogue) ----------------
// MODE 0: +bias    MODE 1: gelu(bn(+bias))    MODE 2: res + gelu(bn(+bias))
// 128x128 block tile, K-step 32, 8 warps each computing 64x32 via m16n16k8 tf32 wmma.
template <int MODE>
__global__ void __launch_bounds__(256) tgemm(
        const float* __restrict__ A, const float* __restrict__ Wt,
        float* __restrict__ Co, const float* __restrict__ bias,
        const float* __restrict__ bng, const float* __restrict__ bnb,
        const float* __restrict__ res, int M, int Nn, int K) {
    extern __shared__ float sm[];
    float* As0 = sm;
    float* As1 = sm + 128 * LDA;
    float* Bs0 = sm + 2 * 128 * LDA;
    float* Bs1 = sm + 3 * 128 * LDA;
    float* Abuf[2] = { As0, As1 };
    float* Bbuf[2] = { Bs0, Bs1 };

    int tid = threadIdx.x;
    int warp = tid >> 5;
    int wm = warp >> 2;          // 0..1  -> 64 rows
    int wn = warp & 3;           // 0..3  -> 32 cols
    int rowA = blockIdx.y * 128;
    int rowB = blockIdx.x * 128;

    wmma::fragment<wmma::accumulator, 16, 16, 8, float> acc[4][2];
#pragma unroll
    for (int i = 0; i < 4; i++)
#pragma unroll
        for (int j = 0; j < 2; j++) wmma::fill_fragment(acc[i][j], 0.f);

    float4 ra[4], rb[4];
    // prologue: load k-tile 0
#pragma unroll
    for (int r = 0; r < 4; r++) {
        int id = tid + 256 * r;
        int row = id >> 3, q = (id & 7) * 4;
        ra[r] = *(const float4*)(A  + (size_t)(rowA + row) * K + q);
        rb[r] = *(const float4*)(Wt + (size_t)(rowB + row) * K + q);
    }
#pragma unroll
    for (int r = 0; r < 4; r++) {
        int id = tid + 256 * r;
        int row = id >> 3, q = (id & 7) * 4;
        float* a = Abuf[0] + row * LDA + q;
        a[0] = t32(ra[r].x); a[1] = t32(ra[r].y); a[2] = t32(ra[r].z); a[3] = t32(ra[r].w);
        float* b = Bbuf[0] + row * LDA + q;
        b[0] = t32(rb[r].x); b[1] = t32(rb[r].y); b[2] = t32(rb[r].z); b[3] = t32(rb[r].w);
    }
    __syncthreads();

    int nk = K >> 5;
    for (int s = 0; s < nk; s++) {
        int cur = s & 1;
        if (s + 1 < nk) {
            int k0 = (s + 1) << 5;
#pragma unroll
            for (int r = 0; r < 4; r++) {
                int id = tid + 256 * r;
                int row = id >> 3, q = (id & 7) * 4;
                ra[r] = *(const float4*)(A  + (size_t)(rowA + row) * K + k0 + q);
                rb[r] = *(const float4*)(Wt + (size_t)(rowB + row) * K + k0 + q);
            }
        }
#pragma unroll
        for (int kk = 0; kk < 32; kk += 8) {
            wmma::fragment<wmma::matrix_a, 16, 16, 8, wmma::precision::tf32, wmma::row_major> fa[4];
            wmma::fragment<wmma::matrix_b, 16, 16, 8, wmma::precision::tf32, wmma::col_major> fb[2];
#pragma unroll
            for (int i = 0; i < 4; i++)
                wmma::load_matrix_sync(fa[i], Abuf[cur] + (wm * 64 + i * 16) * LDA + kk, LDA);
#pragma unroll
            for (int j = 0; j < 2; j++)
                wmma::load_matrix_sync(fb[j], Bbuf[cur] + (wn * 32 + j * 16) * LDA + kk, LDA);
#pragma unroll
            for (int i = 0; i < 4; i++)
#pragma unroll
                for (int j = 0; j < 2; j++)
                    wmma::mma_sync(acc[i][j], fa[i], fb[j], acc[i][j]);
        }
        if (s + 1 < nk) {
            int nb = cur ^ 1;
#pragma unroll
            for (int r = 0; r < 4; r++) {
                int id = tid + 256 * r;
                int row = id >> 3, q = (id & 7) * 4;
                float* a = Abuf[nb] + row * LDA + q;
                a[0] = t32(ra[r].x); a[1] = t32(ra[r].y); a[2] = t32(ra[r].z); a[3] = t32(ra[r].w);
                float* b = Bbuf[nb] + row * LDA + q;
                b[0] = t32(rb[r].x); b[1] = t32(rb[r].y); b[2] = t32(rb[r].z); b[3] = t32(rb[r].w);
            }
        }
        __syncthreads();
    }

    // epilogue through smem C tile (reuses stage buffers)
    float* Cs = sm;
#pragma unroll
    for (int i = 0; i < 4; i++)
#pragma unroll
        for (int j = 0; j < 2; j++)
            wmma::store_matrix_sync(Cs + (wm * 64 + i * 16) * LDC + wn * 32 + j * 16,
                                    acc[i][j], LDC, wmma::mem_row_major);
    __syncthreads();

    const float IS = rsqrtf(1.0f + EPSf);
    int q = tid & 31;               // quad (4 cols) within the 128-wide tile
    int r0 = tid >> 5;              // starting row
    int ncol = rowB + q * 4;
    float4 bv = *(const float4*)(bias + ncol);
    float4 gv = make_float4(0.f, 0.f, 0.f, 0.f), bb = gv;
    if (MODE >= 1) {
        gv = *(const float4*)(bng + ncol);
        bb = *(const float4*)(bnb + ncol);
        gv.x *= IS; gv.y *= IS; gv.z *= IS; gv.w *= IS;
    }
#pragma unroll
    for (int it = 0; it < 16; it++) {
        int r = r0 + it * 8;
        float4 v = *(const float4*)(Cs + r * LDC + q * 4);
        v.x += bv.x; v.y += bv.y; v.z += bv.z; v.w += bv.w;
        if (MODE >= 1) {
            v.x = gelu_exact(v.x * gv.x + bb.x);
            v.y = gelu_exact(v.y * gv.y + bb.y);
            v.z = gelu_exact(v.z * gv.z + bb.z);
            v.w = gelu_exact(v.w * gv.w + bb.w);
        }
        size_t off = (size_t)(rowA + r) * Nn + ncol;
        if (MODE == 2) {
            float4 rv = *(const float4*)(res + off);
            v.x += rv.x; v.y += rv.y; v.z += rv.z; v.w += rv.w;
        }
        *(float4*)(Co + off) = v;
    }
}

// ---------------- 7) NHWC depthwise 3x3 + BN + GELU ----------------
__global__ void __launch_bounds__(256) dwconv_bn_gelu(
        const float* __restrict__ z1, const float* __restrict__ wt,
        const float* __restrict__ wb, const float* __restrict__ bng,
        const float* __restrict__ bnb, float* __restrict__ z2) {
    int idx = blockIdx.x * 256 + threadIdx.x;        // over T * (HID/4)
    int c4 = idx % 384;
    int pix = idx / 384;
    int bi = pix >> 12; int rc = pix & 4095;
    int r = rc >> 6, c = rc & 63;
    int ch = c4 * 4;
    float wr[4][9];
#pragma unroll
    for (int l = 0; l < 4; l++)
#pragma unroll
        for (int k = 0; k < 9; k++) wr[l][k] = wt[(ch + l) * 9 + k];
    float4 acc = make_float4(0.f, 0.f, 0.f, 0.f);
#pragma unroll
    for (int dr = -1; dr <= 1; dr++) {
        int rr = r + dr;
        if (rr < 0 || rr > 63) continue;
#pragma unroll
        for (int dc = -1; dc <= 1; dc++) {
            int cc = c + dc;
            if (cc < 0 || cc > 63) continue;
            float4 v = *(const float4*)(z1 + ((size_t)(bi * 4096 + rr * 64 + cc)) * HIDc + ch);
            int k = (dr + 1) * 3 + (dc + 1);
            acc.x += v.x * wr[0][k];
            acc.y += v.y * wr[1][k];
            acc.z += v.z * wr[2][k];
            acc.w += v.w * wr[3][k];
        }
    }
    const float IS = rsqrtf(1.0f + EPSf);
    float4 o;
    o.x = gelu_exact((acc.x + wb[ch + 0]) * (bng[ch + 0] * IS) + bnb[ch + 0]);
    o.y = gelu_exact((acc.y + wb[ch + 1]) * (bng[ch + 1] * IS) + bnb[ch + 1]);
    o.z = gelu_exact((acc.z + wb[ch + 2]) * (bng[ch + 2] * IS) + bnb[ch + 2]);
    o.w = gelu_exact((acc.w + wb[ch + 3]) * (bng[ch + 3] * IS) + bnb[ch + 3]);
    *(float4*)(z2 + (size_t)pix * HIDc + ch) = o;
}

// ---------------- launcher ----------------
extern "C" void kernel_launch(void* const* d_in, const int* in_sizes, int n_in,
                              void* d_out, int out_size) {
    (void)in_sizes; (void)n_in; (void)out_size;
    const float* x      = (const float*)d_in[0];
    const float* ln1_g  = (const float*)d_in[3];
    const float* ln1_b  = (const float*)d_in[4];
    const float* qkv_w  = (const float*)d_in[5];
    const float* qkv_b  = (const float*)d_in[6];
    const float* rpb    = (const float*)d_in[7];
    const float* proj_w = (const float*)d_in[8];
    const float* proj_b = (const float*)d_in[9];
    const float* ln2_g  = (const float*)d_in[10];
    const float* ln2_b  = (const float*)d_in[11];
    const float* fc1_w  = (const float*)d_in[12];
    const float* fc1_b  = (const float*)d_in[13];
    const float* bn1_g  = (const float*)d_in[14];
    const float* bn1_b  = (const float*)d_in[15];
    const float* dw_w   = (const float*)d_in[16];
    const float* dw_b   = (const float*)d_in[17];
    const float* bn2_g  = (const float*)d_in[18];
    const float* bn2_b  = (const float*)d_in[19];
    const float* fc2_w  = (const float*)d_in[20];
    const float* fc2_b  = (const float*)d_in[21];
    const float* bn3_g  = (const float*)d_in[22];
    const float* bn3_b  = (const float*)d_in[23];
    float* out = (float*)d_out;

    float *xw, *qkvb, *at, *x1, *z1, *z2;
    cudaGetSymbolAddress((void**)&xw,   g_xw);
    cudaGetSymbolAddress((void**)&qkvb, g_qkv);
    cudaGetSymbolAddress((void**)&at,   g_at);
    cudaGetSymbolAddress((void**)&x1,   g_x1);
    cudaGetSymbolAddress((void**)&z1,   g_z1);
    cudaGetSymbolAddress((void**)&z2,   g_z2);

    cudaFuncSetAttribute(tgemm<0>, cudaFuncAttributeMaxDynamicSharedMemorySize, SMEMB);
    cudaFuncSetAttribute(tgemm<1>, cudaFuncAttributeMaxDynamicSharedMemorySize, SMEMB);
    cudaFuncSetAttribute(tgemm<2>, cudaFuncAttributeMaxDynamicSharedMemorySize, SMEMB);

    // 1) LN1 + shift + window
    ln1_shift_win<<<Tt / 8, 256>>>(x, ln1_g, ln1_b, xw);
    // 2) qkv GEMM: [T,384] x [1152,384]^T
    tgemm<0><<<dim3(1152 / 128, Tt / 128), 256, SMEMB>>>(xw, qkv_w, qkvb, qkv_b,
                                                  nullptr, nullptr, nullptr, Tt, 1152, Cc);
    // 3) attention
    attn_win<<<dim3(1024, HEADS), 64>>>(qkvb, rpb, at);
    // 4) proj GEMM (writes into xw, which is free now)
    tgemm<0><<<dim3(384 / 128, Tt / 128), 256, SMEMB>>>(at, proj_w, xw, proj_b,
                                                 nullptr, nullptr, nullptr, Tt, Cc, Cc);
    // 5) un-window + residual + LN2 (h reuses the attention buffer)
    resid_ln2<<<Tt / 8, 256>>>(x, xw, ln2_g, ln2_b, x1, at);
    // 6) fc1 GEMM + BN + GELU
    tgemm<1><<<dim3(HIDc / 128, Tt / 128), 256, SMEMB>>>(at, fc1_w, z1, fc1_b,
                                                  bn1_g, bn1_b, nullptr, Tt, HIDc, Cc);
    // 7) depthwise 3x3 + BN + GELU
    dwconv_bn_gelu<<<(Tt * (HIDc / 4)) / 256, 256>>>(z1, dw_w, dw_b, bn2_g, bn2_b, z2);
    // 8) fc2 GEMM + BN + GELU + residual -> final output
    tgemm<2><<<dim3(384 / 128, Tt / 128), 256, SMEMB>>>(z2, fc2_w, out, fc2_b,
                                                 bn3_g, bn3_b, x1, Tt, Cc, HIDc);
}

// round 4
// speedup vs baseline: 2.7269x; 1.2353x over previous
#include <cuda_runtime.h>
#include <cstdint>
#include <math.h>
#include <mma.h>

using namespace nvcuda;

#define Bc    16
#define Cc    384
#define HEADS 12
#define HIDc  1536
#define Tt    65536          // total tokens = 16*64*64
#define EPSf  1e-5f

#define LDA   40             // 32 k + 8 pad
#define LDC   132            // 128 + 4 pad
#define SMEMB (4 * 128 * LDA * 4)   // 81920 bytes (2 stages x {A,B}); C tile fits inside

// ---------------- scratch (device globals; no allocation) ----------------
__device__ float g_xw [(size_t)Tt * Cc];
__device__ float g_qkv[(size_t)Tt * 3 * Cc];
__device__ float g_at [(size_t)Tt * Cc];
__device__ float g_x1 [(size_t)Tt * Cc];
__device__ float g_z1 [(size_t)Tt * HIDc];
__device__ float g_z2 [(size_t)Tt * HIDc];

// fast GELU: tanh formulation with HW MUFU.TANH
__device__ __forceinline__ float gelu_fast(float x) {
    float u = 0.7978845608028654f * x * (1.0f + 0.044715f * x * x);
    float t;
    asm("tanh.approx.f32 %0, %1;" : "=f"(t) : "f"(u));
    return 0.5f * x * (1.0f + t);
}
__device__ __forceinline__ float warp_sum(float v) {
#pragma unroll
    for (int o = 16; o; o >>= 1) v += __shfl_xor_sync(0xffffffffu, v, o);
    return v;
}
__device__ __forceinline__ void cpa16(void* dst, const void* src) {
    unsigned int s = (unsigned int)__cvta_generic_to_shared(dst);
    asm volatile("cp.async.cg.shared.global [%0], [%1], 16;\n" :: "r"(s), "l"(src));
}
__device__ __forceinline__ void cpa_commit() { asm volatile("cp.async.commit_group;\n"); }
template <int N>
__device__ __forceinline__ void cpa_wait() { asm volatile("cp.async.wait_group %0;\n" :: "n"(N)); }

// ---------------- 1) LN1 + roll(-4,-4) + window partition ----------------
__global__ void __launch_bounds__(256) ln1_shift_win(
        const float* __restrict__ x, const float* __restrict__ g,
        const float* __restrict__ b, float* __restrict__ xw) {
    int warp = threadIdx.x >> 5, lane = threadIdx.x & 31;
    int t = blockIdx.x * 8 + warp;
    int win = t >> 6, n = t & 63;
    int bi = win >> 6, wim = win & 63;
    int r = (((wim >> 3) << 3) + (n >> 3) + 4) & 63;
    int c = (((wim & 7) << 3) + (n & 7) + 4) & 63;
    const float* row = x + ((size_t)bi * 4096 + r * 64 + c) * Cc;
    float v[12]; float s = 0.f;
#pragma unroll
    for (int k = 0; k < 12; k++) { v[k] = row[lane + 32 * k]; s += v[k]; }
    s = warp_sum(s);
    float mean = s * (1.f / 384.f);
    float q = 0.f;
#pragma unroll
    for (int k = 0; k < 12; k++) { float d = v[k] - mean; q += d * d; }
    q = warp_sum(q);
    float rstd = rsqrtf(q * (1.f / 384.f) + EPSf);
    float* o = xw + (size_t)t * Cc;
#pragma unroll
    for (int k = 0; k < 12; k++) {
        int idx = lane + 32 * k;
        o[idx] = (v[k] - mean) * rstd * g[idx] + b[idx];
    }
}

// ---------------- 5) un-window + roll(+4,+4) + residual + LN2 ----------------
__global__ void __launch_bounds__(256) resid_ln2(
        const float* __restrict__ x, const float* __restrict__ proj,
        const float* __restrict__ g, const float* __restrict__ b,
        float* __restrict__ x1, float* __restrict__ h) {
    int warp = threadIdx.x >> 5, lane = threadIdx.x & 31;
    int t = blockIdx.x * 8 + warp;
    int bi = t >> 12, l = t & 4095;
    int r = l >> 6, c = l & 63;
    int sr = (r - 4) & 63, sc = (c - 4) & 63;
    int win = bi * 64 + ((sr >> 3) << 3) + (sc >> 3);
    int nn = ((sr & 7) << 3) + (sc & 7);
    const float* pr = proj + ((size_t)win * 64 + nn) * Cc;
    const float* xr = x + (size_t)t * Cc;
    float* xo = x1 + (size_t)t * Cc;
    float v[12]; float s = 0.f;
#pragma unroll
    for (int k = 0; k < 12; k++) {
        int idx = lane + 32 * k;
        v[k] = xr[idx] + pr[idx];
        xo[idx] = v[k];
        s += v[k];
    }
    s = warp_sum(s);
    float mean = s * (1.f / 384.f);
    float q = 0.f;
#pragma unroll
    for (int k = 0; k < 12; k++) { float d = v[k] - mean; q += d * d; }
    q = warp_sum(q);
    float rstd = rsqrtf(q * (1.f / 384.f) + EPSf);
    float* o = h + (size_t)t * Cc;
#pragma unroll
    for (int k = 0; k < 12; k++) {
        int idx = lane + 32 * k;
        o[idx] = (v[k] - mean) * rstd * g[idx] + b[idx];
    }
}

// ---------------- 3) windowed attention: 128 threads = 2 heads/block ----------------
__global__ void __launch_bounds__(128) attn_win(
        const float* __restrict__ qkv, const float* __restrict__ rpb,
        float* __restrict__ outp) {
    int win = blockIdx.x;
    int y = threadIdx.x >> 6;              // head sub-index 0..1
    int n = threadIdx.x & 63;
    int head = blockIdx.y * 2 + y;
    __shared__ float qs[2][64][32];
    __shared__ float ks[2][64][32];
    __shared__ float vs[2][64][32];
    __shared__ int labs[64];
    int hb = head * 32;
#pragma unroll
    for (int i = 0; i < 8; i++) {
        int id = n + 64 * i;
        int row = id >> 3, c4 = (id & 7) * 4;
        size_t base = ((size_t)win * 64 + row) * (3 * Cc) + hb + c4;
        *(float4*)&qs[y][row][c4] = *(const float4*)(qkv + base);
        *(float4*)&ks[y][row][c4] = *(const float4*)(qkv + base + Cc);
        *(float4*)&vs[y][row][c4] = *(const float4*)(qkv + base + 2 * Cc);
    }
    if (threadIdx.x < 64) {
        int wim = win & 63;
        int gr = ((wim >> 3) << 3) + (n >> 3);
        int gc = ((wim & 7) << 3) + (n & 7);
        labs[n] = (gr < 56 ? 0 : (gr < 60 ? 1 : 2)) * 3 + (gc < 56 ? 0 : (gc < 60 ? 1 : 2));
    }
    __syncthreads();

    const float SC = 0.17677669529663687f;  // 1/sqrt(32)
    float q[32];
#pragma unroll
    for (int d = 0; d < 32; d++) q[d] = qs[y][n][d];
    int cvn = 15 * (n >> 3) + (n & 7);
    int myl = labs[n];
    float s[64];
    float mx = -1e30f;
#pragma unroll
    for (int m = 0; m < 64; m++) {
        float a = 0.f;
#pragma unroll
        for (int d = 0; d < 32; d++) a += q[d] * ks[y][m][d];
        int mm = 63 - m;
        int cvm = 15 * (mm >> 3) + (mm & 7);
        a = a * SC + rpb[(cvn + cvm) * HEADS + head];
        a += (labs[m] != myl) ? -100.f : 0.f;
        s[m] = a;
        mx = fmaxf(mx, a);
    }
    float sum = 0.f;
#pragma unroll
    for (int m = 0; m < 64; m++) { float e = __expf(s[m] - mx); s[m] = e; sum += e; }
    float inv = 1.f / sum;
#pragma unroll 4
    for (int d = 0; d < 32; d++) {
        float a = 0.f;
#pragma unroll
        for (int m = 0; m < 64; m++) a += s[m] * vs[y][m][d];
        qs[y][n][d] = a * inv;
    }
    __syncthreads();
#pragma unroll
    for (int i = 0; i < 8; i++) {
        int id = n + 64 * i;
        int row = id >> 3, c4 = (id & 7) * 4;
        *(float4*)(outp + ((size_t)win * 64 + row) * Cc + hb + c4) = *(float4*)&qs[y][row][c4];
    }
}

// ---------------- TF32 tensor-core GEMM with cp.async pipeline ----------------
// MODE 0: +bias    MODE 1: gelu(bn(+bias))    MODE 2: res + gelu(bn(+bias))
template <int MODE>
__global__ void __launch_bounds__(256, 2) tgemm(
        const float* __restrict__ A, const float* __restrict__ Wt,
        float* __restrict__ Co, const float* __restrict__ bias,
        const float* __restrict__ bng, const float* __restrict__ bnb,
        const float* __restrict__ res, int M, int Nn, int K) {
    extern __shared__ float sm[];
    float* Abuf[2] = { sm, sm + 128 * LDA };
    float* Bbuf[2] = { sm + 2 * 128 * LDA, sm + 3 * 128 * LDA };

    int tid = threadIdx.x;
    int warp = tid >> 5;
    int wm = warp >> 2;          // 0..1  -> 64 rows
    int wn = warp & 3;           // 0..3  -> 32 cols
    int rowA = blockIdx.y * 128;
    int rowB = blockIdx.x * 128;

    wmma::fragment<wmma::accumulator, 16, 16, 8, float> acc[4][2];
#pragma unroll
    for (int i = 0; i < 4; i++)
#pragma unroll
        for (int j = 0; j < 2; j++) wmma::fill_fragment(acc[i][j], 0.f);

    int lrow = tid >> 3, lq = (tid & 7) * 4;   // each thread: 4 (row,16B) per 128x32 tile
    const float* Ag = A  + (size_t)(rowA + lrow) * K + lq;
    const float* Bg = Wt + (size_t)(rowB + lrow) * K + lq;

    // prologue: stage 0
#pragma unroll
    for (int r = 0; r < 4; r++) {
        cpa16(Abuf[0] + (lrow + 32 * r) * LDA + lq, Ag + (size_t)(32 * r) * K);
        cpa16(Bbuf[0] + (lrow + 32 * r) * LDA + lq, Bg + (size_t)(32 * r) * K);
    }
    cpa_commit();

    int nk = K >> 5;
    for (int s = 0; s < nk; s++) {
        int cur = s & 1;
        if (s + 1 < nk) {
            int nb = cur ^ 1;
            int k0 = (s + 1) << 5;
#pragma unroll
            for (int r = 0; r < 4; r++) {
                cpa16(Abuf[nb] + (lrow + 32 * r) * LDA + lq, Ag + (size_t)(32 * r) * K + k0);
                cpa16(Bbuf[nb] + (lrow + 32 * r) * LDA + lq, Bg + (size_t)(32 * r) * K + k0);
            }
            cpa_commit();
            cpa_wait<1>();
        } else {
            cpa_wait<0>();
        }
        __syncthreads();
#pragma unroll
        for (int kk = 0; kk < 32; kk += 8) {
            wmma::fragment<wmma::matrix_a, 16, 16, 8, wmma::precision::tf32, wmma::row_major> fa[4];
            wmma::fragment<wmma::matrix_b, 16, 16, 8, wmma::precision::tf32, wmma::col_major> fb[2];
#pragma unroll
            for (int i = 0; i < 4; i++)
                wmma::load_matrix_sync(fa[i], Abuf[cur] + (wm * 64 + i * 16) * LDA + kk, LDA);
#pragma unroll
            for (int j = 0; j < 2; j++)
                wmma::load_matrix_sync(fb[j], Bbuf[cur] + (wn * 32 + j * 16) * LDA + kk, LDA);
#pragma unroll
            for (int i = 0; i < 4; i++)
#pragma unroll
                for (int j = 0; j < 2; j++)
                    wmma::mma_sync(acc[i][j], fa[i], fb[j], acc[i][j]);
        }
        __syncthreads();
    }

    // epilogue through smem C tile (reuses stage buffers)
    float* Cs = sm;
#pragma unroll
    for (int i = 0; i < 4; i++)
#pragma unroll
        for (int j = 0; j < 2; j++)
            wmma::store_matrix_sync(Cs + (wm * 64 + i * 16) * LDC + wn * 32 + j * 16,
                                    acc[i][j], LDC, wmma::mem_row_major);
    __syncthreads();

    const float IS = rsqrtf(1.0f + EPSf);
    int q = tid & 31;
    int r0 = tid >> 5;
    int ncol = rowB + q * 4;
    float4 bv = *(const float4*)(bias + ncol);
    float4 gv = make_float4(0.f, 0.f, 0.f, 0.f), bb = gv;
    if (MODE >= 1) {
        gv = *(const float4*)(bng + ncol);
        bb = *(const float4*)(bnb + ncol);
        gv.x *= IS; gv.y *= IS; gv.z *= IS; gv.w *= IS;
    }
#pragma unroll
    for (int it = 0; it < 16; it++) {
        int r = r0 + it * 8;
        float4 v = *(const float4*)(Cs + r * LDC + q * 4);
        v.x += bv.x; v.y += bv.y; v.z += bv.z; v.w += bv.w;
        if (MODE >= 1) {
            v.x = gelu_fast(v.x * gv.x + bb.x);
            v.y = gelu_fast(v.y * gv.y + bb.y);
            v.z = gelu_fast(v.z * gv.z + bb.z);
            v.w = gelu_fast(v.w * gv.w + bb.w);
        }
        size_t off = (size_t)(rowA + r) * Nn + ncol;
        if (MODE == 2) {
            float4 rv = *(const float4*)(res + off);
            v.x += rv.x; v.y += rv.y; v.z += rv.z; v.w += rv.w;
        }
        *(float4*)(Co + off) = v;
    }
}

// ---------------- 7) NHWC depthwise 3x3 + BN + GELU ----------------
__global__ void __launch_bounds__(256) dwconv_bn_gelu(
        const float* __restrict__ z1, const float* __restrict__ wt,
        const float* __restrict__ wb, const float* __restrict__ bng,
        const float* __restrict__ bnb, float* __restrict__ z2) {
    int idx = blockIdx.x * 256 + threadIdx.x;
    int c4 = idx % 384;
    int pix = idx / 384;
    int bi = pix >> 12; int rc = pix & 4095;
    int r = rc >> 6, c = rc & 63;
    int ch = c4 * 4;
    float wr[4][9];
#pragma unroll
    for (int l = 0; l < 4; l++)
#pragma unroll
        for (int k = 0; k < 9; k++) wr[l][k] = wt[(ch + l) * 9 + k];
    float4 acc = make_float4(0.f, 0.f, 0.f, 0.f);
#pragma unroll
    for (int dr = -1; dr <= 1; dr++) {
        int rr = r + dr;
        if (rr < 0 || rr > 63) continue;
#pragma unroll
        for (int dc = -1; dc <= 1; dc++) {
            int cc = c + dc;
            if (cc < 0 || cc > 63) continue;
            float4 v = *(const float4*)(z1 + ((size_t)(bi * 4096 + rr * 64 + cc)) * HIDc + ch);
            int k = (dr + 1) * 3 + (dc + 1);
            acc.x += v.x * wr[0][k];
            acc.y += v.y * wr[1][k];
            acc.z += v.z * wr[2][k];
            acc.w += v.w * wr[3][k];
        }
    }
    const float IS = rsqrtf(1.0f + EPSf);
    float4 o;
    o.x = gelu_fast((acc.x + wb[ch + 0]) * (bng[ch + 0] * IS) + bnb[ch + 0]);
    o.y = gelu_fast((acc.y + wb[ch + 1]) * (bng[ch + 1] * IS) + bnb[ch + 1]);
    o.z = gelu_fast((acc.z + wb[ch + 2]) * (bng[ch + 2] * IS) + bnb[ch + 2]);
    o.w = gelu_fast((acc.w + wb[ch + 3]) * (bng[ch + 3] * IS) + bnb[ch + 3]);
    *(float4*)(z2 + (size_t)pix * HIDc + ch) = o;
}

// ---------------- launcher ----------------
extern "C" void kernel_launch(void* const* d_in, const int* in_sizes, int n_in,
                              void* d_out, int out_size) {
    (void)in_sizes; (void)n_in; (void)out_size;
    const float* x      = (const float*)d_in[0];
    const float* ln1_g  = (const float*)d_in[3];
    const float* ln1_b  = (const float*)d_in[4];
    const float* qkv_w  = (const float*)d_in[5];
    const float* qkv_b  = (const float*)d_in[6];
    const float* rpb    = (const float*)d_in[7];
    const float* proj_w = (const float*)d_in[8];
    const float* proj_b = (const float*)d_in[9];
    const float* ln2_g  = (const float*)d_in[10];
    const float* ln2_b  = (const float*)d_in[11];
    const float* fc1_w  = (const float*)d_in[12];
    const float* fc1_b  = (const float*)d_in[13];
    const float* bn1_g  = (const float*)d_in[14];
    const float* bn1_b  = (const float*)d_in[15];
    const float* dw_w   = (const float*)d_in[16];
    const float* dw_b   = (const float*)d_in[17];
    const float* bn2_g  = (const float*)d_in[18];
    const float* bn2_b  = (const float*)d_in[19];
    const float* fc2_w  = (const float*)d_in[20];
    const float* fc2_b  = (const float*)d_in[21];
    const float* bn3_g  = (const float*)d_in[22];
    const float* bn3_b  = (const float*)d_in[23];
    float* out = (float*)d_out;

    float *xw, *qkvb, *at, *x1, *z1, *z2;
    cudaGetSymbolAddress((void**)&xw,   g_xw);
    cudaGetSymbolAddress((void**)&qkvb, g_qkv);
    cudaGetSymbolAddress((void**)&at,   g_at);
    cudaGetSymbolAddress((void**)&x1,   g_x1);
    cudaGetSymbolAddress((void**)&z1,   g_z1);
    cudaGetSymbolAddress((void**)&z2,   g_z2);

    cudaFuncSetAttribute(tgemm<0>, cudaFuncAttributeMaxDynamicSharedMemorySize, SMEMB);
    cudaFuncSetAttribute(tgemm<1>, cudaFuncAttributeMaxDynamicSharedMemorySize, SMEMB);
    cudaFuncSetAttribute(tgemm<2>, cudaFuncAttributeMaxDynamicSharedMemorySize, SMEMB);

    ln1_shift_win<<<Tt / 8, 256>>>(x, ln1_g, ln1_b, xw);
    tgemm<0><<<dim3(1152 / 128, Tt / 128), 256, SMEMB>>>(xw, qkv_w, qkvb, qkv_b,
                                                  nullptr, nullptr, nullptr, Tt, 1152, Cc);
    attn_win<<<dim3(1024, HEADS / 2), 128>>>(qkvb, rpb, at);
    tgemm<0><<<dim3(384 / 128, Tt / 128), 256, SMEMB>>>(at, proj_w, xw, proj_b,
                                                 nullptr, nullptr, nullptr, Tt, Cc, Cc);
    resid_ln2<<<Tt / 8, 256>>>(x, xw, ln2_g, ln2_b, x1, at);
    tgemm<1><<<dim3(HIDc / 128, Tt / 128), 256, SMEMB>>>(at, fc1_w, z1, fc1_b,
                                                  bn1_g, bn1_b, nullptr, Tt, HIDc, Cc);
    dwconv_bn_gelu<<<(Tt * (HIDc / 4)) / 256, 256>>>(z1, dw_w, dw_b, bn2_g, bn2_b, z2);
    tgemm<2><<<dim3(384 / 128, Tt / 128), 256, SMEMB>>>(z2, fc2_w, out, fc2_b,
                                                 bn3_g, bn3_b, x1, Tt, Cc, HIDc);
}

// round 5
// speedup vs baseline: 3.0538x; 1.1199x over previous
#include <cuda_runtime.h>
#include <cstdint>
#include <math.h>
#include <mma.h>

using namespace nvcuda;

#define Bc    16
#define Cc    384
#define HEADS 12
#define HIDc  1536
#define Tt    65536          // total tokens = 16*64*64
#define EPSf  1e-5f

#define LDA   40             // 32 k + 8 pad
#define LDC   132            // 128 + 4 pad
#define SMEMB (4 * 128 * LDA * 4)   // 81920 bytes (2 stages x {A,B}); C tile fits inside

// ---------------- scratch (device globals; no allocation) ----------------
__device__ float g_xw [(size_t)Tt * Cc];
__device__ float g_qkv[(size_t)Tt * 3 * Cc];
__device__ float g_at [(size_t)Tt * Cc];
__device__ float g_x1 [(size_t)Tt * Cc];
__device__ float g_z1 [(size_t)Tt * HIDc];
__device__ float g_z2 [(size_t)Tt * HIDc];

// fast GELU: tanh formulation with HW MUFU.TANH
__device__ __forceinline__ float gelu_fast(float x) {
    float u = 0.7978845608028654f * x * (1.0f + 0.044715f * x * x);
    float t;
    asm("tanh.approx.f32 %0, %1;" : "=f"(t) : "f"(u));
    return 0.5f * x * (1.0f + t);
}
__device__ __forceinline__ float warp_sum(float v) {
#pragma unroll
    for (int o = 16; o; o >>= 1) v += __shfl_xor_sync(0xffffffffu, v, o);
    return v;
}
__device__ __forceinline__ void cpa16(void* dst, const void* src) {
    unsigned int s = (unsigned int)__cvta_generic_to_shared(dst);
    asm volatile("cp.async.cg.shared.global [%0], [%1], 16;\n" :: "r"(s), "l"(src));
}
__device__ __forceinline__ void cpa_commit() { asm volatile("cp.async.commit_group;\n"); }
template <int N>
__device__ __forceinline__ void cpa_wait() { asm volatile("cp.async.wait_group %0;\n" :: "n"(N)); }

// ---------------- 1) LN1 + roll(-4,-4) + window partition ----------------
__global__ void __launch_bounds__(256) ln1_shift_win(
        const float* __restrict__ x, const float* __restrict__ g,
        const float* __restrict__ b, float* __restrict__ xw) {
    int warp = threadIdx.x >> 5, lane = threadIdx.x & 31;
    int t = blockIdx.x * 8 + warp;
    int win = t >> 6, n = t & 63;
    int bi = win >> 6, wim = win & 63;
    int r = (((wim >> 3) << 3) + (n >> 3) + 4) & 63;
    int c = (((wim & 7) << 3) + (n & 7) + 4) & 63;
    const float* row = x + ((size_t)bi * 4096 + r * 64 + c) * Cc;
    float v[12]; float s = 0.f;
#pragma unroll
    for (int k = 0; k < 12; k++) { v[k] = row[lane + 32 * k]; s += v[k]; }
    s = warp_sum(s);
    float mean = s * (1.f / 384.f);
    float q = 0.f;
#pragma unroll
    for (int k = 0; k < 12; k++) { float d = v[k] - mean; q += d * d; }
    q = warp_sum(q);
    float rstd = rsqrtf(q * (1.f / 384.f) + EPSf);
    float* o = xw + (size_t)t * Cc;
#pragma unroll
    for (int k = 0; k < 12; k++) {
        int idx = lane + 32 * k;
        o[idx] = (v[k] - mean) * rstd * g[idx] + b[idx];
    }
}

// ---------------- 5) un-window + roll(+4,+4) + residual + LN2 ----------------
__global__ void __launch_bounds__(256) resid_ln2(
        const float* __restrict__ x, const float* __restrict__ proj,
        const float* __restrict__ g, const float* __restrict__ b,
        float* __restrict__ x1, float* __restrict__ h) {
    int warp = threadIdx.x >> 5, lane = threadIdx.x & 31;
    int t = blockIdx.x * 8 + warp;
    int bi = t >> 12, l = t & 4095;
    int r = l >> 6, c = l & 63;
    int sr = (r - 4) & 63, sc = (c - 4) & 63;
    int win = bi * 64 + ((sr >> 3) << 3) + (sc >> 3);
    int nn = ((sr & 7) << 3) + (sc & 7);
    const float* pr = proj + ((size_t)win * 64 + nn) * Cc;
    const float* xr = x + (size_t)t * Cc;
    float* xo = x1 + (size_t)t * Cc;
    float v[12]; float s = 0.f;
#pragma unroll
    for (int k = 0; k < 12; k++) {
        int idx = lane + 32 * k;
        v[k] = xr[idx] + pr[idx];
        xo[idx] = v[k];
        s += v[k];
    }
    s = warp_sum(s);
    float mean = s * (1.f / 384.f);
    float q = 0.f;
#pragma unroll
    for (int k = 0; k < 12; k++) { float d = v[k] - mean; q += d * d; }
    q = warp_sum(q);
    float rstd = rsqrtf(q * (1.f / 384.f) + EPSf);
    float* o = h + (size_t)t * Cc;
#pragma unroll
    for (int k = 0; k < 12; k++) {
        int idx = lane + 32 * k;
        o[idx] = (v[k] - mean) * rstd * g[idx] + b[idx];
    }
}

// ---------------- 3) windowed attention: 128 threads = 2 heads/block ----------------
__global__ void __launch_bounds__(128) attn_win(
        const float* __restrict__ qkv, const float* __restrict__ rpb,
        float* __restrict__ outp) {
    int win = blockIdx.x;
    int y = threadIdx.x >> 6;              // head sub-index 0..1
    int n = threadIdx.x & 63;
    int head = blockIdx.y * 2 + y;
    __shared__ float qs[2][64][32];
    __shared__ float ks[2][64][32];
    __shared__ float vs[2][64][32];
    __shared__ float rps[2][232];          // rpb column for each of the 2 heads
    __shared__ int labs[64];
    int hb = head * 32;
#pragma unroll
    for (int i = 0; i < 8; i++) {
        int id = n + 64 * i;
        int row = id >> 3, c4 = (id & 7) * 4;
        size_t base = ((size_t)win * 64 + row) * (3 * Cc) + hb + c4;
        *(float4*)&qs[y][row][c4] = *(const float4*)(qkv + base);
        *(float4*)&ks[y][row][c4] = *(const float4*)(qkv + base + Cc);
        *(float4*)&vs[y][row][c4] = *(const float4*)(qkv + base + 2 * Cc);
    }
    // stage relative-position-bias column for this head (225 entries)
    for (int i = n; i < 225; i += 64) rps[y][i] = rpb[i * HEADS + head];
    if (threadIdx.x < 64) {
        int wim = win & 63;
        int gr = ((wim >> 3) << 3) + (n >> 3);
        int gc = ((wim & 7) << 3) + (n & 7);
        labs[n] = (gr < 56 ? 0 : (gr < 60 ? 1 : 2)) * 3 + (gc < 56 ? 0 : (gc < 60 ? 1 : 2));
    }
    __syncthreads();

    const float SC = 0.17677669529663687f;  // 1/sqrt(32)
    float q[32];
#pragma unroll
    for (int d = 0; d < 32; d++) q[d] = qs[y][n][d];
    int cvn = 15 * (n >> 3) + (n & 7);
    int myl = labs[n];
    float s[64];
    float mx = -1e30f;
#pragma unroll
    for (int m = 0; m < 64; m++) {
        float a = 0.f;
#pragma unroll
        for (int d = 0; d < 32; d++) a += q[d] * ks[y][m][d];
        int mm = 63 - m;
        int cvm = 15 * (mm >> 3) + (mm & 7);
        a = a * SC + rps[y][cvn + cvm];
        a += (labs[m] != myl) ? -100.f : 0.f;
        s[m] = a;
        mx = fmaxf(mx, a);
    }
    float sum = 0.f;
#pragma unroll
    for (int m = 0; m < 64; m++) { float e = __expf(s[m] - mx); s[m] = e; sum += e; }
    float inv = 1.f / sum;
#pragma unroll 4
    for (int d = 0; d < 32; d++) {
        float a = 0.f;
#pragma unroll
        for (int m = 0; m < 64; m++) a += s[m] * vs[y][m][d];
        qs[y][n][d] = a * inv;
    }
    __syncthreads();
#pragma unroll
    for (int i = 0; i < 8; i++) {
        int id = n + 64 * i;
        int row = id >> 3, c4 = (id & 7) * 4;
        *(float4*)(outp + ((size_t)win * 64 + row) * Cc + hb + c4) = *(float4*)&qs[y][row][c4];
    }
}

// ---------------- TF32 tensor-core GEMM with cp.async pipeline ----------------
// MODE 0: +bias    MODE 1: gelu(bn(+bias))    MODE 2: res + gelu(bn(+bias))
template <int MODE>
__global__ void __launch_bounds__(256, 2) tgemm(
        const float* __restrict__ A, const float* __restrict__ Wt,
        float* __restrict__ Co, const float* __restrict__ bias,
        const float* __restrict__ bng, const float* __restrict__ bnb,
        const float* __restrict__ res, int M, int Nn, int K) {
    extern __shared__ float sm[];
    float* Abuf[2] = { sm, sm + 128 * LDA };
    float* Bbuf[2] = { sm + 2 * 128 * LDA, sm + 3 * 128 * LDA };

    int tid = threadIdx.x;
    int warp = tid >> 5;
    int wm = warp >> 2;          // 0..1  -> 64 rows
    int wn = warp & 3;           // 0..3  -> 32 cols
    int rowA = blockIdx.y * 128;
    int rowB = blockIdx.x * 128;

    wmma::fragment<wmma::accumulator, 16, 16, 8, float> acc[4][2];
#pragma unroll
    for (int i = 0; i < 4; i++)
#pragma unroll
        for (int j = 0; j < 2; j++) wmma::fill_fragment(acc[i][j], 0.f);

    int lrow = tid >> 3, lq = (tid & 7) * 4;   // each thread: 4 (row,16B) per 128x32 tile
    const float* Ag = A  + (size_t)(rowA + lrow) * K + lq;
    const float* Bg = Wt + (size_t)(rowB + lrow) * K + lq;

    // prologue: stage 0
#pragma unroll
    for (int r = 0; r < 4; r++) {
        cpa16(Abuf[0] + (lrow + 32 * r) * LDA + lq, Ag + (size_t)(32 * r) * K);
        cpa16(Bbuf[0] + (lrow + 32 * r) * LDA + lq, Bg + (size_t)(32 * r) * K);
    }
    cpa_commit();

    int nk = K >> 5;
    for (int s = 0; s < nk; s++) {
        int cur = s & 1;
        if (s + 1 < nk) {
            int nb = cur ^ 1;
            int k0 = (s + 1) << 5;
#pragma unroll
            for (int r = 0; r < 4; r++) {
                cpa16(Abuf[nb] + (lrow + 32 * r) * LDA + lq, Ag + (size_t)(32 * r) * K + k0);
                cpa16(Bbuf[nb] + (lrow + 32 * r) * LDA + lq, Bg + (size_t)(32 * r) * K + k0);
            }
            cpa_commit();
            cpa_wait<1>();
        } else {
            cpa_wait<0>();
        }
        __syncthreads();
#pragma unroll
        for (int kk = 0; kk < 32; kk += 8) {
            wmma::fragment<wmma::matrix_a, 16, 16, 8, wmma::precision::tf32, wmma::row_major> fa[4];
            wmma::fragment<wmma::matrix_b, 16, 16, 8, wmma::precision::tf32, wmma::col_major> fb[2];
#pragma unroll
            for (int i = 0; i < 4; i++)
                wmma::load_matrix_sync(fa[i], Abuf[cur] + (wm * 64 + i * 16) * LDA + kk, LDA);
#pragma unroll
            for (int j = 0; j < 2; j++)
                wmma::load_matrix_sync(fb[j], Bbuf[cur] + (wn * 32 + j * 16) * LDA + kk, LDA);
#pragma unroll
            for (int i = 0; i < 4; i++)
#pragma unroll
                for (int j = 0; j < 2; j++)
                    wmma::mma_sync(acc[i][j], fa[i], fb[j], acc[i][j]);
        }
        __syncthreads();
    }

    // epilogue through smem C tile (reuses stage buffers)
    float* Cs = sm;
#pragma unroll
    for (int i = 0; i < 4; i++)
#pragma unroll
        for (int j = 0; j < 2; j++)
            wmma::store_matrix_sync(Cs + (wm * 64 + i * 16) * LDC + wn * 32 + j * 16,
                                    acc[i][j], LDC, wmma::mem_row_major);
    __syncthreads();

    const float IS = rsqrtf(1.0f + EPSf);
    int q = tid & 31;
    int r0 = tid >> 5;
    int ncol = rowB + q * 4;
    float4 bv = *(const float4*)(bias + ncol);
    float4 gv = make_float4(0.f, 0.f, 0.f, 0.f), bb = gv;
    if (MODE >= 1) {
        gv = *(const float4*)(bng + ncol);
        bb = *(const float4*)(bnb + ncol);
        gv.x *= IS; gv.y *= IS; gv.z *= IS; gv.w *= IS;
    }
#pragma unroll
    for (int it = 0; it < 16; it++) {
        int r = r0 + it * 8;
        float4 v = *(const float4*)(Cs + r * LDC + q * 4);
        v.x += bv.x; v.y += bv.y; v.z += bv.z; v.w += bv.w;
        if (MODE >= 1) {
            v.x = gelu_fast(v.x * gv.x + bb.x);
            v.y = gelu_fast(v.y * gv.y + bb.y);
            v.z = gelu_fast(v.z * gv.z + bb.z);
            v.w = gelu_fast(v.w * gv.w + bb.w);
        }
        size_t off = (size_t)(rowA + r) * Nn + ncol;
        if (MODE == 2) {
            float4 rv = *(const float4*)(res + off);
            v.x += rv.x; v.y += rv.y; v.z += rv.z; v.w += rv.w;
        }
        *(float4*)(Co + off) = v;
    }
}

// ---------------- 7) NHWC depthwise 3x3 + BN + GELU (smem-staged weights) ----------------
// block = 256 thr = 8 pixels x 32 c4-groups ; grid = (Tt/8, 384/32)
__global__ void __launch_bounds__(256) dwconv_bn_gelu(
        const float* __restrict__ z1, const float* __restrict__ wt,
        const float* __restrict__ wb, const float* __restrict__ bng,
        const float* __restrict__ bnb, float* __restrict__ z2) {
    __shared__ float ws[9][4][32];
    int c4l = threadIdx.x & 31;
    int p   = threadIdx.x >> 5;
    int c4  = blockIdx.y * 32 + c4l;
    int ch  = c4 * 4;
    // stage 32 c4-groups x 4 ch x 9 taps = 1152 weights, coalesced on the tap index
    for (int i = threadIdx.x; i < 1152; i += 256) {
        int cc = i & 31;
        int l  = (i >> 5) & 3;
        int k  = i >> 7;
        ws[k][l][cc] = wt[(((blockIdx.y * 32 + cc) * 4) + l) * 9 + k];
    }
    __syncthreads();

    int pix = blockIdx.x * 8 + p;
    int bi = pix >> 12; int rc = pix & 4095;
    int r = rc >> 6, c = rc & 63;
    float4 acc = make_float4(0.f, 0.f, 0.f, 0.f);
#pragma unroll
    for (int dr = -1; dr <= 1; dr++) {
        int rr = r + dr;
        if (rr < 0 || rr > 63) continue;
#pragma unroll
        for (int dc = -1; dc <= 1; dc++) {
            int cc = c + dc;
            if (cc < 0 || cc > 63) continue;
            float4 v = *(const float4*)(z1 + ((size_t)(bi * 4096 + rr * 64 + cc)) * HIDc + ch);
            int k = (dr + 1) * 3 + (dc + 1);
            acc.x += v.x * ws[k][0][c4l];
            acc.y += v.y * ws[k][1][c4l];
            acc.z += v.z * ws[k][2][c4l];
            acc.w += v.w * ws[k][3][c4l];
        }
    }
    const float IS = rsqrtf(1.0f + EPSf);
    float4 o;
    o.x = gelu_fast((acc.x + wb[ch + 0]) * (bng[ch + 0] * IS) + bnb[ch + 0]);
    o.y = gelu_fast((acc.y + wb[ch + 1]) * (bng[ch + 1] * IS) + bnb[ch + 1]);
    o.z = gelu_fast((acc.z + wb[ch + 2]) * (bng[ch + 2] * IS) + bnb[ch + 2]);
    o.w = gelu_fast((acc.w + wb[ch + 3]) * (bng[ch + 3] * IS) + bnb[ch + 3]);
    *(float4*)(z2 + (size_t)pix * HIDc + ch) = o;
}

// ---------------- launcher ----------------
extern "C" void kernel_launch(void* const* d_in, const int* in_sizes, int n_in,
                              void* d_out, int out_size) {
    (void)in_sizes; (void)n_in; (void)out_size;
    const float* x      = (const float*)d_in[0];
    const float* ln1_g  = (const float*)d_in[3];
    const float* ln1_b  = (const float*)d_in[4];
    const float* qkv_w  = (const float*)d_in[5];
    const float* qkv_b  = (const float*)d_in[6];
    const float* rpb    = (const float*)d_in[7];
    const float* proj_w = (const float*)d_in[8];
    const float* proj_b = (const float*)d_in[9];
    const float* ln2_g  = (const float*)d_in[10];
    const float* ln2_b  = (const float*)d_in[11];
    const float* fc1_w  = (const float*)d_in[12];
    const float* fc1_b  = (const float*)d_in[13];
    const float* bn1_g  = (const float*)d_in[14];
    const float* bn1_b  = (const float*)d_in[15];
    const float* dw_w   = (const float*)d_in[16];
    const float* dw_b   = (const float*)d_in[17];
    const float* bn2_g  = (const float*)d_in[18];
    const float* bn2_b  = (const float*)d_in[19];
    const float* fc2_w  = (const float*)d_in[20];
    const float* fc2_b  = (const float*)d_in[21];
    const float* bn3_g  = (const float*)d_in[22];
    const float* bn3_b  = (const float*)d_in[23];
    float* out = (float*)d_out;

    float *xw, *qkvb, *at, *x1, *z1, *z2;
    cudaGetSymbolAddress((void**)&xw,   g_xw);
    cudaGetSymbolAddress((void**)&qkvb, g_qkv);
    cudaGetSymbolAddress((void**)&at,   g_at);
    cudaGetSymbolAddress((void**)&x1,   g_x1);
    cudaGetSymbolAddress((void**)&z1,   g_z1);
    cudaGetSymbolAddress((void**)&z2,   g_z2);

    cudaFuncSetAttribute(tgemm<0>, cudaFuncAttributeMaxDynamicSharedMemorySize, SMEMB);
    cudaFuncSetAttribute(tgemm<1>, cudaFuncAttributeMaxDynamicSharedMemorySize, SMEMB);
    cudaFuncSetAttribute(tgemm<2>, cudaFuncAttributeMaxDynamicSharedMemorySize, SMEMB);

    ln1_shift_win<<<Tt / 8, 256>>>(x, ln1_g, ln1_b, xw);
    tgemm<0><<<dim3(1152 / 128, Tt / 128), 256, SMEMB>>>(xw, qkv_w, qkvb, qkv_b,
                                                  nullptr, nullptr, nullptr, Tt, 1152, Cc);
    attn_win<<<dim3(1024, HEADS / 2), 128>>>(qkvb, rpb, at);
    tgemm<0><<<dim3(384 / 128, Tt / 128), 256, SMEMB>>>(at, proj_w, xw, proj_b,
                                                 nullptr, nullptr, nullptr, Tt, Cc, Cc);
    resid_ln2<<<Tt / 8, 256>>>(x, xw, ln2_g, ln2_b, x1, at);
    tgemm<1><<<dim3(HIDc / 128, Tt / 128), 256, SMEMB>>>(at, fc1_w, z1, fc1_b,
                                                  bn1_g, bn1_b, nullptr, Tt, HIDc, Cc);
    dwconv_bn_gelu<<<dim3(Tt / 8, HIDc / 4 / 32), 256>>>(z1, dw_w, dw_b, bn2_g, bn2_b, z2);
    tgemm<2><<<dim3(384 / 128, Tt / 128), 256, SMEMB>>>(z2, fc2_w, out, fc2_b,
                                                 bn3_g, bn3_b, x1, Tt, Cc, HIDc);
}

// round 6
// speedup vs baseline: 6.5795x; 2.1545x over previous
#include <cuda_runtime.h>
#include <cstdint>
#include <math.h>
#include <mma.h>
#include <cuda_bf16.h>

using namespace nvcuda;

#define Cc    384
#define HEADS 12
#define HIDc  1536
#define Tt    65536          // total tokens = 16*64*64
#define EPSf  1e-5f

#define LDAH  72             // 64 k halfs + 8 pad (16B) -> conflict-free ldmatrix
#define LDC   132            // 128 + 4 pad (fp32 C tile)
#define SMEMB (4 * 128 * LDAH * 2)   // 73728 B: 2 stages x {A,B} bf16; C tile (67.6KB) fits

typedef __nv_bfloat16 bf16;

// ---------------- scratch (device globals; no allocation) ----------------
__device__ bf16  g_xw [(size_t)Tt * Cc];        // LN1 out (bf16)
__device__ float g_qkv[(size_t)Tt * 3 * Cc];    // qkv (fp32, attention input)
__device__ bf16  g_at [(size_t)Tt * Cc];        // attention out (bf16)
__device__ float g_pj [(size_t)Tt * Cc];        // proj out (fp32)
__device__ float g_x1 [(size_t)Tt * Cc];        // x + attn (fp32 residual)
__device__ bf16  g_h  [(size_t)Tt * Cc];        // LN2 out (bf16)
__device__ bf16  g_z1 [(size_t)Tt * HIDc];      // fc1 out (bf16)
__device__ bf16  g_z2 [(size_t)Tt * HIDc];      // dwconv out (bf16)
__device__ bf16  g_wq [1152 * 384];
__device__ bf16  g_wp [384 * 384];
__device__ bf16  g_w1 [1536 * 384];
__device__ bf16  g_w2 [384 * 1536];

__device__ __forceinline__ float gelu_fast(float x) {
    float u = 0.7978845608028654f * x * (1.0f + 0.044715f * x * x);
    float t;
    asm("tanh.approx.f32 %0, %1;" : "=f"(t) : "f"(u));
    return 0.5f * x * (1.0f + t);
}
__device__ __forceinline__ float warp_sum(float v) {
#pragma unroll
    for (int o = 16; o; o >>= 1) v += __shfl_xor_sync(0xffffffffu, v, o);
    return v;
}
__device__ __forceinline__ void cpa16(void* dst, const void* src) {
    unsigned int s = (unsigned int)__cvta_generic_to_shared(dst);
    asm volatile("cp.async.cg.shared.global [%0], [%1], 16;\n" :: "r"(s), "l"(src));
}
__device__ __forceinline__ void cpa_commit() { asm volatile("cp.async.commit_group;\n"); }
template <int N>
__device__ __forceinline__ void cpa_wait() { asm volatile("cp.async.wait_group %0;\n" :: "n"(N)); }

// typed 4-wide store helpers for the GEMM epilogue
__device__ __forceinline__ void store4(float* p, float4 v) { *(float4*)p = v; }
__device__ __forceinline__ void store4(bf16* p, float4 v) {
    __nv_bfloat162 lo = __floats2bfloat162_rn(v.x, v.y);
    __nv_bfloat162 hi = __floats2bfloat162_rn(v.z, v.w);
    uint2 u; u.x = *(unsigned int*)&lo; u.y = *(unsigned int*)&hi;
    *(uint2*)p = u;
}

// ---------------- f32 -> bf16 convert ----------------
__global__ void __launch_bounds__(256) f2bf(const float* __restrict__ in,
                                            bf16* __restrict__ out, int n) {
    int i = blockIdx.x * 256 + threadIdx.x;
    if (i < n) out[i] = __float2bfloat16(in[i]);
}

// ---------------- 1) LN1 + roll(-4,-4) + window partition -> bf16 ----------------
__global__ void __launch_bounds__(256) ln1_shift_win(
        const float* __restrict__ x, const float* __restrict__ g,
        const float* __restrict__ b, bf16* __restrict__ xw) {
    int warp = threadIdx.x >> 5, lane = threadIdx.x & 31;
    int t = blockIdx.x * 8 + warp;
    int win = t >> 6, n = t & 63;
    int bi = win >> 6, wim = win & 63;
    int r = (((wim >> 3) << 3) + (n >> 3) + 4) & 63;
    int c = (((wim & 7) << 3) + (n & 7) + 4) & 63;
    const float* row = x + ((size_t)bi * 4096 + r * 64 + c) * Cc;
    float v[12]; float s = 0.f;
#pragma unroll
    for (int k = 0; k < 12; k++) { v[k] = row[lane + 32 * k]; s += v[k]; }
    s = warp_sum(s);
    float mean = s * (1.f / 384.f);
    float q = 0.f;
#pragma unroll
    for (int k = 0; k < 12; k++) { float d = v[k] - mean; q += d * d; }
    q = warp_sum(q);
    float rstd = rsqrtf(q * (1.f / 384.f) + EPSf);
    bf16* o = xw + (size_t)t * Cc;
#pragma unroll
    for (int k = 0; k < 12; k++) {
        int idx = lane + 32 * k;
        o[idx] = __float2bfloat16((v[k] - mean) * rstd * g[idx] + b[idx]);
    }
}

// ---------------- 5) un-window + roll(+4,+4) + residual + LN2 ----------------
__global__ void __launch_bounds__(256) resid_ln2(
        const float* __restrict__ x, const float* __restrict__ proj,
        const float* __restrict__ g, const float* __restrict__ b,
        float* __restrict__ x1, bf16* __restrict__ h) {
    int warp = threadIdx.x >> 5, lane = threadIdx.x & 31;
    int t = blockIdx.x * 8 + warp;
    int bi = t >> 12, l = t & 4095;
    int r = l >> 6, c = l & 63;
    int sr = (r - 4) & 63, sc = (c - 4) & 63;
    int win = bi * 64 + ((sr >> 3) << 3) + (sc >> 3);
    int nn = ((sr & 7) << 3) + (sc & 7);
    const float* pr = proj + ((size_t)win * 64 + nn) * Cc;
    const float* xr = x + (size_t)t * Cc;
    float* xo = x1 + (size_t)t * Cc;
    float v[12]; float s = 0.f;
#pragma unroll
    for (int k = 0; k < 12; k++) {
        int idx = lane + 32 * k;
        v[k] = xr[idx] + pr[idx];
        xo[idx] = v[k];
        s += v[k];
    }
    s = warp_sum(s);
    float mean = s * (1.f / 384.f);
    float q = 0.f;
#pragma unroll
    for (int k = 0; k < 12; k++) { float d = v[k] - mean; q += d * d; }
    q = warp_sum(q);
    float rstd = rsqrtf(q * (1.f / 384.f) + EPSf);
    bf16* o = h + (size_t)t * Cc;
#pragma unroll
    for (int k = 0; k < 12; k++) {
        int idx = lane + 32 * k;
        o[idx] = __float2bfloat16((v[k] - mean) * rstd * g[idx] + b[idx]);
    }
}

// ---------------- 3) windowed attention: 128 threads = 2 heads/block ----------------
__global__ void __launch_bounds__(128) attn_win(
        const float* __restrict__ qkv, const float* __restrict__ rpb,
        bf16* __restrict__ outp) {
    int win = blockIdx.x;
    int y = threadIdx.x >> 6;
    int n = threadIdx.x & 63;
    int head = blockIdx.y * 2 + y;
    __shared__ float qs[2][64][32];
    __shared__ float ks[2][64][32];
    __shared__ float vs[2][64][32];
    __shared__ float rps[2][232];
    __shared__ int labs[64];
    int hb = head * 32;
#pragma unroll
    for (int i = 0; i < 8; i++) {
        int id = n + 64 * i;
        int row = id >> 3, c4 = (id & 7) * 4;
        size_t base = ((size_t)win * 64 + row) * (3 * Cc) + hb + c4;
        *(float4*)&qs[y][row][c4] = *(const float4*)(qkv + base);
        *(float4*)&ks[y][row][c4] = *(const float4*)(qkv + base + Cc);
        *(float4*)&vs[y][row][c4] = *(const float4*)(qkv + base + 2 * Cc);
    }
    for (int i = n; i < 225; i += 64) rps[y][i] = rpb[i * HEADS + head];
    if (threadIdx.x < 64) {
        int wim = win & 63;
        int gr = ((wim >> 3) << 3) + (n >> 3);
        int gc = ((wim & 7) << 3) + (n & 7);
        labs[n] = (gr < 56 ? 0 : (gr < 60 ? 1 : 2)) * 3 + (gc < 56 ? 0 : (gc < 60 ? 1 : 2));
    }
    __syncthreads();

    const float SC = 0.17677669529663687f;
    float q[32];
#pragma unroll
    for (int d = 0; d < 32; d++) q[d] = qs[y][n][d];
    int cvn = 15 * (n >> 3) + (n & 7);
    int myl = labs[n];
    float s[64];
    float mx = -1e30f;
#pragma unroll
    for (int m = 0; m < 64; m++) {
        float a = 0.f;
#pragma unroll
        for (int d = 0; d < 32; d++) a += q[d] * ks[y][m][d];
        int mm = 63 - m;
        int cvm = 15 * (mm >> 3) + (mm & 7);
        a = a * SC + rps[y][cvn + cvm];
        a += (labs[m] != myl) ? -100.f : 0.f;
        s[m] = a;
        mx = fmaxf(mx, a);
    }
    float sum = 0.f;
#pragma unroll
    for (int m = 0; m < 64; m++) { float e = __expf(s[m] - mx); s[m] = e; sum += e; }
    float inv = 1.f / sum;
#pragma unroll 4
    for (int d = 0; d < 32; d++) {
        float a = 0.f;
#pragma unroll
        for (int m = 0; m < 64; m++) a += s[m] * vs[y][m][d];
        qs[y][n][d] = a * inv;
    }
    __syncthreads();
#pragma unroll
    for (int i = 0; i < 8; i++) {
        int id = n + 64 * i;
        int row = id >> 3, c4 = (id & 7) * 4;
        float4 v = *(float4*)&qs[y][row][c4];
        store4(outp + ((size_t)win * 64 + row) * Cc + hb + c4, v);
    }
}

// ---------------- bf16 tensor-core GEMM with cp.async pipeline ----------------
// C[M,N] = A[M,K] @ W[N,K]^T. MODE 0: +bias  1: gelu(bn(+bias))  2: res + gelu(bn(+bias))
template <int MODE, typename OUTT>
__global__ void __launch_bounds__(256, 2) hgemm(
        const bf16* __restrict__ A, const bf16* __restrict__ Wt,
        OUTT* __restrict__ Co, const float* __restrict__ bias,
        const float* __restrict__ bng, const float* __restrict__ bnb,
        const float* __restrict__ res, int M, int Nn, int K) {
    extern __shared__ char smraw[];
    bf16* smh = (bf16*)smraw;
    bf16* Abuf[2] = { smh, smh + 128 * LDAH };
    bf16* Bbuf[2] = { smh + 2 * 128 * LDAH, smh + 3 * 128 * LDAH };

    int tid = threadIdx.x;
    int warp = tid >> 5;
    int wm = warp >> 2;          // 0..1  -> 64 rows
    int wn = warp & 3;           // 0..3  -> 32 cols
    int rowA = blockIdx.y * 128;
    int rowB = blockIdx.x * 128;

    wmma::fragment<wmma::accumulator, 16, 16, 16, float> acc[4][2];
#pragma unroll
    for (int i = 0; i < 4; i++)
#pragma unroll
        for (int j = 0; j < 2; j++) wmma::fill_fragment(acc[i][j], 0.f);

    int lrow = tid >> 3, lc = (tid & 7) * 8;   // 4 chunks (rows +32r) per matrix per k-tile(64)
    const bf16* Ag = A  + (size_t)(rowA + lrow) * K + lc;
    const bf16* Bg = Wt + (size_t)(rowB + lrow) * K + lc;

    // prologue: stage 0
#pragma unroll
    for (int r = 0; r < 4; r++) {
        cpa16(Abuf[0] + (lrow + 32 * r) * LDAH + lc, Ag + (size_t)(32 * r) * K);
        cpa16(Bbuf[0] + (lrow + 32 * r) * LDAH + lc, Bg + (size_t)(32 * r) * K);
    }
    cpa_commit();

    int nk = K >> 6;
    for (int s = 0; s < nk; s++) {
        int cur = s & 1;
        if (s + 1 < nk) {
            int nb = cur ^ 1;
            int k0 = (s + 1) << 6;
#pragma unroll
            for (int r = 0; r < 4; r++) {
                cpa16(Abuf[nb] + (lrow + 32 * r) * LDAH + lc, Ag + (size_t)(32 * r) * K + k0);
                cpa16(Bbuf[nb] + (lrow + 32 * r) * LDAH + lc, Bg + (size_t)(32 * r) * K + k0);
            }
            cpa_commit();
            cpa_wait<1>();
        } else {
            cpa_wait<0>();
        }
        __syncthreads();
#pragma unroll
        for (int kk = 0; kk < 64; kk += 16) {
            wmma::fragment<wmma::matrix_a, 16, 16, 16, bf16, wmma::row_major> fa[4];
            wmma::fragment<wmma::matrix_b, 16, 16, 16, bf16, wmma::col_major> fb[2];
#pragma unroll
            for (int i = 0; i < 4; i++)
                wmma::load_matrix_sync(fa[i], Abuf[cur] + (wm * 64 + i * 16) * LDAH + kk, LDAH);
#pragma unroll
            for (int j = 0; j < 2; j++)
                wmma::load_matrix_sync(fb[j], Bbuf[cur] + (wn * 32 + j * 16) * LDAH + kk, LDAH);
#pragma unroll
            for (int i = 0; i < 4; i++)
#pragma unroll
                for (int j = 0; j < 2; j++)
                    wmma::mma_sync(acc[i][j], fa[i], fb[j], acc[i][j]);
        }
        __syncthreads();
    }

    // epilogue through fp32 smem C tile (reuses stage buffers)
    float* Cs = (float*)smraw;
#pragma unroll
    for (int i = 0; i < 4; i++)
#pragma unroll
        for (int j = 0; j < 2; j++)
            wmma::store_matrix_sync(Cs + (wm * 64 + i * 16) * LDC + wn * 32 + j * 16,
                                    acc[i][j], LDC, wmma::mem_row_major);
    __syncthreads();

    const float IS = rsqrtf(1.0f + EPSf);
    int q = tid & 31;
    int r0 = tid >> 5;
    int ncol = rowB + q * 4;
    float4 bv = *(const float4*)(bias + ncol);
    float4 gv = make_float4(0.f, 0.f, 0.f, 0.f), bb = gv;
    if (MODE >= 1) {
        gv = *(const float4*)(bng + ncol);
        bb = *(const float4*)(bnb + ncol);
        gv.x *= IS; gv.y *= IS; gv.z *= IS; gv.w *= IS;
    }
#pragma unroll
    for (int it = 0; it < 16; it++) {
        int r = r0 + it * 8;
        float4 v = *(const float4*)(Cs + r * LDC + q * 4);
        v.x += bv.x; v.y += bv.y; v.z += bv.z; v.w += bv.w;
        if (MODE >= 1) {
            v.x = gelu_fast(v.x * gv.x + bb.x);
            v.y = gelu_fast(v.y * gv.y + bb.y);
            v.z = gelu_fast(v.z * gv.z + bb.z);
            v.w = gelu_fast(v.w * gv.w + bb.w);
        }
        size_t off = (size_t)(rowA + r) * Nn + ncol;
        if (MODE == 2) {
            float4 rv = *(const float4*)(res + off);
            v.x += rv.x; v.y += rv.y; v.z += rv.z; v.w += rv.w;
        }
        store4(Co + off, v);
    }
}

// ---------------- 7) NHWC depthwise 3x3 + BN + GELU (bf16 in/out) ----------------
// block = 256 thr = 8 pixels x 32 c4-groups ; grid = (Tt/8, 384/32)
__global__ void __launch_bounds__(256) dwconv_bn_gelu(
        const bf16* __restrict__ z1, const float* __restrict__ wt,
        const float* __restrict__ wb, const float* __restrict__ bng,
        const float* __restrict__ bnb, bf16* __restrict__ z2) {
    __shared__ float ws[9][4][32];
    int c4l = threadIdx.x & 31;
    int p   = threadIdx.x >> 5;
    int c4  = blockIdx.y * 32 + c4l;
    int ch  = c4 * 4;
    for (int i = threadIdx.x; i < 1152; i += 256) {
        int cc = i & 31;
        int l  = (i >> 5) & 3;
        int k  = i >> 7;
        ws[k][l][cc] = wt[(((blockIdx.y * 32 + cc) * 4) + l) * 9 + k];
    }
    __syncthreads();

    int pix = blockIdx.x * 8 + p;
    int bi = pix >> 12; int rc = pix & 4095;
    int r = rc >> 6, c = rc & 63;
    float4 acc = make_float4(0.f, 0.f, 0.f, 0.f);
#pragma unroll
    for (int dr = -1; dr <= 1; dr++) {
        int rr = r + dr;
        if (rr < 0 || rr > 63) continue;
#pragma unroll
        for (int dc = -1; dc <= 1; dc++) {
            int cc = c + dc;
            if (cc < 0 || cc > 63) continue;
            uint2 raw = *(const uint2*)(z1 + ((size_t)(bi * 4096 + rr * 64 + cc)) * HIDc + ch);
            float2 v01 = __bfloat1622float2(*(__nv_bfloat162*)&raw.x);
            float2 v23 = __bfloat1622float2(*(__nv_bfloat162*)&raw.y);
            int k = (dr + 1) * 3 + (dc + 1);
            acc.x += v01.x * ws[k][0][c4l];
            acc.y += v01.y * ws[k][1][c4l];
            acc.z += v23.x * ws[k][2][c4l];
            acc.w += v23.y * ws[k][3][c4l];
        }
    }
    const float IS = rsqrtf(1.0f + EPSf);
    float4 o;
    o.x = gelu_fast((acc.x + wb[ch + 0]) * (bng[ch + 0] * IS) + bnb[ch + 0]);
    o.y = gelu_fast((acc.y + wb[ch + 1]) * (bng[ch + 1] * IS) + bnb[ch + 1]);
    o.z = gelu_fast((acc.z + wb[ch + 2]) * (bng[ch + 2] * IS) + bnb[ch + 2]);
    o.w = gelu_fast((acc.w + wb[ch + 3]) * (bng[ch + 3] * IS) + bnb[ch + 3]);
    store4(z2 + (size_t)pix * HIDc + ch, o);
}

// ---------------- launcher ----------------
extern "C" void kernel_launch(void* const* d_in, const int* in_sizes, int n_in,
                              void* d_out, int out_size) {
    (void)in_sizes; (void)n_in; (void)out_size;
    const float* x      = (const float*)d_in[0];
    const float* ln1_g  = (const float*)d_in[3];
    const float* ln1_b  = (const float*)d_in[4];
    const float* qkv_w  = (const float*)d_in[5];
    const float* qkv_b  = (const float*)d_in[6];
    const float* rpb    = (const float*)d_in[7];
    const float* proj_w = (const float*)d_in[8];
    const float* proj_b = (const float*)d_in[9];
    const float* ln2_g  = (const float*)d_in[10];
    const float* ln2_b  = (const float*)d_in[11];
    const float* fc1_w  = (const float*)d_in[12];
    const float* fc1_b  = (const float*)d_in[13];
    const float* bn1_g  = (const float*)d_in[14];
    const float* bn1_b  = (const float*)d_in[15];
    const float* dw_w   = (const float*)d_in[16];
    const float* dw_b   = (const float*)d_in[17];
    const float* bn2_g  = (const float*)d_in[18];
    const float* bn2_b  = (const float*)d_in[19];
    const float* fc2_w  = (const float*)d_in[20];
    const float* fc2_b  = (const float*)d_in[21];
    const float* bn3_g  = (const float*)d_in[22];
    const float* bn3_b  = (const float*)d_in[23];
    float* out = (float*)d_out;

    bf16 *xw, *at, *h, *z1, *z2, *wq, *wp, *w1, *w2;
    float *qkvb, *pj, *x1;
    cudaGetSymbolAddress((void**)&xw,   g_xw);
    cudaGetSymbolAddress((void**)&qkvb, g_qkv);
    cudaGetSymbolAddress((void**)&at,   g_at);
    cudaGetSymbolAddress((void**)&pj,   g_pj);
    cudaGetSymbolAddress((void**)&x1,   g_x1);
    cudaGetSymbolAddress((void**)&h,    g_h);
    cudaGetSymbolAddress((void**)&z1,   g_z1);
    cudaGetSymbolAddress((void**)&z2,   g_z2);
    cudaGetSymbolAddress((void**)&wq,   g_wq);
    cudaGetSymbolAddress((void**)&wp,   g_wp);
    cudaGetSymbolAddress((void**)&w1,   g_w1);
    cudaGetSymbolAddress((void**)&w2,   g_w2);

    cudaFuncSetAttribute((const void*)hgemm<0, float>, cudaFuncAttributeMaxDynamicSharedMemorySize, SMEMB);
    cudaFuncSetAttribute((const void*)hgemm<1, bf16>,  cudaFuncAttributeMaxDynamicSharedMemorySize, SMEMB);
    cudaFuncSetAttribute((const void*)hgemm<2, float>, cudaFuncAttributeMaxDynamicSharedMemorySize, SMEMB);

    // weight conversions (cheap)
    f2bf<<<(1152 * 384 + 255) / 256, 256>>>(qkv_w, wq, 1152 * 384);
    f2bf<<<(384 * 384 + 255) / 256, 256>>>(proj_w, wp, 384 * 384);
    f2bf<<<(1536 * 384 + 255) / 256, 256>>>(fc1_w, w1, 1536 * 384);
    f2bf<<<(384 * 1536 + 255) / 256, 256>>>(fc2_w, w2, 384 * 1536);

    ln1_shift_win<<<Tt / 8, 256>>>(x, ln1_g, ln1_b, xw);
    hgemm<0, float><<<dim3(1152 / 128, Tt / 128), 256, SMEMB>>>(xw, wq, qkvb, qkv_b,
                                                  nullptr, nullptr, nullptr, Tt, 1152, Cc);
    attn_win<<<dim3(1024, HEADS / 2), 128>>>(qkvb, rpb, at);
    hgemm<0, float><<<dim3(384 / 128, Tt / 128), 256, SMEMB>>>(at, wp, pj, proj_b,
                                                 nullptr, nullptr, nullptr, Tt, Cc, Cc);
    resid_ln2<<<Tt / 8, 256>>>(x, pj, ln2_g, ln2_b, x1, h);
    hgemm<1, bf16><<<dim3(HIDc / 128, Tt / 128), 256, SMEMB>>>(h, w1, z1, fc1_b,
                                                  bn1_g, bn1_b, nullptr, Tt, HIDc, Cc);
    dwconv_bn_gelu<<<dim3(Tt / 8, HIDc / 4 / 32), 256>>>(z1, dw_w, dw_b, bn2_g, bn2_b, z2);
    hgemm<2, float><<<dim3(384 / 128, Tt / 128), 256, SMEMB>>>(z2, w2, out, fc2_b,
                                                 bn3_g, bn3_b, x1, Tt, Cc, HIDc);
}

// round 8
// speedup vs baseline: 7.0696x; 1.0745x over previous
#include <cuda_runtime.h>
#include <cstdint>
#include <math.h>
#include <mma.h>
#include <cuda_bf16.h>

using namespace nvcuda;

#define Cc    384
#define HEADS 12
#define HIDc  1536
#define Tt    65536          // total tokens = 16*64*64
#define EPSf  1e-5f

#define LDAH  72             // 64 k halfs + 8 pad (16B) -> conflict-free ldmatrix
#define LDC   132            // 128 + 4 pad (fp32 C tile)
#define SMEMB (4 * 128 * LDAH * 2)   // 73728 B: 2 stages x {A,B} bf16; C tile (67.6KB) fits

typedef __nv_bfloat16 bf16;

// ---------------- scratch (device globals; no allocation) ----------------
__device__ bf16  g_xw [(size_t)Tt * Cc];        // LN1 out (bf16)
__device__ bf16  g_qkv[(size_t)Tt * 3 * Cc];    // qkv (bf16)
__device__ bf16  g_at [(size_t)Tt * Cc];        // attention out (bf16)
__device__ float g_pj [(size_t)Tt * Cc];        // proj out (fp32)
__device__ float g_x1 [(size_t)Tt * Cc];        // x + attn (fp32 residual)
__device__ bf16  g_h  [(size_t)Tt * Cc];        // LN2 out (bf16)
__device__ bf16  g_z1 [(size_t)Tt * HIDc];      // fc1 out (bf16)
__device__ bf16  g_z2 [(size_t)Tt * HIDc];      // dwconv out (bf16)
__device__ bf16  g_wq [1152 * 384];
__device__ bf16  g_wp [384 * 384];
__device__ bf16  g_w1 [1536 * 384];
__device__ bf16  g_w2 [384 * 1536];

__device__ __forceinline__ float gelu_fast(float x) {
    float u = 0.7978845608028654f * x * (1.0f + 0.044715f * x * x);
    float t;
    asm("tanh.approx.f32 %0, %1;" : "=f"(t) : "f"(u));
    return 0.5f * x * (1.0f + t);
}
__device__ __forceinline__ float warp_sum(float v) {
#pragma unroll
    for (int o = 16; o; o >>= 1) v += __shfl_xor_sync(0xffffffffu, v, o);
    return v;
}
__device__ __forceinline__ void cpa16(void* dst, const void* src) {
    unsigned int s = (unsigned int)__cvta_generic_to_shared(dst);
    asm volatile("cp.async.cg.shared.global [%0], [%1], 16;\n" :: "r"(s), "l"(src));
}
__device__ __forceinline__ void cpa_commit() { asm volatile("cp.async.commit_group;\n"); }
template <int N>
__device__ __forceinline__ void cpa_wait() { asm volatile("cp.async.wait_group %0;\n" :: "n"(N)); }

__device__ __forceinline__ void store4(float* p, float4 v) { *(float4*)p = v; }
__device__ __forceinline__ void store4(bf16* p, float4 v) {
    __nv_bfloat162 lo = __floats2bfloat162_rn(v.x, v.y);
    __nv_bfloat162 hi = __floats2bfloat162_rn(v.z, v.w);
    uint2 u; u.x = *(unsigned int*)&lo; u.y = *(unsigned int*)&hi;
    *(uint2*)p = u;
}
__device__ __forceinline__ float4 load4bf(const bf16* p) {
    uint2 raw = *(const uint2*)p;
    float2 a = __bfloat1622float2(*(__nv_bfloat162*)&raw.x);
    float2 b = __bfloat1622float2(*(__nv_bfloat162*)&raw.y);
    return make_float4(a.x, a.y, b.x, b.y);
}

// ---------------- f32 -> bf16 convert (vectorized x4) ----------------
__global__ void __launch_bounds__(256) f2bf(const float* __restrict__ in,
                                            bf16* __restrict__ out, int n4) {
    int i = blockIdx.x * 256 + threadIdx.x;
    if (i < n4) {
        float4 v = *(const float4*)(in + i * 4);
        store4(out + i * 4, v);
    }
}

// ---------------- 1) LN1 + roll(-4,-4) + window partition -> bf16 ----------------
__global__ void __launch_bounds__(256) ln1_shift_win(
        const float* __restrict__ x, const float* __restrict__ g,
        const float* __restrict__ b, bf16* __restrict__ xw) {
    int warp = threadIdx.x >> 5, lane = threadIdx.x & 31;
    int t = blockIdx.x * 8 + warp;
    int win = t >> 6, n = t & 63;
    int bi = win >> 6, wim = win & 63;
    int r = (((wim >> 3) << 3) + (n >> 3) + 4) & 63;
    int c = (((wim & 7) << 3) + (n & 7) + 4) & 63;
    const float* row = x + ((size_t)bi * 4096 + r * 64 + c) * Cc;
    float v[12]; float s = 0.f;
#pragma unroll
    for (int k = 0; k < 12; k++) { v[k] = row[lane + 32 * k]; s += v[k]; }
    s = warp_sum(s);
    float mean = s * (1.f / 384.f);
    float q = 0.f;
#pragma unroll
    for (int k = 0; k < 12; k++) { float d = v[k] - mean; q += d * d; }
    q = warp_sum(q);
    float rstd = rsqrtf(q * (1.f / 384.f) + EPSf);
    bf16* o = xw + (size_t)t * Cc;
#pragma unroll
    for (int k = 0; k < 12; k++) {
        int idx = lane + 32 * k;
        o[idx] = __float2bfloat16((v[k] - mean) * rstd * g[idx] + b[idx]);
    }
}

// ---------------- 5) un-window + roll(+4,+4) + residual + LN2 ----------------
__global__ void __launch_bounds__(256) resid_ln2(
        const float* __restrict__ x, const float* __restrict__ proj,
        const float* __restrict__ g, const float* __restrict__ b,
        float* __restrict__ x1, bf16* __restrict__ h) {
    int warp = threadIdx.x >> 5, lane = threadIdx.x & 31;
    int t = blockIdx.x * 8 + warp;
    int bi = t >> 12, l = t & 4095;
    int r = l >> 6, c = l & 63;
    int sr = (r - 4) & 63, sc = (c - 4) & 63;
    int win = bi * 64 + ((sr >> 3) << 3) + (sc >> 3);
    int nn = ((sr & 7) << 3) + (sc & 7);
    const float* pr = proj + ((size_t)win * 64 + nn) * Cc;
    const float* xr = x + (size_t)t * Cc;
    float* xo = x1 + (size_t)t * Cc;
    float v[12]; float s = 0.f;
#pragma unroll
    for (int k = 0; k < 12; k++) {
        int idx = lane + 32 * k;
        v[k] = xr[idx] + pr[idx];
        xo[idx] = v[k];
        s += v[k];
    }
    s = warp_sum(s);
    float mean = s * (1.f / 384.f);
    float q = 0.f;
#pragma unroll
    for (int k = 0; k < 12; k++) { float d = v[k] - mean; q += d * d; }
    q = warp_sum(q);
    float rstd = rsqrtf(q * (1.f / 384.f) + EPSf);
    bf16* o = h + (size_t)t * Cc;
#pragma unroll
    for (int k = 0; k < 12; k++) {
        int idx = lane + 32 * k;
        o[idx] = __float2bfloat16((v[k] - mean) * rstd * g[idx] + b[idx]);
    }
}

// ---------------- 3) windowed attention: 128 threads = 2 heads/block ----------------
__global__ void __launch_bounds__(128) attn_win(
        const bf16* __restrict__ qkv, const float* __restrict__ rpb,
        bf16* __restrict__ outp) {
    int win = blockIdx.x;
    int y = threadIdx.x >> 6;
    int n = threadIdx.x & 63;
    int head = blockIdx.y * 2 + y;
    __shared__ float qs[2][64][32];
    __shared__ float ks[2][64][32];
    __shared__ float vs[2][64][32];
    __shared__ float rps[2][232];
    __shared__ int labs[64];
    int hb = head * 32;
#pragma unroll
    for (int i = 0; i < 8; i++) {
        int id = n + 64 * i;
        int row = id >> 3, c4 = (id & 7) * 4;
        size_t base = ((size_t)win * 64 + row) * (3 * Cc) + hb + c4;
        *(float4*)&qs[y][row][c4] = load4bf(qkv + base);
        *(float4*)&ks[y][row][c4] = load4bf(qkv + base + Cc);
        *(float4*)&vs[y][row][c4] = load4bf(qkv + base + 2 * Cc);
    }
    for (int i = n; i < 225; i += 64) rps[y][i] = rpb[i * HEADS + head];
    if (threadIdx.x < 64) {
        int wim = win & 63;
        int gr = ((wim >> 3) << 3) + (n >> 3);
        int gc = ((wim & 7) << 3) + (n & 7);
        labs[n] = (gr < 56 ? 0 : (gr < 60 ? 1 : 2)) * 3 + (gc < 56 ? 0 : (gc < 60 ? 1 : 2));
    }
    __syncthreads();

    const float SC = 0.17677669529663687f;
    float q[32];
#pragma unroll
    for (int d = 0; d < 32; d++) q[d] = qs[y][n][d];
    int cvn = 15 * (n >> 3) + (n & 7);
    int myl = labs[n];
    float s[64];
    float mx = -1e30f;
#pragma unroll
    for (int m = 0; m < 64; m++) {
        float a = 0.f;
#pragma unroll
        for (int d = 0; d < 32; d++) a += q[d] * ks[y][m][d];
        int mm = 63 - m;
        int cvm = 15 * (mm >> 3) + (mm & 7);
        a = a * SC + rps[y][cvn + cvm];
        a += (labs[m] != myl) ? -100.f : 0.f;
        s[m] = a;
        mx = fmaxf(mx, a);
    }
    float sum = 0.f;
#pragma unroll
    for (int m = 0; m < 64; m++) { float e = __expf(s[m] - mx); s[m] = e; sum += e; }
    float inv = 1.f / sum;
#pragma unroll 4
    for (int d = 0; d < 32; d++) {
        float a = 0.f;
#pragma unroll
        for (int m = 0; m < 64; m++) a += s[m] * vs[y][m][d];
        qs[y][n][d] = a * inv;
    }
    __syncthreads();
#pragma unroll
    for (int i = 0; i < 8; i++) {
        int id = n + 64 * i;
        int row = id >> 3, c4 = (id & 7) * 4;
        float4 v = *(float4*)&qs[y][row][c4];
        store4(outp + ((size_t)win * 64 + row) * Cc + hb + c4, v);
    }
}

// ---------------- bf16 tensor-core GEMM, 4 warps x (64x64) warp tile ----------------
// C[M,N] = A[M,K] @ W[N,K]^T. MODE 0: +bias  1: gelu(bn(+bias))  2: res + gelu(bn(+bias))
template <int MODE, typename OUTT>
__global__ void __launch_bounds__(128, 2) hgemm(
        const bf16* __restrict__ A, const bf16* __restrict__ Wt,
        OUTT* __restrict__ Co, const float* __restrict__ bias,
        const float* __restrict__ bng, const float* __restrict__ bnb,
        const float* __restrict__ res, int M, int Nn, int K) {
    extern __shared__ char smraw[];
    bf16* smh = (bf16*)smraw;
    bf16* Abuf[2] = { smh, smh + 128 * LDAH };
    bf16* Bbuf[2] = { smh + 2 * 128 * LDAH, smh + 3 * 128 * LDAH };

    int tid = threadIdx.x;
    int warp = tid >> 5;
    int wm = warp >> 1;          // 0..1 -> 64-row half
    int wn = warp & 1;           // 0..1 -> 64-col half
    int rowA = blockIdx.y * 128;
    int rowB = blockIdx.x * 128;

    wmma::fragment<wmma::accumulator, 16, 16, 16, float> acc[4][4];
#pragma unroll
    for (int i = 0; i < 4; i++)
#pragma unroll
        for (int j = 0; j < 4; j++) wmma::fill_fragment(acc[i][j], 0.f);

    int lrow = tid >> 3, lc = (tid & 7) * 8;   // 8 chunks (rows +16r) per matrix per k-tile(64)
    const bf16* Ag = A  + (size_t)(rowA + lrow) * K + lc;
    const bf16* Bg = Wt + (size_t)(rowB + lrow) * K + lc;

    // prologue: stage 0
#pragma unroll
    for (int r = 0; r < 8; r++) {
        cpa16(Abuf[0] + (lrow + 16 * r) * LDAH + lc, Ag + (size_t)(16 * r) * K);
        cpa16(Bbuf[0] + (lrow + 16 * r) * LDAH + lc, Bg + (size_t)(16 * r) * K);
    }
    cpa_commit();

    int nk = K >> 6;
    for (int s = 0; s < nk; s++) {
        int cur = s & 1;
        if (s + 1 < nk) {
            int nb = cur ^ 1;
            int k0 = (s + 1) << 6;
#pragma unroll
            for (int r = 0; r < 8; r++) {
                cpa16(Abuf[nb] + (lrow + 16 * r) * LDAH + lc, Ag + (size_t)(16 * r) * K + k0);
                cpa16(Bbuf[nb] + (lrow + 16 * r) * LDAH + lc, Bg + (size_t)(16 * r) * K + k0);
            }
            cpa_commit();
            cpa_wait<1>();
        } else {
            cpa_wait<0>();
        }
        __syncthreads();
#pragma unroll
        for (int kk = 0; kk < 64; kk += 16) {
            wmma::fragment<wmma::matrix_a, 16, 16, 16, bf16, wmma::row_major> fa[4];
            wmma::fragment<wmma::matrix_b, 16, 16, 16, bf16, wmma::col_major> fb[4];
#pragma unroll
            for (int i = 0; i < 4; i++)
                wmma::load_matrix_sync(fa[i], Abuf[cur] + (wm * 64 + i * 16) * LDAH + kk, LDAH);
#pragma unroll
            for (int j = 0; j < 4; j++)
                wmma::load_matrix_sync(fb[j], Bbuf[cur] + (wn * 64 + j * 16) * LDAH + kk, LDAH);
#pragma unroll
            for (int i = 0; i < 4; i++)
#pragma unroll
                for (int j = 0; j < 4; j++)
                    wmma::mma_sync(acc[i][j], fa[i], fb[j], acc[i][j]);
        }
        __syncthreads();
    }

    // epilogue through fp32 smem C tile (reuses stage buffers)
    float* Cs = (float*)smraw;
#pragma unroll
    for (int i = 0; i < 4; i++)
#pragma unroll
        for (int j = 0; j < 4; j++)
            wmma::store_matrix_sync(Cs + (wm * 64 + i * 16) * LDC + wn * 64 + j * 16,
                                    acc[i][j], LDC, wmma::mem_row_major);
    __syncthreads();

    const float IS = rsqrtf(1.0f + EPSf);
    int q = tid & 31;
    int r0 = tid >> 5;               // 0..3
    int ncol = rowB + q * 4;
    float4 bv = *(const float4*)(bias + ncol);
    float4 gv = make_float4(0.f, 0.f, 0.f, 0.f), bb = gv;
    if (MODE >= 1) {
        gv = *(const float4*)(bng + ncol);
        bb = *(const float4*)(bnb + ncol);
        gv.x *= IS; gv.y *= IS; gv.z *= IS; gv.w *= IS;
    }
#pragma unroll
    for (int it = 0; it < 32; it++) {
        int r = r0 + it * 4;
        float4 v = *(const float4*)(Cs + r * LDC + q * 4);
        v.x += bv.x; v.y += bv.y; v.z += bv.z; v.w += bv.w;
        if (MODE >= 1) {
            v.x = gelu_fast(v.x * gv.x + bb.x);
            v.y = gelu_fast(v.y * gv.y + bb.y);
            v.z = gelu_fast(v.z * gv.z + bb.z);
            v.w = gelu_fast(v.w * gv.w + bb.w);
        }
        size_t off = (size_t)(rowA + r) * Nn + ncol;
        if (MODE == 2) {
            float4 rv = *(const float4*)(res + off);
            v.x += rv.x; v.y += rv.y; v.z += rv.z; v.w += rv.w;
        }
        store4(Co + off, v);
    }
}

// ---------------- 7) NHWC depthwise 3x3 + BN + GELU (bf16 in/out) ----------------
__global__ void __launch_bounds__(256) dwconv_bn_gelu(
        const bf16* __restrict__ z1, const float* __restrict__ wt,
        const float* __restrict__ wb, const float* __restrict__ bng,
        const float* __restrict__ bnb, bf16* __restrict__ z2) {
    __shared__ float ws[9][4][32];
    int c4l = threadIdx.x & 31;
    int p   = threadIdx.x >> 5;
    int c4  = blockIdx.y * 32 + c4l;
    int ch  = c4 * 4;
    for (int i = threadIdx.x; i < 1152; i += 256) {
        int cc = i & 31;
        int l  = (i >> 5) & 3;
        int k  = i >> 7;
        ws[k][l][cc] = wt[(((blockIdx.y * 32 + cc) * 4) + l) * 9 + k];
    }
    __syncthreads();

    int pix = blockIdx.x * 8 + p;
    int bi = pix >> 12; int rc = pix & 4095;
    int r = rc >> 6, c = rc & 63;
    float4 acc = make_float4(0.f, 0.f, 0.f, 0.f);
#pragma unroll
    for (int dr = -1; dr <= 1; dr++) {
        int rr = r + dr;
        if (rr < 0 || rr > 63) continue;
#pragma unroll
        for (int dc = -1; dc <= 1; dc++) {
            int cc = c + dc;
            if (cc < 0 || cc > 63) continue;
            float4 v = load4bf(z1 + ((size_t)(bi * 4096 + rr * 64 + cc)) * HIDc + ch);
            int k = (dr + 1) * 3 + (dc + 1);
            acc.x += v.x * ws[k][0][c4l];
            acc.y += v.y * ws[k][1][c4l];
            acc.z += v.z * ws[k][2][c4l];
            acc.w += v.w * ws[k][3][c4l];
        }
    }
    const float IS = rsqrtf(1.0f + EPSf);
    float4 o;
    o.x = gelu_fast((acc.x + wb[ch + 0]) * (bng[ch + 0] * IS) + bnb[ch + 0]);
    o.y = gelu_fast((acc.y + wb[ch + 1]) * (bng[ch + 1] * IS) + bnb[ch + 1]);
    o.z = gelu_fast((acc.z + wb[ch + 2]) * (bng[ch + 2] * IS) + bnb[ch + 2]);
    o.w = gelu_fast((acc.w + wb[ch + 3]) * (bng[ch + 3] * IS) + bnb[ch + 3]);
    store4(z2 + (size_t)pix * HIDc + ch, o);
}

// ---------------- launcher ----------------
extern "C" void kernel_launch(void* const* d_in, const int* in_sizes, int n_in,
                              void* d_out, int out_size) {
    (void)in_sizes; (void)n_in; (void)out_size;
    const float* x      = (const float*)d_in[0];
    const float* ln1_g  = (const float*)d_in[3];
    const float* ln1_b  = (const float*)d_in[4];
    const float* qkv_w  = (const float*)d_in[5];
    const float* qkv_b  = (const float*)d_in[6];
    const float* rpb    = (const float*)d_in[7];
    const float* proj_w = (const float*)d_in[8];
    const float* proj_b = (const float*)d_in[9];
    const float* ln2_g  = (const float*)d_in[10];
    const float* ln2_b  = (const float*)d_in[11];
    const float* fc1_w  = (const float*)d_in[12];
    const float* fc1_b  = (const float*)d_in[13];
    const float* bn1_g  = (const float*)d_in[14];
    const float* bn1_b  = (const float*)d_in[15];
    const float* dw_w   = (const float*)d_in[16];
    const float* dw_b   = (const float*)d_in[17];
    const float* bn2_g  = (const float*)d_in[18];
    const float* bn2_b  = (const float*)d_in[19];
    const float* fc2_w  = (const float*)d_in[20];
    const float* fc2_b  = (const float*)d_in[21];
    const float* bn3_g  = (const float*)d_in[22];
    const float* bn3_b  = (const float*)d_in[23];
    float* out = (float*)d_out;

    bf16 *xw, *qkvb, *at, *h, *z1, *z2, *wq, *wp, *w1, *w2;
    float *pj, *x1;
    cudaGetSymbolAddress((void**)&xw,   g_xw);
    cudaGetSymbolAddress((void**)&qkvb, g_qkv);
    cudaGetSymbolAddress((void**)&at,   g_at);
    cudaGetSymbolAddress((void**)&pj,   g_pj);
    cudaGetSymbolAddress((void**)&x1,   g_x1);
    cudaGetSymbolAddress((void**)&h,    g_h);
    cudaGetSymbolAddress((void**)&z1,   g_z1);
    cudaGetSymbolAddress((void**)&z2,   g_z2);
    cudaGetSymbolAddress((void**)&wq,   g_wq);
    cudaGetSymbolAddress((void**)&wp,   g_wp);
    cudaGetSymbolAddress((void**)&w1,   g_w1);
    cudaGetSymbolAddress((void**)&w2,   g_w2);

    cudaFuncSetAttribute((const void*)hgemm<0, bf16>,  cudaFuncAttributeMaxDynamicSharedMemorySize, SMEMB);
    cudaFuncSetAttribute((const void*)hgemm<0, float>, cudaFuncAttributeMaxDynamicSharedMemorySize, SMEMB);
    cudaFuncSetAttribute((const void*)hgemm<1, bf16>,  cudaFuncAttributeMaxDynamicSharedMemorySize, SMEMB);
    cudaFuncSetAttribute((const void*)hgemm<2, float>, cudaFuncAttributeMaxDynamicSharedMemorySize, SMEMB);

    f2bf<<<(1152 * 384 / 4 + 255) / 256, 256>>>(qkv_w, wq, 1152 * 384 / 4);
    f2bf<<<(384 * 384 / 4 + 255) / 256, 256>>>(proj_w, wp, 384 * 384 / 4);
    f2bf<<<(1536 * 384 / 4 + 255) / 256, 256>>>(fc1_w, w1, 1536 * 384 / 4);
    f2bf<<<(384 * 1536 / 4 + 255) / 256, 256>>>(fc2_w, w2, 384 * 1536 / 4);

    ln1_shift_win<<<Tt / 8, 256>>>(x, ln1_g, ln1_b, xw);
    hgemm<0, bf16><<<dim3(1152 / 128, Tt / 128), 128, SMEMB>>>(xw, wq, qkvb, qkv_b,
                                                  nullptr, nullptr, nullptr, Tt, 1152, Cc);
    attn_win<<<dim3(1024, HEADS / 2), 128>>>(qkvb, rpb, at);
    hgemm<0, float><<<dim3(384 / 128, Tt / 128), 128, SMEMB>>>(at, wp, pj, proj_b,
                                                 nullptr, nullptr, nullptr, Tt, Cc, Cc);
    resid_ln2<<<Tt / 8, 256>>>(x, pj, ln2_g, ln2_b, x1, h);
    hgemm<1, bf16><<<dim3(HIDc / 128, Tt / 128), 128, SMEMB>>>(h, w1, z1, fc1_b,
                                                  bn1_g, bn1_b, nullptr, Tt, HIDc, Cc);
    dwconv_bn_gelu<<<dim3(Tt / 8, HIDc / 4 / 32), 256>>>(z1, dw_w, dw_b, bn2_g, bn2_b, z2);
    hgemm<2, float><<<dim3(384 / 128, Tt / 128), 128, SMEMB>>>(z2, w2, out, fc2_b,
                                                 bn3_g, bn3_b, x1, Tt, Cc, HIDc);
}

// round 9
// speedup vs baseline: 8.2508x; 1.1671x over previous
#include <cuda_runtime.h>
#include <cstdint>
#include <math.h>
#include <mma.h>
#include <cuda_bf16.h>

using namespace nvcuda;

#define Cc    384
#define HEADS 12
#define HIDc  1536
#define Tt    65536          // total tokens = 16*64*64
#define EPSf  1e-5f

#define LDAH  72             // 64 k halfs + 8 pad -> conflict-free ldmatrix
#define LDC   132            // 128 + 4 pad (fp32 C tile)
#define SMEMB (3 * 2 * 128 * LDAH * 2)   // 110592 B: 3 stages x {A,B} bf16; C tile (67.6KB) fits

typedef __nv_bfloat16 bf16;

// ---------------- scratch (device globals; no allocation) ----------------
__device__ bf16  g_xw [(size_t)Tt * Cc];        // LN1 out (bf16)
__device__ bf16  g_qkv[(size_t)Tt * 3 * Cc];    // qkv (bf16)
__device__ bf16  g_at [(size_t)Tt * Cc];        // attention out (bf16)
__device__ float g_pj [(size_t)Tt * Cc];        // proj out (fp32)
__device__ float g_x1 [(size_t)Tt * Cc];        // x + attn (fp32 residual)
__device__ bf16  g_h  [(size_t)Tt * Cc];        // LN2 out (bf16)
__device__ bf16  g_z1 [(size_t)Tt * HIDc];      // fc1 out (bf16)
__device__ bf16  g_z2 [(size_t)Tt * HIDc];      // dwconv out (bf16)
__device__ bf16  g_wq [1152 * 384];
__device__ bf16  g_wp [384 * 384];
__device__ bf16  g_w1 [1536 * 384];
__device__ bf16  g_w2 [384 * 1536];

__device__ __forceinline__ float gelu_fast(float x) {
    float u = 0.7978845608028654f * x * (1.0f + 0.044715f * x * x);
    float t;
    asm("tanh.approx.f32 %0, %1;" : "=f"(t) : "f"(u));
    return 0.5f * x * (1.0f + t);
}
__device__ __forceinline__ float warp_sum(float v) {
#pragma unroll
    for (int o = 16; o; o >>= 1) v += __shfl_xor_sync(0xffffffffu, v, o);
    return v;
}
__device__ __forceinline__ void cpa16(void* dst, const void* src) {
    unsigned int s = (unsigned int)__cvta_generic_to_shared(dst);
    asm volatile("cp.async.cg.shared.global [%0], [%1], 16;\n" :: "r"(s), "l"(src));
}
__device__ __forceinline__ void cpa_commit() { asm volatile("cp.async.commit_group;\n"); }
template <int N>
__device__ __forceinline__ void cpa_wait() { asm volatile("cp.async.wait_group %0;\n" :: "n"(N)); }

__device__ __forceinline__ void store4(float* p, float4 v) { *(float4*)p = v; }
__device__ __forceinline__ void store4(bf16* p, float4 v) {
    __nv_bfloat162 lo = __floats2bfloat162_rn(v.x, v.y);
    __nv_bfloat162 hi = __floats2bfloat162_rn(v.z, v.w);
    uint2 u; u.x = *(unsigned int*)&lo; u.y = *(unsigned int*)&hi;
    *(uint2*)p = u;
}
__device__ __forceinline__ float4 load4bf(const bf16* p) {
    uint2 raw = *(const uint2*)p;
    float2 a = __bfloat1622float2(*(__nv_bfloat162*)&raw.x);
    float2 b = __bfloat1622float2(*(__nv_bfloat162*)&raw.y);
    return make_float4(a.x, a.y, b.x, b.y);
}

// ---------------- f32 -> bf16 convert (vectorized x4) ----------------
__global__ void __launch_bounds__(256) f2bf(const float* __restrict__ in,
                                            bf16* __restrict__ out, int n4) {
    int i = blockIdx.x * 256 + threadIdx.x;
    if (i < n4) {
        float4 v = *(const float4*)(in + i * 4);
        store4(out + i * 4, v);
    }
}

// ---------------- 1) LN1 + roll(-4,-4) + window partition -> bf16 ----------------
__global__ void __launch_bounds__(256) ln1_shift_win(
        const float* __restrict__ x, const float* __restrict__ g,
        const float* __restrict__ b, bf16* __restrict__ xw) {
    int warp = threadIdx.x >> 5, lane = threadIdx.x & 31;
    int t = blockIdx.x * 8 + warp;
    int win = t >> 6, n = t & 63;
    int bi = win >> 6, wim = win & 63;
    int r = (((wim >> 3) << 3) + (n >> 3) + 4) & 63;
    int c = (((wim & 7) << 3) + (n & 7) + 4) & 63;
    const float* row = x + ((size_t)bi * 4096 + r * 64 + c) * Cc;
    float v[12]; float s = 0.f;
#pragma unroll
    for (int k = 0; k < 12; k++) { v[k] = row[lane + 32 * k]; s += v[k]; }
    s = warp_sum(s);
    float mean = s * (1.f / 384.f);
    float q = 0.f;
#pragma unroll
    for (int k = 0; k < 12; k++) { float d = v[k] - mean; q += d * d; }
    q = warp_sum(q);
    float rstd = rsqrtf(q * (1.f / 384.f) + EPSf);
    bf16* o = xw + (size_t)t * Cc;
#pragma unroll
    for (int k = 0; k < 12; k++) {
        int idx = lane + 32 * k;
        o[idx] = __float2bfloat16((v[k] - mean) * rstd * g[idx] + b[idx]);
    }
}

// ---------------- 5) un-window + roll(+4,+4) + residual + LN2 ----------------
__global__ void __launch_bounds__(256) resid_ln2(
        const float* __restrict__ x, const float* __restrict__ proj,
        const float* __restrict__ g, const float* __restrict__ b,
        float* __restrict__ x1, bf16* __restrict__ h) {
    int warp = threadIdx.x >> 5, lane = threadIdx.x & 31;
    int t = blockIdx.x * 8 + warp;
    int bi = t >> 12, l = t & 4095;
    int r = l >> 6, c = l & 63;
    int sr = (r - 4) & 63, sc = (c - 4) & 63;
    int win = bi * 64 + ((sr >> 3) << 3) + (sc >> 3);
    int nn = ((sr & 7) << 3) + (sc & 7);
    const float* pr = proj + ((size_t)win * 64 + nn) * Cc;
    const float* xr = x + (size_t)t * Cc;
    float* xo = x1 + (size_t)t * Cc;
    float v[12]; float s = 0.f;
#pragma unroll
    for (int k = 0; k < 12; k++) {
        int idx = lane + 32 * k;
        v[k] = xr[idx] + pr[idx];
        xo[idx] = v[k];
        s += v[k];
    }
    s = warp_sum(s);
    float mean = s * (1.f / 384.f);
    float q = 0.f;
#pragma unroll
    for (int k = 0; k < 12; k++) { float d = v[k] - mean; q += d * d; }
    q = warp_sum(q);
    float rstd = rsqrtf(q * (1.f / 384.f) + EPSf);
    bf16* o = h + (size_t)t * Cc;
#pragma unroll
    for (int k = 0; k < 12; k++) {
        int idx = lane + 32 * k;
        o[idx] = __float2bfloat16((v[k] - mean) * rstd * g[idx] + b[idx]);
    }
}

// ---------------- 3) windowed attention, tensor-core QK^T and P@V ----------------
// block = 128 thr = 4 warps, handles one window x 2 heads.
// dynamic smem per head (32768 B): Q[64][40] bf16 | K[64][40] | V[64][40] | S[64][68] f32
// P[64][72] bf16 overlays Q+K after S is computed.
#define ATT_SMEM (2 * 32768)
__global__ void __launch_bounds__(128) attn_win(
        const bf16* __restrict__ qkv, const float* __restrict__ rpb,
        bf16* __restrict__ outp) {
    extern __shared__ char asm_[];
    __shared__ float rps[2][232];
    __shared__ int labs[64];
    int win = blockIdx.x;
    int tid = threadIdx.x;
    int warp = tid >> 5;
    int wy = warp & 1;             // row half (0..1)
    int wh = warp >> 1;            // head sub (0..1)

    // load Q,K,V for both heads (cooperative, all 128 threads)
#pragma unroll
    for (int hh = 0; hh < 2; hh++) {
        int head_h = blockIdx.y * 2 + hh;
        bf16* Q = (bf16*)(asm_ + hh * 32768);
        bf16* K = (bf16*)(asm_ + hh * 32768 + 5120);
        bf16* V = (bf16*)(asm_ + hh * 32768 + 10240);
#pragma unroll
        for (int i = 0; i < 4; i++) {
            int id = tid + 128 * i;
            int row = id >> 3, c4 = (id & 7) * 4;
            const bf16* src = qkv + ((size_t)win * 64 + row) * (3 * Cc) + head_h * 32 + c4;
            *(uint2*)(Q + row * 40 + c4) = *(const uint2*)(src);
            *(uint2*)(K + row * 40 + c4) = *(const uint2*)(src + Cc);
            *(uint2*)(V + row * 40 + c4) = *(const uint2*)(src + 2 * Cc);
        }
    }
    {
        int n = tid & 63;
        int hh = tid >> 6;
        for (int i = n; i < 225; i += 64) rps[hh][i] = rpb[i * HEADS + (blockIdx.y * 2 + hh)];
        if (tid < 64) {
            int wim = win & 63;
            int gr = ((wim >> 3) << 3) + (n >> 3);
            int gc = ((wim & 7) << 3) + (n & 7);
            labs[n] = (gr < 56 ? 0 : (gr < 60 ? 1 : 2)) * 3 + (gc < 56 ? 0 : (gc < 60 ? 1 : 2));
        }
    }
    __syncthreads();

    // --- S = Q @ K^T (64x64x32), warp (wh, wy) does rows wy*32..+31 of head wh ---
    {
        bf16* Q = (bf16*)(asm_ + wh * 32768);
        bf16* K = (bf16*)(asm_ + wh * 32768 + 5120);
        float* S = (float*)(asm_ + wh * 32768 + 15360);
        wmma::fragment<wmma::accumulator, 16, 16, 16, float> acc[2][4];
#pragma unroll
        for (int i = 0; i < 2; i++)
#pragma unroll
            for (int j = 0; j < 4; j++) wmma::fill_fragment(acc[i][j], 0.f);
#pragma unroll
        for (int kk = 0; kk < 32; kk += 16) {
            wmma::fragment<wmma::matrix_a, 16, 16, 16, bf16, wmma::row_major> fa[2];
            wmma::fragment<wmma::matrix_b, 16, 16, 16, bf16, wmma::col_major> fb[4];
#pragma unroll
            for (int i = 0; i < 2; i++)
                wmma::load_matrix_sync(fa[i], Q + (wy * 32 + i * 16) * 40 + kk, 40);
#pragma unroll
            for (int j = 0; j < 4; j++)
                wmma::load_matrix_sync(fb[j], K + (j * 16) * 40 + kk, 40);
#pragma unroll
            for (int i = 0; i < 2; i++)
#pragma unroll
                for (int j = 0; j < 4; j++)
                    wmma::mma_sync(acc[i][j], fa[i], fb[j], acc[i][j]);
        }
#pragma unroll
        for (int i = 0; i < 2; i++)
#pragma unroll
            for (int j = 0; j < 4; j++)
                wmma::store_matrix_sync(S + (wy * 32 + i * 16) * 68 + j * 16,
                                        acc[i][j], 68, wmma::mem_row_major);
    }
    __syncthreads();

    // --- softmax: thread t handles row n of head y2; write P (bf16) over Q/K ---
    {
        int y2 = tid >> 6, n = tid & 63;
        const float* S = (const float*)(asm_ + y2 * 32768 + 15360);
        bf16* P = (bf16*)(asm_ + y2 * 32768);
        const float SC = 0.17677669529663687f;   // 1/sqrt(32)
        int cvn = 15 * (n >> 3) + (n & 7);
        int myl = labs[n];
        float s[64];
        float mx = -1e30f;
#pragma unroll
        for (int m = 0; m < 64; m++) {
            int mm = 63 - m;
            int cvm = 15 * (mm >> 3) + (mm & 7);
            float a = S[n * 68 + m] * SC + rps[y2][cvn + cvm];
            a += (labs[m] != myl) ? -100.f : 0.f;
            s[m] = a;
            mx = fmaxf(mx, a);
        }
        float sum = 0.f;
#pragma unroll
        for (int m = 0; m < 64; m++) { float e = __expf(s[m] - mx); s[m] = e; sum += e; }
        float inv = 1.f / sum;
#pragma unroll
        for (int m = 0; m < 64; m += 2) {
            __nv_bfloat162 pr2 = __floats2bfloat162_rn(s[m] * inv, s[m + 1] * inv);
            *(__nv_bfloat162*)(P + n * 72 + m) = pr2;
        }
    }
    __syncthreads();

    // --- O = P @ V (64x32x64); result into S region (fp32) ---
    {
        bf16* P = (bf16*)(asm_ + wh * 32768);
        bf16* V = (bf16*)(asm_ + wh * 32768 + 10240);
        float* S = (float*)(asm_ + wh * 32768 + 15360);
        wmma::fragment<wmma::accumulator, 16, 16, 16, float> acc[2][2];
#pragma unroll
        for (int i = 0; i < 2; i++)
#pragma unroll
            for (int j = 0; j < 2; j++) wmma::fill_fragment(acc[i][j], 0.f);
#pragma unroll
        for (int kk = 0; kk < 64; kk += 16) {
            wmma::fragment<wmma::matrix_a, 16, 16, 16, bf16, wmma::row_major> fa[2];
            wmma::fragment<wmma::matrix_b, 16, 16, 16, bf16, wmma::row_major> fb[2];
#pragma unroll
            for (int i = 0; i < 2; i++)
                wmma::load_matrix_sync(fa[i], P + (wy * 32 + i * 16) * 72 + kk, 72);
#pragma unroll
            for (int j = 0; j < 2; j++)
                wmma::load_matrix_sync(fb[j], V + kk * 40 + j * 16, 40);
#pragma unroll
            for (int i = 0; i < 2; i++)
#pragma unroll
                for (int j = 0; j < 2; j++)
                    wmma::mma_sync(acc[i][j], fa[i], fb[j], acc[i][j]);
        }
        __syncthreads();   // S reads (softmax) done before overwrite? softmax done pre-PV sync; this protects nothing extra but cheap
#pragma unroll
        for (int i = 0; i < 2; i++)
#pragma unroll
            for (int j = 0; j < 2; j++)
                wmma::store_matrix_sync(S + (wy * 32 + i * 16) * 68 + j * 16,
                                        acc[i][j], 68, wmma::mem_row_major);
    }
    __syncthreads();

    // --- coalesced bf16 store of O ---
#pragma unroll
    for (int hh = 0; hh < 2; hh++) {
        int head_h = blockIdx.y * 2 + hh;
        const float* S = (const float*)(asm_ + hh * 32768 + 15360);
#pragma unroll
        for (int i = 0; i < 4; i++) {
            int id = tid + 128 * i;
            int row = id >> 3, c4 = (id & 7) * 4;
            float4 v = *(const float4*)(S + row * 68 + c4);
            store4(outp + ((size_t)win * 64 + row) * Cc + head_h * 32 + c4, v);
        }
    }
}

// ---------------- bf16 tensor-core GEMM, 3-stage cp.async, 4 warps x (64x64) ----------------
// C[M,N] = A[M,K] @ W[N,K]^T. MODE 0: +bias  1: gelu(bn(+bias))  2: res + gelu(bn(+bias))
template <int MODE, typename OUTT>
__global__ void __launch_bounds__(128, 2) hgemm(
        const bf16* __restrict__ A, const bf16* __restrict__ Wt,
        OUTT* __restrict__ Co, const float* __restrict__ bias,
        const float* __restrict__ bng, const float* __restrict__ bnb,
        const float* __restrict__ res, int M, int Nn, int K) {
    extern __shared__ char smraw[];
    bf16* smh = (bf16*)smraw;
    bf16* Abuf[3] = { smh, smh + 2 * 128 * LDAH, smh + 4 * 128 * LDAH };
    bf16* Bbuf[3] = { smh + 128 * LDAH, smh + 3 * 128 * LDAH, smh + 5 * 128 * LDAH };

    int tid = threadIdx.x;
    int warp = tid >> 5;
    int wm = warp >> 1;
    int wn = warp & 1;
    int rowA = blockIdx.y * 128;
    int rowB = blockIdx.x * 128;

    wmma::fragment<wmma::accumulator, 16, 16, 16, float> acc[4][4];
#pragma unroll
    for (int i = 0; i < 4; i++)
#pragma unroll
        for (int j = 0; j < 4; j++) wmma::fill_fragment(acc[i][j], 0.f);

    int lrow = tid >> 3, lc = (tid & 7) * 8;
    const bf16* Ag = A  + (size_t)(rowA + lrow) * K + lc;
    const bf16* Bg = Wt + (size_t)(rowB + lrow) * K + lc;
    int nk = K >> 6;

    // prologue: stages 0 and 1
#pragma unroll
    for (int st = 0; st < 2; st++) {
        int k0 = st << 6;
#pragma unroll
        for (int r = 0; r < 8; r++) {
            cpa16(Abuf[st] + (lrow + 16 * r) * LDAH + lc, Ag + (size_t)(16 * r) * K + k0);
            cpa16(Bbuf[st] + (lrow + 16 * r) * LDAH + lc, Bg + (size_t)(16 * r) * K + k0);
        }
        cpa_commit();
    }

    int cur = 0, nxt = 2;
    for (int s = 0; s < nk; s++) {
        if (s + 1 < nk) cpa_wait<1>(); else cpa_wait<0>();
        __syncthreads();
        if (s + 2 < nk) {
            int k0 = (s + 2) << 6;
#pragma unroll
            for (int r = 0; r < 8; r++) {
                cpa16(Abuf[nxt] + (lrow + 16 * r) * LDAH + lc, Ag + (size_t)(16 * r) * K + k0);
                cpa16(Bbuf[nxt] + (lrow + 16 * r) * LDAH + lc, Bg + (size_t)(16 * r) * K + k0);
            }
            cpa_commit();
        }
#pragma unroll
        for (int kk = 0; kk < 64; kk += 16) {
            wmma::fragment<wmma::matrix_a, 16, 16, 16, bf16, wmma::row_major> fa[4];
            wmma::fragment<wmma::matrix_b, 16, 16, 16, bf16, wmma::col_major> fb[4];
#pragma unroll
            for (int i = 0; i < 4; i++)
                wmma::load_matrix_sync(fa[i], Abuf[cur] + (wm * 64 + i * 16) * LDAH + kk, LDAH);
#pragma unroll
            for (int j = 0; j < 4; j++)
                wmma::load_matrix_sync(fb[j], Bbuf[cur] + (wn * 64 + j * 16) * LDAH + kk, LDAH);
#pragma unroll
            for (int i = 0; i < 4; i++)
#pragma unroll
                for (int j = 0; j < 4; j++)
                    wmma::mma_sync(acc[i][j], fa[i], fb[j], acc[i][j]);
        }
        cur = cur + 1 == 3 ? 0 : cur + 1;
        nxt = nxt + 1 == 3 ? 0 : nxt + 1;
    }
    __syncthreads();

    // epilogue through fp32 smem C tile (reuses stage buffers)
    float* Cs = (float*)smraw;
#pragma unroll
    for (int i = 0; i < 4; i++)
#pragma unroll
        for (int j = 0; j < 4; j++)
            wmma::store_matrix_sync(Cs + (wm * 64 + i * 16) * LDC + wn * 64 + j * 16,
                                    acc[i][j], LDC, wmma::mem_row_major);
    __syncthreads();

    const float IS = rsqrtf(1.0f + EPSf);
    int q = tid & 31;
    int r0 = tid >> 5;
    int ncol = rowB + q * 4;
    float4 bv = *(const float4*)(bias + ncol);
    float4 gv = make_float4(0.f, 0.f, 0.f, 0.f), bb = gv;
    if (MODE >= 1) {
        gv = *(const float4*)(bng + ncol);
        bb = *(const float4*)(bnb + ncol);
        gv.x *= IS; gv.y *= IS; gv.z *= IS; gv.w *= IS;
    }
#pragma unroll
    for (int it = 0; it < 32; it++) {
        int r = r0 + it * 4;
        float4 v = *(const float4*)(Cs + r * LDC + q * 4);
        v.x += bv.x; v.y += bv.y; v.z += bv.z; v.w += bv.w;
        if (MODE >= 1) {
            v.x = gelu_fast(v.x * gv.x + bb.x);
            v.y = gelu_fast(v.y * gv.y + bb.y);
            v.z = gelu_fast(v.z * gv.z + bb.z);
            v.w = gelu_fast(v.w * gv.w + bb.w);
        }
        size_t off = (size_t)(rowA + r) * Nn + ncol;
        if (MODE == 2) {
            float4 rv = *(const float4*)(res + off);
            v.x += rv.x; v.y += rv.y; v.z += rv.z; v.w += rv.w;
        }
        store4(Co + off, v);
    }
}

// ---------------- 7) NHWC depthwise 3x3 + BN + GELU (bf16 in/out) ----------------
__global__ void __launch_bounds__(256) dwconv_bn_gelu(
        const bf16* __restrict__ z1, const float* __restrict__ wt,
        const float* __restrict__ wb, const float* __restrict__ bng,
        const float* __restrict__ bnb, bf16* __restrict__ z2) {
    __shared__ float ws[9][4][32];
    int c4l = threadIdx.x & 31;
    int p   = threadIdx.x >> 5;
    int c4  = blockIdx.y * 32 + c4l;
    int ch  = c4 * 4;
    for (int i = threadIdx.x; i < 1152; i += 256) {
        int cc = i & 31;
        int l  = (i >> 5) & 3;
        int k  = i >> 7;
        ws[k][l][cc] = wt[(((blockIdx.y * 32 + cc) * 4) + l) * 9 + k];
    }
    __syncthreads();

    int pix = blockIdx.x * 8 + p;
    int bi = pix >> 12; int rc = pix & 4095;
    int r = rc >> 6, c = rc & 63;
    float4 acc = make_float4(0.f, 0.f, 0.f, 0.f);
#pragma unroll
    for (int dr = -1; dr <= 1; dr++) {
        int rr = r + dr;
        if (rr < 0 || rr > 63) continue;
#pragma unroll
        for (int dc = -1; dc <= 1; dc++) {
            int cc = c + dc;
            if (cc < 0 || cc > 63) continue;
            float4 v = load4bf(z1 + ((size_t)(bi * 4096 + rr * 64 + cc)) * HIDc + ch);
            int k = (dr + 1) * 3 + (dc + 1);
            acc.x += v.x * ws[k][0][c4l];
            acc.y += v.y * ws[k][1][c4l];
            acc.z += v.z * ws[k][2][c4l];
            acc.w += v.w * ws[k][3][c4l];
        }
    }
    const float IS = rsqrtf(1.0f + EPSf);
    float4 o;
    o.x = gelu_fast((acc.x + wb[ch + 0]) * (bng[ch + 0] * IS) + bnb[ch + 0]);
    o.y = gelu_fast((acc.y + wb[ch + 1]) * (bng[ch + 1] * IS) + bnb[ch + 1]);
    o.z = gelu_fast((acc.z + wb[ch + 2]) * (bng[ch + 2] * IS) + bnb[ch + 2]);
    o.w = gelu_fast((acc.w + wb[ch + 3]) * (bng[ch + 3] * IS) + bnb[ch + 3]);
    store4(z2 + (size_t)pix * HIDc + ch, o);
}

// ---------------- launcher ----------------
extern "C" void kernel_launch(void* const* d_in, const int* in_sizes, int n_in,
                              void* d_out, int out_size) {
    (void)in_sizes; (void)n_in; (void)out_size;
    const float* x      = (const float*)d_in[0];
    const float* ln1_g  = (const float*)d_in[3];
    const float* ln1_b  = (const float*)d_in[4];
    const float* qkv_w  = (const float*)d_in[5];
    const float* qkv_b  = (const float*)d_in[6];
    const float* rpb    = (const float*)d_in[7];
    const float* proj_w = (const float*)d_in[8];
    const float* proj_b = (const float*)d_in[9];
    const float* ln2_g  = (const float*)d_in[10];
    const float* ln2_b  = (const float*)d_in[11];
    const float* fc1_w  = (const float*)d_in[12];
    const float* fc1_b  = (const float*)d_in[13];
    const float* bn1_g  = (const float*)d_in[14];
    const float* bn1_b  = (const float*)d_in[15];
    const float* dw_w   = (const float*)d_in[16];
    const float* dw_b   = (const float*)d_in[17];
    const float* bn2_g  = (const float*)d_in[18];
    const float* bn2_b  = (const float*)d_in[19];
    const float* fc2_w  = (const float*)d_in[20];
    const float* fc2_b  = (const float*)d_in[21];
    const float* bn3_g  = (const float*)d_in[22];
    const float* bn3_b  = (const float*)d_in[23];
    float* out = (float*)d_out;

    bf16 *xw, *qkvb, *at, *h, *z1, *z2, *wq, *wp, *w1, *w2;
    float *pj, *x1;
    cudaGetSymbolAddress((void**)&xw,   g_xw);
    cudaGetSymbolAddress((void**)&qkvb, g_qkv);
    cudaGetSymbolAddress((void**)&at,   g_at);
    cudaGetSymbolAddress((void**)&pj,   g_pj);
    cudaGetSymbolAddress((void**)&x1,   g_x1);
    cudaGetSymbolAddress((void**)&h,    g_h);
    cudaGetSymbolAddress((void**)&z1,   g_z1);
    cudaGetSymbolAddress((void**)&z2,   g_z2);
    cudaGetSymbolAddress((void**)&wq,   g_wq);
    cudaGetSymbolAddress((void**)&wp,   g_wp);
    cudaGetSymbolAddress((void**)&w1,   g_w1);
    cudaGetSymbolAddress((void**)&w2,   g_w2);

    cudaFuncSetAttribute((const void*)hgemm<0, bf16>,  cudaFuncAttributeMaxDynamicSharedMemorySize, SMEMB);
    cudaFuncSetAttribute((const void*)hgemm<0, float>, cudaFuncAttributeMaxDynamicSharedMemorySize, SMEMB);
    cudaFuncSetAttribute((const void*)hgemm<1, bf16>,  cudaFuncAttributeMaxDynamicSharedMemorySize, SMEMB);
    cudaFuncSetAttribute((const void*)hgemm<2, float>, cudaFuncAttributeMaxDynamicSharedMemorySize, SMEMB);
    cudaFuncSetAttribute((const void*)attn_win, cudaFuncAttributeMaxDynamicSharedMemorySize, ATT_SMEM);

    f2bf<<<(1152 * 384 / 4 + 255) / 256, 256>>>(qkv_w, wq, 1152 * 384 / 4);
    f2bf<<<(384 * 384 / 4 + 255) / 256, 256>>>(proj_w, wp, 384 * 384 / 4);
    f2bf<<<(1536 * 384 / 4 + 255) / 256, 256>>>(fc1_w, w1, 1536 * 384 / 4);
    f2bf<<<(384 * 1536 / 4 + 255) / 256, 256>>>(fc2_w, w2, 384 * 1536 / 4);

    ln1_shift_win<<<Tt / 8, 256>>>(x, ln1_g, ln1_b, xw);
    hgemm<0, bf16><<<dim3(1152 / 128, Tt / 128), 128, SMEMB>>>(xw, wq, qkvb, qkv_b,
                                                  nullptr, nullptr, nullptr, Tt, 1152, Cc);
    attn_win<<<dim3(1024, HEADS / 2), 128, ATT_SMEM>>>(qkvb, rpb, at);
    hgemm<0, float><<<dim3(384 / 128, Tt / 128), 128, SMEMB>>>(at, wp, pj, proj_b,
                                                 nullptr, nullptr, nullptr, Tt, Cc, Cc);
    resid_ln2<<<Tt / 8, 256>>>(x, pj, ln2_g, ln2_b, x1, h);
    hgemm<1, bf16><<<dim3(HIDc / 128, Tt / 128), 128, SMEMB>>>(h, w1, z1, fc1_b,
                                                  bn1_g, bn1_b, nullptr, Tt, HIDc, Cc);
    dwconv_bn_gelu<<<dim3(Tt / 8, HIDc / 4 / 32), 256>>>(z1, dw_w, dw_b, bn2_g, bn2_b, z2);
    hgemm<2, float><<<dim3(384 / 128, Tt / 128), 128, SMEMB>>>(z2, w2, out, fc2_b,
                                                 bn3_g, bn3_b, x1, Tt, Cc, HIDc);
}

// round 11
// speedup vs baseline: 8.9648x; 1.0865x over previous
#include <cuda_runtime.h>
#include <cstdint>
#include <math.h>
#include <mma.h>
#include <cuda_bf16.h>

using namespace nvcuda;

#define Cc    384
#define HEADS 12
#define HIDc  1536
#define Tt    65536          // total tokens = 16*64*64
#define EPSf  1e-5f

#define LDAH  72             // 64 k halfs + 8 pad -> conflict-free ldmatrix
#define LDC   132            // 128 + 4 pad (fp32 C tile)
#define SMEMB (4 * 128 * LDAH * 2)   // 73728 B: 2 stages x {A,B} bf16; C tile (67.6KB) fits

typedef __nv_bfloat16 bf16;

// ---------------- scratch (device globals; no allocation) ----------------
__device__ bf16  g_xw [(size_t)Tt * Cc];        // LN1 out (bf16)
__device__ bf16  g_qkv[(size_t)Tt * 3 * Cc];    // qkv (bf16)
__device__ bf16  g_at [(size_t)Tt * Cc];        // attention out (bf16)
__device__ bf16  g_pj [(size_t)Tt * Cc];        // proj out (bf16)
__device__ float g_x1 [(size_t)Tt * Cc];        // x + attn (fp32 residual)
__device__ bf16  g_h  [(size_t)Tt * Cc];        // LN2 out (bf16)
__device__ bf16  g_z1 [(size_t)Tt * HIDc];      // fc1 out (bf16)
__device__ bf16  g_z2 [(size_t)Tt * HIDc];      // dwconv out (bf16)
__device__ bf16  g_wq [1152 * 384];
__device__ bf16  g_wp [384 * 384];
__device__ bf16  g_w1 [1536 * 384];
__device__ bf16  g_w2 [384 * 1536];

__device__ __forceinline__ float gelu_fast(float x) {
    float u = 0.7978845608028654f * x * (1.0f + 0.044715f * x * x);
    float t;
    asm("tanh.approx.f32 %0, %1;" : "=f"(t) : "f"(u));
    return 0.5f * x * (1.0f + t);
}
__device__ __forceinline__ float warp_sum(float v) {
#pragma unroll
    for (int o = 16; o; o >>= 1) v += __shfl_xor_sync(0xffffffffu, v, o);
    return v;
}
__device__ __forceinline__ void cpa16(void* dst, const void* src) {
    unsigned int s = (unsigned int)__cvta_generic_to_shared(dst);
    asm volatile("cp.async.cg.shared.global [%0], [%1], 16;\n" :: "r"(s), "l"(src));
}
__device__ __forceinline__ void cpa_commit() { asm volatile("cp.async.commit_group;\n"); }
template <int N>
__device__ __forceinline__ void cpa_wait() { asm volatile("cp.async.wait_group %0;\n" :: "n"(N)); }

__device__ __forceinline__ void store4(float* p, float4 v) { *(float4*)p = v; }
__device__ __forceinline__ void store4(bf16* p, float4 v) {
    __nv_bfloat162 lo = __floats2bfloat162_rn(v.x, v.y);
    __nv_bfloat162 hi = __floats2bfloat162_rn(v.z, v.w);
    uint2 u; u.x = *(unsigned int*)&lo; u.y = *(unsigned int*)&hi;
    *(uint2*)p = u;
}
__device__ __forceinline__ float4 load4bf(const bf16* p) {
    uint2 raw = *(const uint2*)p;
    float2 a = __bfloat1622float2(*(__nv_bfloat162*)&raw.x);
    float2 b = __bfloat1622float2(*(__nv_bfloat162*)&raw.y);
    return make_float4(a.x, a.y, b.x, b.y);
}

// ---------------- fused f32 -> bf16 convert of all 4 weight matrices ----------------
#define WQ4 (1152 * 384 / 4)
#define WP4 (384 * 384 / 4)
#define W14 (1536 * 384 / 4)
#define W24 (384 * 1536 / 4)
__global__ void __launch_bounds__(256) f2bf_all(
        const float* __restrict__ qkv_w, const float* __restrict__ proj_w,
        const float* __restrict__ fc1_w, const float* __restrict__ fc2_w,
        bf16* __restrict__ wq, bf16* __restrict__ wp,
        bf16* __restrict__ w1, bf16* __restrict__ w2) {
    int i = blockIdx.x * 256 + threadIdx.x;
    const float* src; bf16* dst; int off;
    if (i < WQ4)                      { src = qkv_w;  dst = wq; off = i; }
    else if (i < WQ4 + WP4)           { src = proj_w; dst = wp; off = i - WQ4; }
    else if (i < WQ4 + WP4 + W14)     { src = fc1_w;  dst = w1; off = i - WQ4 - WP4; }
    else if (i < WQ4 + WP4 + W14 + W24) { src = fc2_w; dst = w2; off = i - WQ4 - WP4 - W14; }
    else return;
    float4 v = *(const float4*)(src + off * 4);
    store4(dst + off * 4, v);
}

// ---------------- 1) LN1 + roll(-4,-4) + window partition -> bf16 ----------------
__global__ void __launch_bounds__(256) ln1_shift_win(
        const float* __restrict__ x, const float* __restrict__ g,
        const float* __restrict__ b, bf16* __restrict__ xw) {
    int warp = threadIdx.x >> 5, lane = threadIdx.x & 31;
    int t = blockIdx.x * 8 + warp;
    int win = t >> 6, n = t & 63;
    int bi = win >> 6, wim = win & 63;
    int r = (((wim >> 3) << 3) + (n >> 3) + 4) & 63;
    int c = (((wim & 7) << 3) + (n & 7) + 4) & 63;
    const float* row = x + ((size_t)bi * 4096 + r * 64 + c) * Cc;
    float v[12]; float s = 0.f;
#pragma unroll
    for (int k = 0; k < 12; k++) { v[k] = row[lane + 32 * k]; s += v[k]; }
    s = warp_sum(s);
    float mean = s * (1.f / 384.f);
    float q = 0.f;
#pragma unroll
    for (int k = 0; k < 12; k++) { float d = v[k] - mean; q += d * d; }
    q = warp_sum(q);
    float rstd = rsqrtf(q * (1.f / 384.f) + EPSf);
    bf16* o = xw + (size_t)t * Cc;
#pragma unroll
    for (int k = 0; k < 12; k++) {
        int idx = lane + 32 * k;
        o[idx] = __float2bfloat16((v[k] - mean) * rstd * g[idx] + b[idx]);
    }
}

// ---------------- 5) un-window + roll(+4,+4) + residual + LN2 ----------------
__global__ void __launch_bounds__(256) resid_ln2(
        const float* __restrict__ x, const bf16* __restrict__ proj,
        const float* __restrict__ g, const float* __restrict__ b,
        float* __restrict__ x1, bf16* __restrict__ h) {
    int warp = threadIdx.x >> 5, lane = threadIdx.x & 31;
    int t = blockIdx.x * 8 + warp;
    int bi = t >> 12, l = t & 4095;
    int r = l >> 6, c = l & 63;
    int sr = (r - 4) & 63, sc = (c - 4) & 63;
    int win = bi * 64 + ((sr >> 3) << 3) + (sc >> 3);
    int nn = ((sr & 7) << 3) + (sc & 7);
    const bf16* pr = proj + ((size_t)win * 64 + nn) * Cc;
    const float* xr = x + (size_t)t * Cc;
    float* xo = x1 + (size_t)t * Cc;
    float v[12]; float s = 0.f;
#pragma unroll
    for (int k = 0; k < 12; k++) {
        int idx = lane + 32 * k;
        v[k] = xr[idx] + __bfloat162float(pr[idx]);
        xo[idx] = v[k];
        s += v[k];
    }
    s = warp_sum(s);
    float mean = s * (1.f / 384.f);
    float q = 0.f;
#pragma unroll
    for (int k = 0; k < 12; k++) { float d = v[k] - mean; q += d * d; }
    q = warp_sum(q);
    float rstd = rsqrtf(q * (1.f / 384.f) + EPSf);
    bf16* o = h + (size_t)t * Cc;
#pragma unroll
    for (int k = 0; k < 12; k++) {
        int idx = lane + 32 * k;
        o[idx] = __float2bfloat16((v[k] - mean) * rstd * g[idx] + b[idx]);
    }
}

// ---------------- 3) windowed attention, tensor-core QK^T and P@V ----------------
#define ATT_SMEM (2 * 32768)
__global__ void __launch_bounds__(128) attn_win(
        const bf16* __restrict__ qkv, const float* __restrict__ rpb,
        bf16* __restrict__ outp) {
    extern __shared__ char asm_[];
    __shared__ float rps[2][232];
    __shared__ int labs[64];
    int win = blockIdx.x;
    int tid = threadIdx.x;
    int warp = tid >> 5;
    int wy = warp & 1;
    int wh = warp >> 1;

#pragma unroll
    for (int hh = 0; hh < 2; hh++) {
        int head_h = blockIdx.y * 2 + hh;
        bf16* Q = (bf16*)(asm_ + hh * 32768);
        bf16* K = (bf16*)(asm_ + hh * 32768 + 5120);
        bf16* V = (bf16*)(asm_ + hh * 32768 + 10240);
#pragma unroll
        for (int i = 0; i < 4; i++) {
            int id = tid + 128 * i;
            int row = id >> 3, c4 = (id & 7) * 4;
            const bf16* src = qkv + ((size_t)win * 64 + row) * (3 * Cc) + head_h * 32 + c4;
            *(uint2*)(Q + row * 40 + c4) = *(const uint2*)(src);
            *(uint2*)(K + row * 40 + c4) = *(const uint2*)(src + Cc);
            *(uint2*)(V + row * 40 + c4) = *(const uint2*)(src + 2 * Cc);
        }
    }
    {
        int n = tid & 63;
        int hh = tid >> 6;
        for (int i = n; i < 225; i += 64) rps[hh][i] = rpb[i * HEADS + (blockIdx.y * 2 + hh)];
        if (tid < 64) {
            int wim = win & 63;
            int gr = ((wim >> 3) << 3) + (n >> 3);
            int gc = ((wim & 7) << 3) + (n & 7);
            labs[n] = (gr < 56 ? 0 : (gr < 60 ? 1 : 2)) * 3 + (gc < 56 ? 0 : (gc < 60 ? 1 : 2));
        }
    }
    __syncthreads();

    {
        bf16* Q = (bf16*)(asm_ + wh * 32768);
        bf16* K = (bf16*)(asm_ + wh * 32768 + 5120);
        float* S = (float*)(asm_ + wh * 32768 + 15360);
        wmma::fragment<wmma::accumulator, 16, 16, 16, float> acc[2][4];
#pragma unroll
        for (int i = 0; i < 2; i++)
#pragma unroll
            for (int j = 0; j < 4; j++) wmma::fill_fragment(acc[i][j], 0.f);
#pragma unroll
        for (int kk = 0; kk < 32; kk += 16) {
            wmma::fragment<wmma::matrix_a, 16, 16, 16, bf16, wmma::row_major> fa[2];
            wmma::fragment<wmma::matrix_b, 16, 16, 16, bf16, wmma::col_major> fb[4];
#pragma unroll
            for (int i = 0; i < 2; i++)
                wmma::load_matrix_sync(fa[i], Q + (wy * 32 + i * 16) * 40 + kk, 40);
#pragma unroll
            for (int j = 0; j < 4; j++)
                wmma::load_matrix_sync(fb[j], K + (j * 16) * 40 + kk, 40);
#pragma unroll
            for (int i = 0; i < 2; i++)
#pragma unroll
                for (int j = 0; j < 4; j++)
                    wmma::mma_sync(acc[i][j], fa[i], fb[j], acc[i][j]);
        }
#pragma unroll
        for (int i = 0; i < 2; i++)
#pragma unroll
            for (int j = 0; j < 4; j++)
                wmma::store_matrix_sync(S + (wy * 32 + i * 16) * 68 + j * 16,
                                        acc[i][j], 68, wmma::mem_row_major);
    }
    __syncthreads();

    {
        int y2 = tid >> 6, n = tid & 63;
        const float* S = (const float*)(asm_ + y2 * 32768 + 15360);
        bf16* P = (bf16*)(asm_ + y2 * 32768);
        const float SC = 0.17677669529663687f;
        int cvn = 15 * (n >> 3) + (n & 7);
        int myl = labs[n];
        float s[64];
        float mx = -1e30f;
#pragma unroll
        for (int m = 0; m < 64; m++) {
            int mm = 63 - m;
            int cvm = 15 * (mm >> 3) + (mm & 7);
            float a = S[n * 68 + m] * SC + rps[y2][cvn + cvm];
            a += (labs[m] != myl) ? -100.f : 0.f;
            s[m] = a;
            mx = fmaxf(mx, a);
        }
        float sum = 0.f;
#pragma unroll
        for (int m = 0; m < 64; m++) { float e = __expf(s[m] - mx); s[m] = e; sum += e; }
        float inv = 1.f / sum;
#pragma unroll
        for (int m = 0; m < 64; m += 2) {
            __nv_bfloat162 pr2 = __floats2bfloat162_rn(s[m] * inv, s[m + 1] * inv);
            *(__nv_bfloat162*)(P + n * 72 + m) = pr2;
        }
    }
    __syncthreads();

    {
        bf16* P = (bf16*)(asm_ + wh * 32768);
        bf16* V = (bf16*)(asm_ + wh * 32768 + 10240);
        float* S = (float*)(asm_ + wh * 32768 + 15360);
        wmma::fragment<wmma::accumulator, 16, 16, 16, float> acc[2][2];
#pragma unroll
        for (int i = 0; i < 2; i++)
#pragma unroll
            for (int j = 0; j < 2; j++) wmma::fill_fragment(acc[i][j], 0.f);
#pragma unroll
        for (int kk = 0; kk < 64; kk += 16) {
            wmma::fragment<wmma::matrix_a, 16, 16, 16, bf16, wmma::row_major> fa[2];
            wmma::fragment<wmma::matrix_b, 16, 16, 16, bf16, wmma::row_major> fb[2];
#pragma unroll
            for (int i = 0; i < 2; i++)
                wmma::load_matrix_sync(fa[i], P + (wy * 32 + i * 16) * 72 + kk, 72);
#pragma unroll
            for (int j = 0; j < 2; j++)
                wmma::load_matrix_sync(fb[j], V + kk * 40 + j * 16, 40);
#pragma unroll
            for (int i = 0; i < 2; i++)
#pragma unroll
                for (int j = 0; j < 2; j++)
                    wmma::mma_sync(acc[i][j], fa[i], fb[j], acc[i][j]);
        }
        __syncthreads();
#pragma unroll
        for (int i = 0; i < 2; i++)
#pragma unroll
            for (int j = 0; j < 2; j++)
                wmma::store_matrix_sync(S + (wy * 32 + i * 16) * 68 + j * 16,
                                        acc[i][j], 68, wmma::mem_row_major);
    }
    __syncthreads();

#pragma unroll
    for (int hh = 0; hh < 2; hh++) {
        int head_h = blockIdx.y * 2 + hh;
        const float* S = (const float*)(asm_ + hh * 32768 + 15360);
#pragma unroll
        for (int i = 0; i < 4; i++) {
            int id = tid + 128 * i;
            int row = id >> 3, c4 = (id & 7) * 4;
            float4 v = *(const float4*)(S + row * 68 + c4);
            store4(outp + ((size_t)win * 64 + row) * Cc + head_h * 32 + c4, v);
        }
    }
}

// ---------------- bf16 tensor-core GEMM, 2-stage cp.async, 3 CTAs/SM ----------------
// C[M,N] = A[M,K] @ W[N,K]^T. MODE 0: +bias  1: gelu(bn(+bias))  2: res + gelu(bn(+bias))
template <int MODE, typename OUTT>
__global__ void __launch_bounds__(128, 3) hgemm(
        const bf16* __restrict__ A, const bf16* __restrict__ Wt,
        OUTT* __restrict__ Co, const float* __restrict__ bias,
        const float* __restrict__ bng, const float* __restrict__ bnb,
        const float* __restrict__ res, int M, int Nn, int K) {
    extern __shared__ char smraw[];
    bf16* smh = (bf16*)smraw;
    bf16* Abuf[2] = { smh, smh + 2 * 128 * LDAH };
    bf16* Bbuf[2] = { smh + 128 * LDAH, smh + 3 * 128 * LDAH };

    int tid = threadIdx.x;
    int warp = tid >> 5;
    int wm = warp >> 1;
    int wn = warp & 1;
    int rowA = blockIdx.y * 128;
    int rowB = blockIdx.x * 128;

    wmma::fragment<wmma::accumulator, 16, 16, 16, float> acc[4][4];
#pragma unroll
    for (int i = 0; i < 4; i++)
#pragma unroll
        for (int j = 0; j < 4; j++) wmma::fill_fragment(acc[i][j], 0.f);

    int lrow = tid >> 3, lc = (tid & 7) * 8;
    const bf16* Ag = A  + (size_t)(rowA + lrow) * K + lc;
    const bf16* Bg = Wt + (size_t)(rowB + lrow) * K + lc;
    int nk = K >> 6;

    // prologue: stage 0
#pragma unroll
    for (int r = 0; r < 8; r++) {
        cpa16(Abuf[0] + (lrow + 16 * r) * LDAH + lc, Ag + (size_t)(16 * r) * K);
        cpa16(Bbuf[0] + (lrow + 16 * r) * LDAH + lc, Bg + (size_t)(16 * r) * K);
    }
    cpa_commit();

    for (int s = 0; s < nk; s++) {
        int cur = s & 1;
        if (s + 1 < nk) {
            int nb = cur ^ 1;
            int k0 = (s + 1) << 6;
#pragma unroll
            for (int r = 0; r < 8; r++) {
                cpa16(Abuf[nb] + (lrow + 16 * r) * LDAH + lc, Ag + (size_t)(16 * r) * K + k0);
                cpa16(Bbuf[nb] + (lrow + 16 * r) * LDAH + lc, Bg + (size_t)(16 * r) * K + k0);
            }
            cpa_commit();
            cpa_wait<1>();
        } else {
            cpa_wait<0>();
        }
        __syncthreads();
#pragma unroll
        for (int kk = 0; kk < 64; kk += 16) {
            wmma::fragment<wmma::matrix_a, 16, 16, 16, bf16, wmma::row_major> fa[4];
            wmma::fragment<wmma::matrix_b, 16, 16, 16, bf16, wmma::col_major> fb[4];
#pragma unroll
            for (int i = 0; i < 4; i++)
                wmma::load_matrix_sync(fa[i], Abuf[cur] + (wm * 64 + i * 16) * LDAH + kk, LDAH);
#pragma unroll
            for (int j = 0; j < 4; j++)
                wmma::load_matrix_sync(fb[j], Bbuf[cur] + (wn * 64 + j * 16) * LDAH + kk, LDAH);
#pragma unroll
            for (int i = 0; i < 4; i++)
#pragma unroll
                for (int j = 0; j < 4; j++)
                    wmma::mma_sync(acc[i][j], fa[i], fb[j], acc[i][j]);
        }
        __syncthreads();
    }

    // epilogue through fp32 smem C tile (reuses stage buffers)
    float* Cs = (float*)smraw;
#pragma unroll
    for (int i = 0; i < 4; i++)
#pragma unroll
        for (int j = 0; j < 4; j++)
            wmma::store_matrix_sync(Cs + (wm * 64 + i * 16) * LDC + wn * 64 + j * 16,
                                    acc[i][j], LDC, wmma::mem_row_major);
    __syncthreads();

    const float IS = rsqrtf(1.0f + EPSf);
    int q = tid & 31;
    int r0 = tid >> 5;
    int ncol = rowB + q * 4;
    float4 bv = *(const float4*)(bias + ncol);
    float4 gv = make_float4(0.f, 0.f, 0.f, 0.f), bb = gv;
    if (MODE >= 1) {
        gv = *(const float4*)(bng + ncol);
        bb = *(const float4*)(bnb + ncol);
        gv.x *= IS; gv.y *= IS; gv.z *= IS; gv.w *= IS;
    }
#pragma unroll
    for (int it = 0; it < 32; it++) {
        int r = r0 + it * 4;
        float4 v = *(const float4*)(Cs + r * LDC + q * 4);
        v.x += bv.x; v.y += bv.y; v.z += bv.z; v.w += bv.w;
        if (MODE >= 1) {
            v.x = gelu_fast(v.x * gv.x + bb.x);
            v.y = gelu_fast(v.y * gv.y + bb.y);
            v.z = gelu_fast(v.z * gv.z + bb.z);
            v.w = gelu_fast(v.w * gv.w + bb.w);
        }
        size_t off = (size_t)(rowA + r) * Nn + ncol;
        if (MODE == 2) {
            float4 rv = *(const float4*)(res + off);
            v.x += rv.x; v.y += rv.y; v.z += rv.z; v.w += rv.w;
        }
        store4(Co + off, v);
    }
}

// ---------------- 7) NHWC depthwise 3x3 + BN + GELU (bf16 in/out) ----------------
__global__ void __launch_bounds__(256) dwconv_bn_gelu(
        const bf16* __restrict__ z1, const float* __restrict__ wt,
        const float* __restrict__ wb, const float* __restrict__ bng,
        const float* __restrict__ bnb, bf16* __restrict__ z2) {
    __shared__ float ws[9][4][32];
    int c4l = threadIdx.x & 31;
    int p   = threadIdx.x >> 5;
    int c4  = blockIdx.y * 32 + c4l;
    int ch  = c4 * 4;
    for (int i = threadIdx.x; i < 1152; i += 256) {
        int cc = i & 31;
        int l  = (i >> 5) & 3;
        int k  = i >> 7;
        ws[k][l][cc] = wt[(((blockIdx.y * 32 + cc) * 4) + l) * 9 + k];
    }
    __syncthreads();

    int pix = blockIdx.x * 8 + p;
    int bi = pix >> 12; int rc = pix & 4095;
    int r = rc >> 6, c = rc & 63;
    float4 acc = make_float4(0.f, 0.f, 0.f, 0.f);
#pragma unroll
    for (int dr = -1; dr <= 1; dr++) {
        int rr = r + dr;
        if (rr < 0 || rr > 63) continue;
#pragma unroll
        for (int dc = -1; dc <= 1; dc++) {
            int cc = c + dc;
            if (cc < 0 || cc > 63) continue;
            float4 v = load4bf(z1 + ((size_t)(bi * 4096 + rr * 64 + cc)) * HIDc + ch);
            int k = (dr + 1) * 3 + (dc + 1);
            acc.x += v.x * ws[k][0][c4l];
            acc.y += v.y * ws[k][1][c4l];
            acc.z += v.z * ws[k][2][c4l];
            acc.w += v.w * ws[k][3][c4l];
        }
    }
    const float IS = rsqrtf(1.0f + EPSf);
    float4 o;
    o.x = gelu_fast((acc.x + wb[ch + 0]) * (bng[ch + 0] * IS) + bnb[ch + 0]);
    o.y = gelu_fast((acc.y + wb[ch + 1]) * (bng[ch + 1] * IS) + bnb[ch + 1]);
    o.z = gelu_fast((acc.z + wb[ch + 2]) * (bng[ch + 2] * IS) + bnb[ch + 2]);
    o.w = gelu_fast((acc.w + wb[ch + 3]) * (bng[ch + 3] * IS) + bnb[ch + 3]);
    store4(z2 + (size_t)pix * HIDc + ch, o);
}

// ---------------- launcher ----------------
extern "C" void kernel_launch(void* const* d_in, const int* in_sizes, int n_in,
                              void* d_out, int out_size) {
    (void)in_sizes; (void)n_in; (void)out_size;
    const float* x      = (const float*)d_in[0];
    const float* ln1_g  = (const float*)d_in[3];
    const float* ln1_b  = (const float*)d_in[4];
    const float* qkv_w  = (const float*)d_in[5];
    const float* qkv_b  = (const float*)d_in[6];
    const float* rpb    = (const float*)d_in[7];
    const float* proj_w = (const float*)d_in[8];
    const float* proj_b = (const float*)d_in[9];
    const float* ln2_g  = (const float*)d_in[10];
    const float* ln2_b  = (const float*)d_in[11];
    const float* fc1_w  = (const float*)d_in[12];
    const float* fc1_b  = (const float*)d_in[13];
    const float* bn1_g  = (const float*)d_in[14];
    const float* bn1_b  = (const float*)d_in[15];
    const float* dw_w   = (const float*)d_in[16];
    const float* dw_b   = (const float*)d_in[17];
    const float* bn2_g  = (const float*)d_in[18];
    const float* bn2_b  = (const float*)d_in[19];
    const float* fc2_w  = (const float*)d_in[20];
    const float* fc2_b  = (const float*)d_in[21];
    const float* bn3_g  = (const float*)d_in[22];
    const float* bn3_b  = (const float*)d_in[23];
    float* out = (float*)d_out;

    bf16 *xw, *qkvb, *at, *pj, *h, *z1, *z2, *wq, *wp, *w1, *w2;
    float *x1;
    cudaGetSymbolAddress((void**)&xw,   g_xw);
    cudaGetSymbolAddress((void**)&qkvb, g_qkv);
    cudaGetSymbolAddress((void**)&at,   g_at);
    cudaGetSymbolAddress((void**)&pj,   g_pj);
    cudaGetSymbolAddress((void**)&x1,   g_x1);
    cudaGetSymbolAddress((void**)&h,    g_h);
    cudaGetSymbolAddress((void**)&z1,   g_z1);
    cudaGetSymbolAddress((void**)&z2,   g_z2);
    cudaGetSymbolAddress((void**)&wq,   g_wq);
    cudaGetSymbolAddress((void**)&wp,   g_wp);
    cudaGetSymbolAddress((void**)&w1,   g_w1);
    cudaGetSymbolAddress((void**)&w2,   g_w2);

    cudaFuncSetAttribute((const void*)hgemm<0, bf16>,  cudaFuncAttributeMaxDynamicSharedMemorySize, SMEMB);
    cudaFuncSetAttribute((const void*)hgemm<1, bf16>,  cudaFuncAttributeMaxDynamicSharedMemorySize, SMEMB);
    cudaFuncSetAttribute((const void*)hgemm<2, float>, cudaFuncAttributeMaxDynamicSharedMemorySize, SMEMB);
    cudaFuncSetAttribute((const void*)attn_win, cudaFuncAttributeMaxDynamicSharedMemorySize, ATT_SMEM);

    f2bf_all<<<(WQ4 + WP4 + W14 + W24 + 255) / 256, 256>>>(qkv_w, proj_w, fc1_w, fc2_w,
                                                           wq, wp, w1, w2);

    ln1_shift_win<<<Tt / 8, 256>>>(x, ln1_g, ln1_b, xw);
    hgemm<0, bf16><<<dim3(1152 / 128, Tt / 128), 128, SMEMB>>>(xw, wq, qkvb, qkv_b,
                                                  nullptr, nullptr, nullptr, Tt, 1152, Cc);
    attn_win<<<dim3(1024, HEADS / 2), 128, ATT_SMEM>>>(qkvb, rpb, at);
    hgemm<0, bf16><<<dim3(384 / 128, Tt / 128), 128, SMEMB>>>(at, wp, pj, proj_b,
                                                 nullptr, nullptr, nullptr, Tt, Cc, Cc);
    resid_ln2<<<Tt / 8, 256>>>(x, pj, ln2_g, ln2_b, x1, h);
    hgemm<1, bf16><<<dim3(HIDc / 128, Tt / 128), 128, SMEMB>>>(h, w1, z1, fc1_b,
                                                  bn1_g, bn1_b, nullptr, Tt, HIDc, Cc);
    dwconv_bn_gelu<<<dim3(Tt / 8, HIDc / 4 / 32), 256>>>(z1, dw_w, dw_b, bn2_g, bn2_b, z2);
    hgemm<2, float><<<dim3(384 / 128, Tt / 128), 128, SMEMB>>>(z2, w2, out, fc2_b,
                                                 bn3_g, bn3_b, x1, Tt, Cc, HIDc);
}

// round 12
// speedup vs baseline: 10.7010x; 1.1937x over previous
#include <cuda_runtime.h>
#include <cstdint>
#include <math.h>
#include <mma.h>
#include <cuda_bf16.h>

using namespace nvcuda;

#define Cc    384
#define HEADS 12
#define HIDc  1536
#define Tt    65536          // total tokens = 16*64*64
#define EPSf  1e-5f

#define LDAH  72             // 64 k halfs + 8 pad -> conflict-free ldmatrix
#define LDC   132            // 128 + 4 pad (fp32 C tile)
#define SMEMB (4 * 128 * LDAH * 2)   // 73728 B: 2 stages x {A,B} bf16; C tile (67.6KB) fits

typedef __nv_bfloat16 bf16;

// ---------------- scratch (device globals; no allocation) ----------------
__device__ bf16  g_xw [(size_t)Tt * Cc];        // LN1 out (bf16)
__device__ bf16  g_qkv[(size_t)Tt * 3 * Cc];    // qkv (bf16)
__device__ bf16  g_at [(size_t)Tt * Cc];        // attention out (bf16)
__device__ bf16  g_pj [(size_t)Tt * Cc];        // proj out (bf16)
__device__ float g_x1 [(size_t)Tt * Cc];        // x + attn (fp32 residual)
__device__ bf16  g_h  [(size_t)Tt * Cc];        // LN2 out (bf16)
__device__ bf16  g_z1 [(size_t)Tt * HIDc];      // fc1 out (bf16)
__device__ bf16  g_z2 [(size_t)Tt * HIDc];      // dwconv out (bf16)
__device__ bf16  g_wq [1152 * 384];
__device__ bf16  g_wp [384 * 384];
__device__ bf16  g_w1 [1536 * 384];
__device__ bf16  g_w2 [384 * 1536];

__device__ __forceinline__ float gelu_fast(float x) {
    float u = 0.7978845608028654f * x * (1.0f + 0.044715f * x * x);
    float t;
    asm("tanh.approx.f32 %0, %1;" : "=f"(t) : "f"(u));
    return 0.5f * x * (1.0f + t);
}
__device__ __forceinline__ float warp_sum(float v) {
#pragma unroll
    for (int o = 16; o; o >>= 1) v += __shfl_xor_sync(0xffffffffu, v, o);
    return v;
}
__device__ __forceinline__ void cpa16(void* dst, const void* src) {
    unsigned int s = (unsigned int)__cvta_generic_to_shared(dst);
    asm volatile("cp.async.cg.shared.global [%0], [%1], 16;\n" :: "r"(s), "l"(src));
}
__device__ __forceinline__ void cpa_commit() { asm volatile("cp.async.commit_group;\n"); }
template <int N>
__device__ __forceinline__ void cpa_wait() { asm volatile("cp.async.wait_group %0;\n" :: "n"(N)); }

__device__ __forceinline__ void store4(float* p, float4 v) { *(float4*)p = v; }
__device__ __forceinline__ void store4(bf16* p, float4 v) {
    __nv_bfloat162 lo = __floats2bfloat162_rn(v.x, v.y);
    __nv_bfloat162 hi = __floats2bfloat162_rn(v.z, v.w);
    uint2 u; u.x = *(unsigned int*)&lo; u.y = *(unsigned int*)&hi;
    *(uint2*)p = u;
}
__device__ __forceinline__ float4 load4bf(const bf16* p) {
    uint2 raw = *(const uint2*)p;
    float2 a = __bfloat1622float2(*(__nv_bfloat162*)&raw.x);
    float2 b = __bfloat1622float2(*(__nv_bfloat162*)&raw.y);
    return make_float4(a.x, a.y, b.x, b.y);
}

// ---------------- fused f32 -> bf16 convert of all 4 weight matrices ----------------
#define WQ4 (1152 * 384 / 4)
#define WP4 (384 * 384 / 4)
#define W14 (1536 * 384 / 4)
#define W24 (384 * 1536 / 4)
__global__ void __launch_bounds__(256) f2bf_all(
        const float* __restrict__ qkv_w, const float* __restrict__ proj_w,
        const float* __restrict__ fc1_w, const float* __restrict__ fc2_w,
        bf16* __restrict__ wq, bf16* __restrict__ wp,
        bf16* __restrict__ w1, bf16* __restrict__ w2) {
    int i = blockIdx.x * 256 + threadIdx.x;
    const float* src; bf16* dst; int off;
    if (i < WQ4)                      { src = qkv_w;  dst = wq; off = i; }
    else if (i < WQ4 + WP4)           { src = proj_w; dst = wp; off = i - WQ4; }
    else if (i < WQ4 + WP4 + W14)     { src = fc1_w;  dst = w1; off = i - WQ4 - WP4; }
    else if (i < WQ4 + WP4 + W14 + W24) { src = fc2_w; dst = w2; off = i - WQ4 - WP4 - W14; }
    else return;
    float4 v = *(const float4*)(src + off * 4);
    store4(dst + off * 4, v);
}

// ---------------- 1) LN1 + roll(-4,-4) + window partition -> bf16 ----------------
__global__ void __launch_bounds__(256) ln1_shift_win(
        const float* __restrict__ x, const float* __restrict__ g,
        const float* __restrict__ b, bf16* __restrict__ xw) {
    int warp = threadIdx.x >> 5, lane = threadIdx.x & 31;
    int t = blockIdx.x * 8 + warp;
    int win = t >> 6, n = t & 63;
    int bi = win >> 6, wim = win & 63;
    int r = (((wim >> 3) << 3) + (n >> 3) + 4) & 63;
    int c = (((wim & 7) << 3) + (n & 7) + 4) & 63;
    const float* row = x + ((size_t)bi * 4096 + r * 64 + c) * Cc;
    float v[12]; float s = 0.f;
#pragma unroll
    for (int k = 0; k < 12; k++) { v[k] = row[lane + 32 * k]; s += v[k]; }
    s = warp_sum(s);
    float mean = s * (1.f / 384.f);
    float q = 0.f;
#pragma unroll
    for (int k = 0; k < 12; k++) { float d = v[k] - mean; q += d * d; }
    q = warp_sum(q);
    float rstd = rsqrtf(q * (1.f / 384.f) + EPSf);
    bf16* o = xw + (size_t)t * Cc;
#pragma unroll
    for (int k = 0; k < 12; k++) {
        int idx = lane + 32 * k;
        o[idx] = __float2bfloat16((v[k] - mean) * rstd * g[idx] + b[idx]);
    }
}

// ---------------- 5) un-window + roll(+4,+4) + residual + LN2 ----------------
__global__ void __launch_bounds__(256) resid_ln2(
        const float* __restrict__ x, const bf16* __restrict__ proj,
        const float* __restrict__ g, const float* __restrict__ b,
        float* __restrict__ x1, bf16* __restrict__ h) {
    int warp = threadIdx.x >> 5, lane = threadIdx.x & 31;
    int t = blockIdx.x * 8 + warp;
    int bi = t >> 12, l = t & 4095;
    int r = l >> 6, c = l & 63;
    int sr = (r - 4) & 63, sc = (c - 4) & 63;
    int win = bi * 64 + ((sr >> 3) << 3) + (sc >> 3);
    int nn = ((sr & 7) << 3) + (sc & 7);
    const bf16* pr = proj + ((size_t)win * 64 + nn) * Cc;
    const float* xr = x + (size_t)t * Cc;
    float* xo = x1 + (size_t)t * Cc;
    float v[12]; float s = 0.f;
#pragma unroll
    for (int k = 0; k < 12; k++) {
        int idx = lane + 32 * k;
        v[k] = xr[idx] + __bfloat162float(pr[idx]);
        xo[idx] = v[k];
        s += v[k];
    }
    s = warp_sum(s);
    float mean = s * (1.f / 384.f);
    float q = 0.f;
#pragma unroll
    for (int k = 0; k < 12; k++) { float d = v[k] - mean; q += d * d; }
    q = warp_sum(q);
    float rstd = rsqrtf(q * (1.f / 384.f) + EPSf);
    bf16* o = h + (size_t)t * Cc;
#pragma unroll
    for (int k = 0; k < 12; k++) {
        int idx = lane + 32 * k;
        o[idx] = __float2bfloat16((v[k] - mean) * rstd * g[idx] + b[idx]);
    }
}

// ---------------- 3) windowed attention, tensor-core QK^T and P@V ----------------
#define ATT_SMEM (2 * 32768)
__global__ void __launch_bounds__(128) attn_win(
        const bf16* __restrict__ qkv, const float* __restrict__ rpb,
        bf16* __restrict__ outp) {
    extern __shared__ char asm_[];
    __shared__ float rps[2][232];
    __shared__ int labs[64];
    int win = blockIdx.x;
    int tid = threadIdx.x;
    int warp = tid >> 5;
    int wy = warp & 1;
    int wh = warp >> 1;

#pragma unroll
    for (int hh = 0; hh < 2; hh++) {
        int head_h = blockIdx.y * 2 + hh;
        bf16* Q = (bf16*)(asm_ + hh * 32768);
        bf16* K = (bf16*)(asm_ + hh * 32768 + 5120);
        bf16* V = (bf16*)(asm_ + hh * 32768 + 10240);
#pragma unroll
        for (int i = 0; i < 4; i++) {
            int id = tid + 128 * i;
            int row = id >> 3, c4 = (id & 7) * 4;
            const bf16* src = qkv + ((size_t)win * 64 + row) * (3 * Cc) + head_h * 32 + c4;
            *(uint2*)(Q + row * 40 + c4) = *(const uint2*)(src);
            *(uint2*)(K + row * 40 + c4) = *(const uint2*)(src + Cc);
            *(uint2*)(V + row * 40 + c4) = *(const uint2*)(src + 2 * Cc);
        }
    }
    {
        int n = tid & 63;
        int hh = tid >> 6;
        for (int i = n; i < 225; i += 64) rps[hh][i] = rpb[i * HEADS + (blockIdx.y * 2 + hh)];
        if (tid < 64) {
            int wim = win & 63;
            int gr = ((wim >> 3) << 3) + (n >> 3);
            int gc = ((wim & 7) << 3) + (n & 7);
            labs[n] = (gr < 56 ? 0 : (gr < 60 ? 1 : 2)) * 3 + (gc < 56 ? 0 : (gc < 60 ? 1 : 2));
        }
    }
    __syncthreads();

    {
        bf16* Q = (bf16*)(asm_ + wh * 32768);
        bf16* K = (bf16*)(asm_ + wh * 32768 + 5120);
        float* S = (float*)(asm_ + wh * 32768 + 15360);
        wmma::fragment<wmma::accumulator, 16, 16, 16, float> acc[2][4];
#pragma unroll
        for (int i = 0; i < 2; i++)
#pragma unroll
            for (int j = 0; j < 4; j++) wmma::fill_fragment(acc[i][j], 0.f);
#pragma unroll
        for (int kk = 0; kk < 32; kk += 16) {
            wmma::fragment<wmma::matrix_a, 16, 16, 16, bf16, wmma::row_major> fa[2];
            wmma::fragment<wmma::matrix_b, 16, 16, 16, bf16, wmma::col_major> fb[4];
#pragma unroll
            for (int i = 0; i < 2; i++)
                wmma::load_matrix_sync(fa[i], Q + (wy * 32 + i * 16) * 40 + kk, 40);
#pragma unroll
            for (int j = 0; j < 4; j++)
                wmma::load_matrix_sync(fb[j], K + (j * 16) * 40 + kk, 40);
#pragma unroll
            for (int i = 0; i < 2; i++)
#pragma unroll
                for (int j = 0; j < 4; j++)
                    wmma::mma_sync(acc[i][j], fa[i], fb[j], acc[i][j]);
        }
#pragma unroll
        for (int i = 0; i < 2; i++)
#pragma unroll
            for (int j = 0; j < 4; j++)
                wmma::store_matrix_sync(S + (wy * 32 + i * 16) * 68 + j * 16,
                                        acc[i][j], 68, wmma::mem_row_major);
    }
    __syncthreads();

    {
        int y2 = tid >> 6, n = tid & 63;
        const float* S = (const float*)(asm_ + y2 * 32768 + 15360);
        bf16* P = (bf16*)(asm_ + y2 * 32768);
        const float SC = 0.17677669529663687f;
        int cvn = 15 * (n >> 3) + (n & 7);
        int myl = labs[n];
        float s[64];
        float mx = -1e30f;
#pragma unroll
        for (int m = 0; m < 64; m++) {
            int mm = 63 - m;
            int cvm = 15 * (mm >> 3) + (mm & 7);
            float a = S[n * 68 + m] * SC + rps[y2][cvn + cvm];
            a += (labs[m] != myl) ? -100.f : 0.f;
            s[m] = a;
            mx = fmaxf(mx, a);
        }
        float sum = 0.f;
#pragma unroll
        for (int m = 0; m < 64; m++) { float e = __expf(s[m] - mx); s[m] = e; sum += e; }
        float inv = 1.f / sum;
#pragma unroll
        for (int m = 0; m < 64; m += 2) {
            __nv_bfloat162 pr2 = __floats2bfloat162_rn(s[m] * inv, s[m + 1] * inv);
            *(__nv_bfloat162*)(P + n * 72 + m) = pr2;
        }
    }
    __syncthreads();

    {
        bf16* P = (bf16*)(asm_ + wh * 32768);
        bf16* V = (bf16*)(asm_ + wh * 32768 + 10240);
        float* S = (float*)(asm_ + wh * 32768 + 15360);
        wmma::fragment<wmma::accumulator, 16, 16, 16, float> acc[2][2];
#pragma unroll
        for (int i = 0; i < 2; i++)
#pragma unroll
            for (int j = 0; j < 2; j++) wmma::fill_fragment(acc[i][j], 0.f);
#pragma unroll
        for (int kk = 0; kk < 64; kk += 16) {
            wmma::fragment<wmma::matrix_a, 16, 16, 16, bf16, wmma::row_major> fa[2];
            wmma::fragment<wmma::matrix_b, 16, 16, 16, bf16, wmma::row_major> fb[2];
#pragma unroll
            for (int i = 0; i < 2; i++)
                wmma::load_matrix_sync(fa[i], P + (wy * 32 + i * 16) * 72 + kk, 72);
#pragma unroll
            for (int j = 0; j < 2; j++)
                wmma::load_matrix_sync(fb[j], V + kk * 40 + j * 16, 40);
#pragma unroll
            for (int i = 0; i < 2; i++)
#pragma unroll
                for (int j = 0; j < 2; j++)
                    wmma::mma_sync(acc[i][j], fa[i], fb[j], acc[i][j]);
        }
        __syncthreads();
#pragma unroll
        for (int i = 0; i < 2; i++)
#pragma unroll
            for (int j = 0; j < 2; j++)
                wmma::store_matrix_sync(S + (wy * 32 + i * 16) * 68 + j * 16,
                                        acc[i][j], 68, wmma::mem_row_major);
    }
    __syncthreads();

#pragma unroll
    for (int hh = 0; hh < 2; hh++) {
        int head_h = blockIdx.y * 2 + hh;
        const float* S = (const float*)(asm_ + hh * 32768 + 15360);
#pragma unroll
        for (int i = 0; i < 4; i++) {
            int id = tid + 128 * i;
            int row = id >> 3, c4 = (id & 7) * 4;
            float4 v = *(const float4*)(S + row * 68 + c4);
            store4(outp + ((size_t)win * 64 + row) * Cc + head_h * 32 + c4, v);
        }
    }
}

// ---------------- bf16 tensor-core GEMM, 2-stage cp.async, 3 CTAs/SM ----------------
// C[M,N] = A[M,K] @ W[N,K]^T. MODE 0: +bias  1: gelu(bn(+bias))  2: res + gelu(bn(+bias))
template <int MODE, typename OUTT>
__global__ void __launch_bounds__(128, 3) hgemm(
        const bf16* __restrict__ A, const bf16* __restrict__ Wt,
        OUTT* __restrict__ Co, const float* __restrict__ bias,
        const float* __restrict__ bng, const float* __restrict__ bnb,
        const float* __restrict__ res, int M, int Nn, int K) {
    extern __shared__ char smraw[];
    bf16* smh = (bf16*)smraw;
    bf16* Abuf[2] = { smh, smh + 2 * 128 * LDAH };
    bf16* Bbuf[2] = { smh + 128 * LDAH, smh + 3 * 128 * LDAH };

    int tid = threadIdx.x;
    int warp = tid >> 5;
    int wm = warp >> 1;
    int wn = warp & 1;
    int rowA = blockIdx.y * 128;
    int rowB = blockIdx.x * 128;

    wmma::fragment<wmma::accumulator, 16, 16, 16, float> acc[4][4];
#pragma unroll
    for (int i = 0; i < 4; i++)
#pragma unroll
        for (int j = 0; j < 4; j++) wmma::fill_fragment(acc[i][j], 0.f);

    int lrow = tid >> 3, lc = (tid & 7) * 8;
    const bf16* Ag = A  + (size_t)(rowA + lrow) * K + lc;
    const bf16* Bg = Wt + (size_t)(rowB + lrow) * K + lc;
    int nk = K >> 6;

    // prologue: stage 0
#pragma unroll
    for (int r = 0; r < 8; r++) {
        cpa16(Abuf[0] + (lrow + 16 * r) * LDAH + lc, Ag + (size_t)(16 * r) * K);
        cpa16(Bbuf[0] + (lrow + 16 * r) * LDAH + lc, Bg + (size_t)(16 * r) * K);
    }
    cpa_commit();

    for (int s = 0; s < nk; s++) {
        int cur = s & 1;
        if (s + 1 < nk) {
            int nb = cur ^ 1;
            int k0 = (s + 1) << 6;
#pragma unroll
            for (int r = 0; r < 8; r++) {
                cpa16(Abuf[nb] + (lrow + 16 * r) * LDAH + lc, Ag + (size_t)(16 * r) * K + k0);
                cpa16(Bbuf[nb] + (lrow + 16 * r) * LDAH + lc, Bg + (size_t)(16 * r) * K + k0);
            }
            cpa_commit();
            cpa_wait<1>();
        } else {
            cpa_wait<0>();
        }
        __syncthreads();
#pragma unroll
        for (int kk = 0; kk < 64; kk += 16) {
            wmma::fragment<wmma::matrix_a, 16, 16, 16, bf16, wmma::row_major> fa[4];
            wmma::fragment<wmma::matrix_b, 16, 16, 16, bf16, wmma::col_major> fb[4];
#pragma unroll
            for (int i = 0; i < 4; i++)
                wmma::load_matrix_sync(fa[i], Abuf[cur] + (wm * 64 + i * 16) * LDAH + kk, LDAH);
#pragma unroll
            for (int j = 0; j < 4; j++)
                wmma::load_matrix_sync(fb[j], Bbuf[cur] + (wn * 64 + j * 16) * LDAH + kk, LDAH);
#pragma unroll
            for (int i = 0; i < 4; i++)
#pragma unroll
                for (int j = 0; j < 4; j++)
                    wmma::mma_sync(acc[i][j], fa[i], fb[j], acc[i][j]);
        }
        __syncthreads();
    }

    // epilogue through fp32 smem C tile (reuses stage buffers)
    float* Cs = (float*)smraw;
#pragma unroll
    for (int i = 0; i < 4; i++)
#pragma unroll
        for (int j = 0; j < 4; j++)
            wmma::store_matrix_sync(Cs + (wm * 64 + i * 16) * LDC + wn * 64 + j * 16,
                                    acc[i][j], LDC, wmma::mem_row_major);
    __syncthreads();

    const float IS = rsqrtf(1.0f + EPSf);
    int q = tid & 31;
    int r0 = tid >> 5;
    int ncol = rowB + q * 4;
    float4 bv = *(const float4*)(bias + ncol);
    float4 gv = make_float4(0.f, 0.f, 0.f, 0.f), bb = gv;
    if (MODE >= 1) {
        gv = *(const float4*)(bng + ncol);
        bb = *(const float4*)(bnb + ncol);
        gv.x *= IS; gv.y *= IS; gv.z *= IS; gv.w *= IS;
    }
#pragma unroll
    for (int it = 0; it < 32; it++) {
        int r = r0 + it * 4;
        float4 v = *(const float4*)(Cs + r * LDC + q * 4);
        v.x += bv.x; v.y += bv.y; v.z += bv.z; v.w += bv.w;
        if (MODE >= 1) {
            v.x = gelu_fast(v.x * gv.x + bb.x);
            v.y = gelu_fast(v.y * gv.y + bb.y);
            v.z = gelu_fast(v.z * gv.z + bb.z);
            v.w = gelu_fast(v.w * gv.w + bb.w);
        }
        size_t off = (size_t)(rowA + r) * Nn + ncol;
        if (MODE == 2) {
            float4 rv = *(const float4*)(res + off);
            v.x += rv.x; v.y += rv.y; v.z += rv.z; v.w += rv.w;
        }
        store4(Co + off, v);
    }
}

// ---------------- 7) NHWC depthwise 3x3 + BN + GELU, 4 pixels/thread ----------------
// block = 256 thr = 8 pixel-groups x 32 c4-groups ; grid = (Tt/32, 384/32)
// thread handles 4 consecutive pixels in one image row; loads the 3x6 column window once.
__global__ void __launch_bounds__(256) dwconv_bn_gelu(
        const bf16* __restrict__ z1, const float* __restrict__ wt,
        const float* __restrict__ wb, const float* __restrict__ bng,
        const float* __restrict__ bnb, bf16* __restrict__ z2) {
    __shared__ float ws[9][4][32];
    int c4l = threadIdx.x & 31;
    int p   = threadIdx.x >> 5;              // 0..7
    int ch  = (blockIdx.y * 32 + c4l) * 4;
    for (int i = threadIdx.x; i < 1152; i += 256) {
        int cc = i & 31;
        int l  = (i >> 5) & 3;
        int k  = i >> 7;
        ws[k][l][cc] = wt[(((blockIdx.y * 32 + cc) * 4) + l) * 9 + k];
    }
    __syncthreads();

    int pixbase = blockIdx.x * 32 + p * 4;   // 4 consecutive pixels, same row (64 | 32)
    int bi = pixbase >> 12; int rc = pixbase & 4095;
    int r = rc >> 6, c = rc & 63;            // c in {0,4,...,60}
    float4 acc[4];
#pragma unroll
    for (int i = 0; i < 4; i++) acc[i] = make_float4(0.f, 0.f, 0.f, 0.f);

#pragma unroll
    for (int dr = -1; dr <= 1; dr++) {
        int rr = r + dr;
        if (rr < 0 || rr > 63) continue;
        const bf16* rowp = z1 + ((size_t)(bi * 4096 + rr * 64)) * HIDc + ch;
        int kb = (dr + 1) * 3;
#pragma unroll
        for (int j = -1; j <= 4; j++) {
            int cc = c + j;
            if (cc < 0 || cc > 63) continue;
            float4 v = load4bf(rowp + (size_t)cc * HIDc);
#pragma unroll
            for (int i = 0; i < 4; i++) {
                int d = j - i;                  // tap column offset for pixel i
                if (d < -1 || d > 1) continue;
                int k = kb + d + 1;
                acc[i].x += v.x * ws[k][0][c4l];
                acc[i].y += v.y * ws[k][1][c4l];
                acc[i].z += v.z * ws[k][2][c4l];
                acc[i].w += v.w * ws[k][3][c4l];
            }
        }
    }
    const float IS = rsqrtf(1.0f + EPSf);
    float b0 = wb[ch + 0], b1 = wb[ch + 1], b2 = wb[ch + 2], b3 = wb[ch + 3];
    float g0 = bng[ch + 0] * IS, g1 = bng[ch + 1] * IS, g2 = bng[ch + 2] * IS, g3 = bng[ch + 3] * IS;
    float c0 = bnb[ch + 0], c1 = bnb[ch + 1], c2 = bnb[ch + 2], c3 = bnb[ch + 3];
#pragma unroll
    for (int i = 0; i < 4; i++) {
        float4 o;
        o.x = gelu_fast((acc[i].x + b0) * g0 + c0);
        o.y = gelu_fast((acc[i].y + b1) * g1 + c1);
        o.z = gelu_fast((acc[i].z + b2) * g2 + c2);
        o.w = gelu_fast((acc[i].w + b3) * g3 + c3);
        store4(z2 + (size_t)(pixbase + i) * HIDc + ch, o);
    }
}

// ---------------- launcher ----------------
extern "C" void kernel_launch(void* const* d_in, const int* in_sizes, int n_in,
                              void* d_out, int out_size) {
    (void)in_sizes; (void)n_in; (void)out_size;
    const float* x      = (const float*)d_in[0];
    const float* ln1_g  = (const float*)d_in[3];
    const float* ln1_b  = (const float*)d_in[4];
    const float* qkv_w  = (const float*)d_in[5];
    const float* qkv_b  = (const float*)d_in[6];
    const float* rpb    = (const float*)d_in[7];
    const float* proj_w = (const float*)d_in[8];
    const float* proj_b = (const float*)d_in[9];
    const float* ln2_g  = (const float*)d_in[10];
    const float* ln2_b  = (const float*)d_in[11];
    const float* fc1_w  = (const float*)d_in[12];
    const float* fc1_b  = (const float*)d_in[13];
    const float* bn1_g  = (const float*)d_in[14];
    const float* bn1_b  = (const float*)d_in[15];
    const float* dw_w   = (const float*)d_in[16];
    const float* dw_b   = (const float*)d_in[17];
    const float* bn2_g  = (const float*)d_in[18];
    const float* bn2_b  = (const float*)d_in[19];
    const float* fc2_w  = (const float*)d_in[20];
    const float* fc2_b  = (const float*)d_in[21];
    const float* bn3_g  = (const float*)d_in[22];
    const float* bn3_b  = (const float*)d_in[23];
    float* out = (float*)d_out;

    bf16 *xw, *qkvb, *at, *pj, *h, *z1, *z2, *wq, *wp, *w1, *w2;
    float *x1;
    cudaGetSymbolAddress((void**)&xw,   g_xw);
    cudaGetSymbolAddress((void**)&qkvb, g_qkv);
    cudaGetSymbolAddress((void**)&at,   g_at);
    cudaGetSymbolAddress((void**)&pj,   g_pj);
    cudaGetSymbolAddress((void**)&x1,   g_x1);
    cudaGetSymbolAddress((void**)&h,    g_h);
    cudaGetSymbolAddress((void**)&z1,   g_z1);
    cudaGetSymbolAddress((void**)&z2,   g_z2);
    cudaGetSymbolAddress((void**)&wq,   g_wq);
    cudaGetSymbolAddress((void**)&wp,   g_wp);
    cudaGetSymbolAddress((void**)&w1,   g_w1);
    cudaGetSymbolAddress((void**)&w2,   g_w2);

    cudaFuncSetAttribute((const void*)hgemm<0, bf16>,  cudaFuncAttributeMaxDynamicSharedMemorySize, SMEMB);
    cudaFuncSetAttribute((const void*)hgemm<1, bf16>,  cudaFuncAttributeMaxDynamicSharedMemorySize, SMEMB);
    cudaFuncSetAttribute((const void*)hgemm<2, float>, cudaFuncAttributeMaxDynamicSharedMemorySize, SMEMB);
    cudaFuncSetAttribute((const void*)attn_win, cudaFuncAttributeMaxDynamicSharedMemorySize, ATT_SMEM);

    f2bf_all<<<(WQ4 + WP4 + W14 + W24 + 255) / 256, 256>>>(qkv_w, proj_w, fc1_w, fc2_w,
                                                           wq, wp, w1, w2);

    ln1_shift_win<<<Tt / 8, 256>>>(x, ln1_g, ln1_b, xw);
    hgemm<0, bf16><<<dim3(1152 / 128, Tt / 128), 128, SMEMB>>>(xw, wq, qkvb, qkv_b,
                                                  nullptr, nullptr, nullptr, Tt, 1152, Cc);
    attn_win<<<dim3(1024, HEADS / 2), 128, ATT_SMEM>>>(qkvb, rpb, at);
    hgemm<0, bf16><<<dim3(384 / 128, Tt / 128), 128, SMEMB>>>(at, wp, pj, proj_b,
                                                 nullptr, nullptr, nullptr, Tt, Cc, Cc);
    resid_ln2<<<Tt / 8, 256>>>(x, pj, ln2_g, ln2_b, x1, h);
    hgemm<1, bf16><<<dim3(HIDc / 128, Tt / 128), 128, SMEMB>>>(h, w1, z1, fc1_b,
                                                  bn1_g, bn1_b, nullptr, Tt, HIDc, Cc);
    dwconv_bn_gelu<<<dim3(Tt / 32, HIDc / 4 / 32), 256>>>(z1, dw_w, dw_b, bn2_g, bn2_b, z2);
    hgemm<2, float><<<dim3(384 / 128, Tt / 128), 128, SMEMB>>>(z2, w2, out, fc2_b,
                                                 bn3_g, bn3_b, x1, Tt, Cc, HIDc);
}

// round 13
// speedup vs baseline: 10.7819x; 1.0076x over previous
#include <cuda_runtime.h>
#include <cstdint>
#include <math.h>
#include <mma.h>
#include <cuda_bf16.h>

using namespace nvcuda;

#define Cc    384
#define HEADS 12
#define HIDc  1536
#define Tt    65536          // total tokens = 16*64*64
#define EPSf  1e-5f

#define LDAH  72             // 64 k halfs + 8 pad -> conflict-free ldmatrix
#define LDC   132            // 128 + 4 pad (fp32 C tile)
#define SMEMB (4 * 128 * LDAH * 2)   // 73728 B: 2 stages x {A,B} bf16; C tile (67.6KB) fits

typedef __nv_bfloat16 bf16;

// ---------------- scratch (device globals; no allocation) ----------------
__device__ bf16  g_xw [(size_t)Tt * Cc];        // LN1 out (bf16)
__device__ bf16  g_qkv[(size_t)Tt * 3 * Cc];    // qkv (bf16)
__device__ bf16  g_at [(size_t)Tt * Cc];        // attention out (bf16)
__device__ bf16  g_pj [(size_t)Tt * Cc];        // proj out (bf16)
__device__ float g_x1 [(size_t)Tt * Cc];        // x + attn (fp32 residual)
__device__ bf16  g_h  [(size_t)Tt * Cc];        // LN2 out (bf16)
__device__ bf16  g_z1 [(size_t)Tt * HIDc];      // fc1 out (bf16)
__device__ bf16  g_z2 [(size_t)Tt * HIDc];      // dwconv out (bf16)
__device__ bf16  g_wq [1152 * 384];
__device__ bf16  g_wp [384 * 384];
__device__ bf16  g_w1 [1536 * 384];
__device__ bf16  g_w2 [384 * 1536];

__device__ __forceinline__ float gelu_fast(float x) {
    float u = 0.7978845608028654f * x * (1.0f + 0.044715f * x * x);
    float t;
    asm("tanh.approx.f32 %0, %1;" : "=f"(t) : "f"(u));
    return 0.5f * x * (1.0f + t);
}
__device__ __forceinline__ float warp_sum(float v) {
#pragma unroll
    for (int o = 16; o; o >>= 1) v += __shfl_xor_sync(0xffffffffu, v, o);
    return v;
}
__device__ __forceinline__ void cpa16(void* dst, const void* src) {
    unsigned int s = (unsigned int)__cvta_generic_to_shared(dst);
    asm volatile("cp.async.cg.shared.global [%0], [%1], 16;\n" :: "r"(s), "l"(src));
}
__device__ __forceinline__ void cpa_commit() { asm volatile("cp.async.commit_group;\n"); }
template <int N>
__device__ __forceinline__ void cpa_wait() { asm volatile("cp.async.wait_group %0;\n" :: "n"(N)); }

__device__ __forceinline__ void store4(float* p, float4 v) { *(float4*)p = v; }
__device__ __forceinline__ void store4(bf16* p, float4 v) {
    __nv_bfloat162 lo = __floats2bfloat162_rn(v.x, v.y);
    __nv_bfloat162 hi = __floats2bfloat162_rn(v.z, v.w);
    uint2 u; u.x = *(unsigned int*)&lo; u.y = *(unsigned int*)&hi;
    *(uint2*)p = u;
}
__device__ __forceinline__ float4 load4bf(const bf16* p) {
    uint2 raw = *(const uint2*)p;
    float2 a = __bfloat1622float2(*(__nv_bfloat162*)&raw.x);
    float2 b = __bfloat1622float2(*(__nv_bfloat162*)&raw.y);
    return make_float4(a.x, a.y, b.x, b.y);
}

// ---------------- fused f32 -> bf16 convert of all 4 weight matrices ----------------
#define WQ4 (1152 * 384 / 4)
#define WP4 (384 * 384 / 4)
#define W14 (1536 * 384 / 4)
#define W24 (384 * 1536 / 4)
__global__ void __launch_bounds__(256) f2bf_all(
        const float* __restrict__ qkv_w, const float* __restrict__ proj_w,
        const float* __restrict__ fc1_w, const float* __restrict__ fc2_w,
        bf16* __restrict__ wq, bf16* __restrict__ wp,
        bf16* __restrict__ w1, bf16* __restrict__ w2) {
    int i = blockIdx.x * 256 + threadIdx.x;
    const float* src; bf16* dst; int off;
    if (i < WQ4)                      { src = qkv_w;  dst = wq; off = i; }
    else if (i < WQ4 + WP4)           { src = proj_w; dst = wp; off = i - WQ4; }
    else if (i < WQ4 + WP4 + W14)     { src = fc1_w;  dst = w1; off = i - WQ4 - WP4; }
    else if (i < WQ4 + WP4 + W14 + W24) { src = fc2_w; dst = w2; off = i - WQ4 - WP4 - W14; }
    else return;
    float4 v = *(const float4*)(src + off * 4);
    store4(dst + off * 4, v);
}

// ---------------- 1) LN1 + roll(-4,-4) + window partition -> bf16 ----------------
__global__ void __launch_bounds__(256) ln1_shift_win(
        const float* __restrict__ x, const float* __restrict__ g,
        const float* __restrict__ b, bf16* __restrict__ xw) {
    int warp = threadIdx.x >> 5, lane = threadIdx.x & 31;
    int t = blockIdx.x * 8 + warp;
    int win = t >> 6, n = t & 63;
    int bi = win >> 6, wim = win & 63;
    int r = (((wim >> 3) << 3) + (n >> 3) + 4) & 63;
    int c = (((wim & 7) << 3) + (n & 7) + 4) & 63;
    const float* row = x + ((size_t)bi * 4096 + r * 64 + c) * Cc;
    float v[12]; float s = 0.f;
#pragma unroll
    for (int k = 0; k < 12; k++) { v[k] = row[lane + 32 * k]; s += v[k]; }
    s = warp_sum(s);
    float mean = s * (1.f / 384.f);
    float q = 0.f;
#pragma unroll
    for (int k = 0; k < 12; k++) { float d = v[k] - mean; q += d * d; }
    q = warp_sum(q);
    float rstd = rsqrtf(q * (1.f / 384.f) + EPSf);
    bf16* o = xw + (size_t)t * Cc;
#pragma unroll
    for (int k = 0; k < 12; k++) {
        int idx = lane + 32 * k;
        o[idx] = __float2bfloat16((v[k] - mean) * rstd * g[idx] + b[idx]);
    }
}

// ---------------- 5) un-window + roll(+4,+4) + residual + LN2 ----------------
__global__ void __launch_bounds__(256) resid_ln2(
        const float* __restrict__ x, const bf16* __restrict__ proj,
        const float* __restrict__ g, const float* __restrict__ b,
        float* __restrict__ x1, bf16* __restrict__ h) {
    int warp = threadIdx.x >> 5, lane = threadIdx.x & 31;
    int t = blockIdx.x * 8 + warp;
    int bi = t >> 12, l = t & 4095;
    int r = l >> 6, c = l & 63;
    int sr = (r - 4) & 63, sc = (c - 4) & 63;
    int win = bi * 64 + ((sr >> 3) << 3) + (sc >> 3);
    int nn = ((sr & 7) << 3) + (sc & 7);
    const bf16* pr = proj + ((size_t)win * 64 + nn) * Cc;
    const float* xr = x + (size_t)t * Cc;
    float* xo = x1 + (size_t)t * Cc;
    float v[12]; float s = 0.f;
#pragma unroll
    for (int k = 0; k < 12; k++) {
        int idx = lane + 32 * k;
        v[k] = xr[idx] + __bfloat162float(pr[idx]);
        xo[idx] = v[k];
        s += v[k];
    }
    s = warp_sum(s);
    float mean = s * (1.f / 384.f);
    float q = 0.f;
#pragma unroll
    for (int k = 0; k < 12; k++) { float d = v[k] - mean; q += d * d; }
    q = warp_sum(q);
    float rstd = rsqrtf(q * (1.f / 384.f) + EPSf);
    bf16* o = h + (size_t)t * Cc;
#pragma unroll
    for (int k = 0; k < 12; k++) {
        int idx = lane + 32 * k;
        o[idx] = __float2bfloat16((v[k] - mean) * rstd * g[idx] + b[idx]);
    }
}

// ---------------- 3) windowed attention: one (window, head) per block ----------------
// 128 thr = 4 warps; smem 32 KB: Q[64][40] bf16 @0 | K @5120 | V @10240 | S[64][68] f32 @15360.
// P[64][72] bf16 overlays Q+K after softmax.
#define ATT_SMEM 32768
__global__ void __launch_bounds__(128) attn_win(
        const bf16* __restrict__ qkv, const float* __restrict__ rpb,
        bf16* __restrict__ outp) {
    extern __shared__ char asm_[];
    __shared__ float rps[232];
    __shared__ int labs[64];
    int win = blockIdx.x;
    int head = blockIdx.y;
    int tid = threadIdx.x;
    int warp = tid >> 5;

    bf16* Q = (bf16*)(asm_);
    bf16* K = (bf16*)(asm_ + 5120);
    bf16* V = (bf16*)(asm_ + 10240);
    float* S = (float*)(asm_ + 15360);

    // cooperative load of Q,K,V (64 rows x 32 cols bf16 each)
#pragma unroll
    for (int i = 0; i < 4; i++) {
        int id = tid + 128 * i;
        int row = id >> 3, c4 = (id & 7) * 4;
        const bf16* src = qkv + ((size_t)win * 64 + row) * (3 * Cc) + head * 32 + c4;
        *(uint2*)(Q + row * 40 + c4) = *(const uint2*)(src);
        *(uint2*)(K + row * 40 + c4) = *(const uint2*)(src + Cc);
        *(uint2*)(V + row * 40 + c4) = *(const uint2*)(src + 2 * Cc);
    }
    for (int i = tid; i < 225; i += 128) rps[i] = rpb[i * HEADS + head];
    if (tid < 64) {
        int n = tid;
        int wim = win & 63;
        int gr = ((wim >> 3) << 3) + (n >> 3);
        int gc = ((wim & 7) << 3) + (n & 7);
        labs[n] = (gr < 56 ? 0 : (gr < 60 ? 1 : 2)) * 3 + (gc < 56 ? 0 : (gc < 60 ? 1 : 2));
    }
    __syncthreads();

    // --- S = Q @ K^T (64x64x32): warp w does rows w*16..+15 ---
    {
        wmma::fragment<wmma::accumulator, 16, 16, 16, float> acc[4];
#pragma unroll
        for (int j = 0; j < 4; j++) wmma::fill_fragment(acc[j], 0.f);
#pragma unroll
        for (int kk = 0; kk < 32; kk += 16) {
            wmma::fragment<wmma::matrix_a, 16, 16, 16, bf16, wmma::row_major> fa;
            wmma::fragment<wmma::matrix_b, 16, 16, 16, bf16, wmma::col_major> fb[4];
            wmma::load_matrix_sync(fa, Q + (warp * 16) * 40 + kk, 40);
#pragma unroll
            for (int j = 0; j < 4; j++)
                wmma::load_matrix_sync(fb[j], K + (j * 16) * 40 + kk, 40);
#pragma unroll
            for (int j = 0; j < 4; j++)
                wmma::mma_sync(acc[j], fa, fb[j], acc[j]);
        }
#pragma unroll
        for (int j = 0; j < 4; j++)
            wmma::store_matrix_sync(S + (warp * 16) * 68 + j * 16, acc[j], 68,
                                    wmma::mem_row_major);
    }
    __syncthreads();

    // --- softmax: threads 0..63, one row each; write P (bf16) over Q/K ---
    if (tid < 64) {
        int n = tid;
        bf16* P = (bf16*)asm_;
        const float SC = 0.17677669529663687f;   // 1/sqrt(32)
        int cvn = 15 * (n >> 3) + (n & 7);
        int myl = labs[n];
        float s[64];
        float mx = -1e30f;
#pragma unroll
        for (int m = 0; m < 64; m++) {
            int mm = 63 - m;
            int cvm = 15 * (mm >> 3) + (mm & 7);
            float a = S[n * 68 + m] * SC + rps[cvn + cvm];
            a += (labs[m] != myl) ? -100.f : 0.f;
            s[m] = a;
            mx = fmaxf(mx, a);
        }
        float sum = 0.f;
#pragma unroll
        for (int m = 0; m < 64; m++) { float e = __expf(s[m] - mx); s[m] = e; sum += e; }
        float inv = 1.f / sum;
#pragma unroll
        for (int m = 0; m < 64; m += 2) {
            __nv_bfloat162 pr2 = __floats2bfloat162_rn(s[m] * inv, s[m + 1] * inv);
            *(__nv_bfloat162*)(P + n * 72 + m) = pr2;
        }
    }
    __syncthreads();

    // --- O = P @ V (64x32x64): warp w rows w*16..+15; result into S ---
    {
        bf16* P = (bf16*)asm_;
        wmma::fragment<wmma::accumulator, 16, 16, 16, float> acc[2];
#pragma unroll
        for (int j = 0; j < 2; j++) wmma::fill_fragment(acc[j], 0.f);
#pragma unroll
        for (int kk = 0; kk < 64; kk += 16) {
            wmma::fragment<wmma::matrix_a, 16, 16, 16, bf16, wmma::row_major> fa;
            wmma::fragment<wmma::matrix_b, 16, 16, 16, bf16, wmma::row_major> fb[2];
            wmma::load_matrix_sync(fa, P + (warp * 16) * 72 + kk, 72);
#pragma unroll
            for (int j = 0; j < 2; j++)
                wmma::load_matrix_sync(fb[j], V + kk * 40 + j * 16, 40);
#pragma unroll
            for (int j = 0; j < 2; j++)
                wmma::mma_sync(acc[j], fa, fb[j], acc[j]);
        }
#pragma unroll
        for (int j = 0; j < 2; j++)
            wmma::store_matrix_sync(S + (warp * 16) * 68 + j * 16, acc[j], 68,
                                    wmma::mem_row_major);
    }
    __syncthreads();

    // --- coalesced bf16 store of O ---
#pragma unroll
    for (int i = 0; i < 4; i++) {
        int id = tid + 128 * i;
        int row = id >> 3, c4 = (id & 7) * 4;
        float4 v = *(const float4*)(S + row * 68 + c4);
        store4(outp + ((size_t)win * 64 + row) * Cc + head * 32 + c4, v);
    }
}

// ---------------- bf16 tensor-core GEMM, 2-stage cp.async, 3 CTAs/SM ----------------
// C[M,N] = A[M,K] @ W[N,K]^T. MODE 0: +bias  1: gelu(bn(+bias))  2: res + gelu(bn(+bias))
template <int MODE, typename OUTT>
__global__ void __launch_bounds__(128, 3) hgemm(
        const bf16* __restrict__ A, const bf16* __restrict__ Wt,
        OUTT* __restrict__ Co, const float* __restrict__ bias,
        const float* __restrict__ bng, const float* __restrict__ bnb,
        const float* __restrict__ res, int M, int Nn, int K) {
    extern __shared__ char smraw[];
    bf16* smh = (bf16*)smraw;
    bf16* Abuf[2] = { smh, smh + 2 * 128 * LDAH };
    bf16* Bbuf[2] = { smh + 128 * LDAH, smh + 3 * 128 * LDAH };

    int tid = threadIdx.x;
    int warp = tid >> 5;
    int wm = warp >> 1;
    int wn = warp & 1;
    int rowA = blockIdx.y * 128;
    int rowB = blockIdx.x * 128;

    wmma::fragment<wmma::accumulator, 16, 16, 16, float> acc[4][4];
#pragma unroll
    for (int i = 0; i < 4; i++)
#pragma unroll
        for (int j = 0; j < 4; j++) wmma::fill_fragment(acc[i][j], 0.f);

    int lrow = tid >> 3, lc = (tid & 7) * 8;
    const bf16* Ag = A  + (size_t)(rowA + lrow) * K + lc;
    const bf16* Bg = Wt + (size_t)(rowB + lrow) * K + lc;
    int nk = K >> 6;

    // prologue: stage 0
#pragma unroll
    for (int r = 0; r < 8; r++) {
        cpa16(Abuf[0] + (lrow + 16 * r) * LDAH + lc, Ag + (size_t)(16 * r) * K);
        cpa16(Bbuf[0] + (lrow + 16 * r) * LDAH + lc, Bg + (size_t)(16 * r) * K);
    }
    cpa_commit();

    for (int s = 0; s < nk; s++) {
        int cur = s & 1;
        if (s + 1 < nk) {
            int nb = cur ^ 1;
            int k0 = (s + 1) << 6;
#pragma unroll
            for (int r = 0; r < 8; r++) {
                cpa16(Abuf[nb] + (lrow + 16 * r) * LDAH + lc, Ag + (size_t)(16 * r) * K + k0);
                cpa16(Bbuf[nb] + (lrow + 16 * r) * LDAH + lc, Bg + (size_t)(16 * r) * K + k0);
            }
            cpa_commit();
            cpa_wait<1>();
        } else {
            cpa_wait<0>();
        }
        __syncthreads();
#pragma unroll
        for (int kk = 0; kk < 64; kk += 16) {
            wmma::fragment<wmma::matrix_a, 16, 16, 16, bf16, wmma::row_major> fa[4];
            wmma::fragment<wmma::matrix_b, 16, 16, 16, bf16, wmma::col_major> fb[4];
#pragma unroll
            for (int i = 0; i < 4; i++)
                wmma::load_matrix_sync(fa[i], Abuf[cur] + (wm * 64 + i * 16) * LDAH + kk, LDAH);
#pragma unroll
            for (int j = 0; j < 4; j++)
                wmma::load_matrix_sync(fb[j], Bbuf[cur] + (wn * 64 + j * 16) * LDAH + kk, LDAH);
#pragma unroll
            for (int i = 0; i < 4; i++)
#pragma unroll
                for (int j = 0; j < 4; j++)
                    wmma::mma_sync(acc[i][j], fa[i], fb[j], acc[i][j]);
        }
        __syncthreads();
    }

    // epilogue through fp32 smem C tile (reuses stage buffers)
    float* Cs = (float*)smraw;
#pragma unroll
    for (int i = 0; i < 4; i++)
#pragma unroll
        for (int j = 0; j < 4; j++)
            wmma::store_matrix_sync(Cs + (wm * 64 + i * 16) * LDC + wn * 64 + j * 16,
                                    acc[i][j], LDC, wmma::mem_row_major);
    __syncthreads();

    const float IS = rsqrtf(1.0f + EPSf);
    int q = tid & 31;
    int r0 = tid >> 5;
    int ncol = rowB + q * 4;
    float4 bv = *(const float4*)(bias + ncol);
    float4 gv = make_float4(0.f, 0.f, 0.f, 0.f), bb = gv;
    if (MODE >= 1) {
        gv = *(const float4*)(bng + ncol);
        bb = *(const float4*)(bnb + ncol);
        gv.x *= IS; gv.y *= IS; gv.z *= IS; gv.w *= IS;
    }
#pragma unroll
    for (int it = 0; it < 32; it++) {
        int r = r0 + it * 4;
        float4 v = *(const float4*)(Cs + r * LDC + q * 4);
        v.x += bv.x; v.y += bv.y; v.z += bv.z; v.w += bv.w;
        if (MODE >= 1) {
            v.x = gelu_fast(v.x * gv.x + bb.x);
            v.y = gelu_fast(v.y * gv.y + bb.y);
            v.z = gelu_fast(v.z * gv.z + bb.z);
            v.w = gelu_fast(v.w * gv.w + bb.w);
        }
        size_t off = (size_t)(rowA + r) * Nn + ncol;
        if (MODE == 2) {
            float4 rv = *(const float4*)(res + off);
            v.x += rv.x; v.y += rv.y; v.z += rv.z; v.w += rv.w;
        }
        store4(Co + off, v);
    }
}

// ---------------- 7) NHWC depthwise 3x3 + BN + GELU, 4 pixels/thread ----------------
__global__ void __launch_bounds__(256) dwconv_bn_gelu(
        const bf16* __restrict__ z1, const float* __restrict__ wt,
        const float* __restrict__ wb, const float* __restrict__ bng,
        const float* __restrict__ bnb, bf16* __restrict__ z2) {
    __shared__ float ws[9][4][32];
    int c4l = threadIdx.x & 31;
    int p   = threadIdx.x >> 5;              // 0..7
    int ch  = (blockIdx.y * 32 + c4l) * 4;
    for (int i = threadIdx.x; i < 1152; i += 256) {
        int cc = i & 31;
        int l  = (i >> 5) & 3;
        int k  = i >> 7;
        ws[k][l][cc] = wt[(((blockIdx.y * 32 + cc) * 4) + l) * 9 + k];
    }
    __syncthreads();

    int pixbase = blockIdx.x * 32 + p * 4;
    int bi = pixbase >> 12; int rc = pixbase & 4095;
    int r = rc >> 6, c = rc & 63;
    float4 acc[4];
#pragma unroll
    for (int i = 0; i < 4; i++) acc[i] = make_float4(0.f, 0.f, 0.f, 0.f);

#pragma unroll
    for (int dr = -1; dr <= 1; dr++) {
        int rr = r + dr;
        if (rr < 0 || rr > 63) continue;
        const bf16* rowp = z1 + ((size_t)(bi * 4096 + rr * 64)) * HIDc + ch;
        int kb = (dr + 1) * 3;
#pragma unroll
        for (int j = -1; j <= 4; j++) {
            int cc = c + j;
            if (cc < 0 || cc > 63) continue;
            float4 v = load4bf(rowp + (size_t)cc * HIDc);
#pragma unroll
            for (int i = 0; i < 4; i++) {
                int d = j - i;
                if (d < -1 || d > 1) continue;
                int k = kb + d + 1;
                acc[i].x += v.x * ws[k][0][c4l];
                acc[i].y += v.y * ws[k][1][c4l];
                acc[i].z += v.z * ws[k][2][c4l];
                acc[i].w += v.w * ws[k][3][c4l];
            }
        }
    }
    const float IS = rsqrtf(1.0f + EPSf);
    float b0 = wb[ch + 0], b1 = wb[ch + 1], b2 = wb[ch + 2], b3 = wb[ch + 3];
    float g0 = bng[ch + 0] * IS, g1 = bng[ch + 1] * IS, g2 = bng[ch + 2] * IS, g3 = bng[ch + 3] * IS;
    float c0 = bnb[ch + 0], c1 = bnb[ch + 1], c2 = bnb[ch + 2], c3 = bnb[ch + 3];
#pragma unroll
    for (int i = 0; i < 4; i++) {
        float4 o;
        o.x = gelu_fast((acc[i].x + b0) * g0 + c0);
        o.y = gelu_fast((acc[i].y + b1) * g1 + c1);
        o.z = gelu_fast((acc[i].z + b2) * g2 + c2);
        o.w = gelu_fast((acc[i].w + b3) * g3 + c3);
        store4(z2 + (size_t)(pixbase + i) * HIDc + ch, o);
    }
}

// ---------------- launcher ----------------
extern "C" void kernel_launch(void* const* d_in, const int* in_sizes, int n_in,
                              void* d_out, int out_size) {
    (void)in_sizes; (void)n_in; (void)out_size;
    const float* x      = (const float*)d_in[0];
    const float* ln1_g  = (const float*)d_in[3];
    const float* ln1_b  = (const float*)d_in[4];
    const float* qkv_w  = (const float*)d_in[5];
    const float* qkv_b  = (const float*)d_in[6];
    const float* rpb    = (const float*)d_in[7];
    const float* proj_w = (const float*)d_in[8];
    const float* proj_b = (const float*)d_in[9];
    const float* ln2_g  = (const float*)d_in[10];
    const float* ln2_b  = (const float*)d_in[11];
    const float* fc1_w  = (const float*)d_in[12];
    const float* fc1_b  = (const float*)d_in[13];
    const float* bn1_g  = (const float*)d_in[14];
    const float* bn1_b  = (const float*)d_in[15];
    const float* dw_w   = (const float*)d_in[16];
    const float* dw_b   = (const float*)d_in[17];
    const float* bn2_g  = (const float*)d_in[18];
    const float* bn2_b  = (const float*)d_in[19];
    const float* fc2_w  = (const float*)d_in[20];
    const float* fc2_b  = (const float*)d_in[21];
    const float* bn3_g  = (const float*)d_in[22];
    const float* bn3_b  = (const float*)d_in[23];
    float* out = (float*)d_out;

    bf16 *xw, *qkvb, *at, *pj, *h, *z1, *z2, *wq, *wp, *w1, *w2;
    float *x1;
    cudaGetSymbolAddress((void**)&xw,   g_xw);
    cudaGetSymbolAddress((void**)&qkvb, g_qkv);
    cudaGetSymbolAddress((void**)&at,   g_at);
    cudaGetSymbolAddress((void**)&pj,   g_pj);
    cudaGetSymbolAddress((void**)&x1,   g_x1);
    cudaGetSymbolAddress((void**)&h,    g_h);
    cudaGetSymbolAddress((void**)&z1,   g_z1);
    cudaGetSymbolAddress((void**)&z2,   g_z2);
    cudaGetSymbolAddress((void**)&wq,   g_wq);
    cudaGetSymbolAddress((void**)&wp,   g_wp);
    cudaGetSymbolAddress((void**)&w1,   g_w1);
    cudaGetSymbolAddress((void**)&w2,   g_w2);

    cudaFuncSetAttribute((const void*)hgemm<0, bf16>,  cudaFuncAttributeMaxDynamicSharedMemorySize, SMEMB);
    cudaFuncSetAttribute((const void*)hgemm<1, bf16>,  cudaFuncAttributeMaxDynamicSharedMemorySize, SMEMB);
    cudaFuncSetAttribute((const void*)hgemm<2, float>, cudaFuncAttributeMaxDynamicSharedMemorySize, SMEMB);
    cudaFuncSetAttribute((const void*)attn_win, cudaFuncAttributeMaxDynamicSharedMemorySize, ATT_SMEM);

    f2bf_all<<<(WQ4 + WP4 + W14 + W24 + 255) / 256, 256>>>(qkv_w, proj_w, fc1_w, fc2_w,
                                                           wq, wp, w1, w2);

    ln1_shift_win<<<Tt / 8, 256>>>(x, ln1_g, ln1_b, xw);
    hgemm<0, bf16><<<dim3(1152 / 128, Tt / 128), 128, SMEMB>>>(xw, wq, qkvb, qkv_b,
                                                  nullptr, nullptr, nullptr, Tt, 1152, Cc);
    attn_win<<<dim3(1024, HEADS), 128, ATT_SMEM>>>(qkvb, rpb, at);
    hgemm<0, bf16><<<dim3(384 / 128, Tt / 128), 128, SMEMB>>>(at, wp, pj, proj_b,
                                                 nullptr, nullptr, nullptr, Tt, Cc, Cc);
    resid_ln2<<<Tt / 8, 256>>>(x, pj, ln2_g, ln2_b, x1, h);
    hgemm<1, bf16><<<dim3(HIDc / 128, Tt / 128), 128, SMEMB>>>(h, w1, z1, fc1_b,
                                                  bn1_g, bn1_b, nullptr, Tt, HIDc, Cc);
    dwconv_bn_gelu<<<dim3(Tt / 32, HIDc / 4 / 32), 256>>>(z1, dw_w, dw_b, bn2_g, bn2_b, z2);
    hgemm<2, float><<<dim3(384 / 128, Tt / 128), 128, SMEMB>>>(z2, w2, out, fc2_b,
                                                 bn3_g, bn3_b, x1, Tt, Cc, HIDc);
}

// round 14
// speedup vs baseline: 10.8135x; 1.0029x over previous
#include <cuda_runtime.h>
#include <cstdint>
#include <math.h>
#include <mma.h>
#include <cuda_bf16.h>

using namespace nvcuda;

#define Cc    384
#define HEADS 12
#define HIDc  1536
#define Tt    65536          // total tokens = 16*64*64
#define EPSf  1e-5f

#define LDAH  72             // 64 k halfs + 8 pad -> conflict-free ldmatrix
#define LDC   132            // 128 + 4 pad (fp32 C tile)
#define SMEMB (4 * 128 * LDAH * 2)   // 73728 B: 2 stages x {A,B} bf16; C tile (67.6KB) fits

typedef __nv_bfloat16 bf16;

// ---------------- scratch (device globals; no allocation) ----------------
__device__ bf16  g_xw [(size_t)Tt * Cc];        // LN1 out (bf16)
__device__ bf16  g_qkv[(size_t)Tt * 3 * Cc];    // qkv (bf16)
__device__ bf16  g_at [(size_t)Tt * Cc];        // attention out (bf16)
__device__ bf16  g_pj [(size_t)Tt * Cc];        // proj out (bf16, window order)
__device__ bf16  g_h  [(size_t)Tt * Cc];        // LN2 out (bf16)
__device__ bf16  g_z1 [(size_t)Tt * HIDc];      // fc1 out (bf16)
__device__ bf16  g_z2 [(size_t)Tt * HIDc];      // dwconv out (bf16)
__device__ bf16  g_wq [1152 * 384];
__device__ bf16  g_wp [384 * 384];
__device__ bf16  g_w1 [1536 * 384];
__device__ bf16  g_w2 [384 * 1536];

__device__ __forceinline__ float gelu_fast(float x) {
    float u = 0.7978845608028654f * x * (1.0f + 0.044715f * x * x);
    float t;
    asm("tanh.approx.f32 %0, %1;" : "=f"(t) : "f"(u));
    return 0.5f * x * (1.0f + t);
}
__device__ __forceinline__ float warp_sum(float v) {
#pragma unroll
    for (int o = 16; o; o >>= 1) v += __shfl_xor_sync(0xffffffffu, v, o);
    return v;
}
__device__ __forceinline__ void cpa16(void* dst, const void* src) {
    unsigned int s = (unsigned int)__cvta_generic_to_shared(dst);
    asm volatile("cp.async.cg.shared.global [%0], [%1], 16;\n" :: "r"(s), "l"(src));
}
__device__ __forceinline__ void cpa_commit() { asm volatile("cp.async.commit_group;\n"); }
template <int N>
__device__ __forceinline__ void cpa_wait() { asm volatile("cp.async.wait_group %0;\n" :: "n"(N)); }

__device__ __forceinline__ void store4(float* p, float4 v) { *(float4*)p = v; }
__device__ __forceinline__ void store4(bf16* p, float4 v) {
    __nv_bfloat162 lo = __floats2bfloat162_rn(v.x, v.y);
    __nv_bfloat162 hi = __floats2bfloat162_rn(v.z, v.w);
    uint2 u; u.x = *(unsigned int*)&lo; u.y = *(unsigned int*)&hi;
    *(uint2*)p = u;
}
__device__ __forceinline__ float4 load4bf(const bf16* p) {
    uint2 raw = *(const uint2*)p;
    float2 a = __bfloat1622float2(*(__nv_bfloat162*)&raw.x);
    float2 b = __bfloat1622float2(*(__nv_bfloat162*)&raw.y);
    return make_float4(a.x, a.y, b.x, b.y);
}

// ---------------- fused f32 -> bf16 convert of all 4 weight matrices ----------------
#define WQ4 (1152 * 384 / 4)
#define WP4 (384 * 384 / 4)
#define W14 (1536 * 384 / 4)
#define W24 (384 * 1536 / 4)
__global__ void __launch_bounds__(256) f2bf_all(
        const float* __restrict__ qkv_w, const float* __restrict__ proj_w,
        const float* __restrict__ fc1_w, const float* __restrict__ fc2_w,
        bf16* __restrict__ wq, bf16* __restrict__ wp,
        bf16* __restrict__ w1, bf16* __restrict__ w2) {
    int i = blockIdx.x * 256 + threadIdx.x;
    const float* src; bf16* dst; int off;
    if (i < WQ4)                      { src = qkv_w;  dst = wq; off = i; }
    else if (i < WQ4 + WP4)           { src = proj_w; dst = wp; off = i - WQ4; }
    else if (i < WQ4 + WP4 + W14)     { src = fc1_w;  dst = w1; off = i - WQ4 - WP4; }
    else if (i < WQ4 + WP4 + W14 + W24) { src = fc2_w; dst = w2; off = i - WQ4 - WP4 - W14; }
    else return;
    float4 v = *(const float4*)(src + off * 4);
    store4(dst + off * 4, v);
}

// ---------------- 1) LN1 + roll(-4,-4) + window partition -> bf16 ----------------
__global__ void __launch_bounds__(256) ln1_shift_win(
        const float* __restrict__ x, const float* __restrict__ g,
        const float* __restrict__ b, bf16* __restrict__ xw) {
    int warp = threadIdx.x >> 5, lane = threadIdx.x & 31;
    int t = blockIdx.x * 8 + warp;
    int win = t >> 6, n = t & 63;
    int bi = win >> 6, wim = win & 63;
    int r = (((wim >> 3) << 3) + (n >> 3) + 4) & 63;
    int c = (((wim & 7) << 3) + (n & 7) + 4) & 63;
    const float* row = x + ((size_t)bi * 4096 + r * 64 + c) * Cc;
    float v[12]; float s = 0.f;
#pragma unroll
    for (int k = 0; k < 12; k++) { v[k] = row[lane + 32 * k]; s += v[k]; }
    s = warp_sum(s);
    float mean = s * (1.f / 384.f);
    float q = 0.f;
#pragma unroll
    for (int k = 0; k < 12; k++) { float d = v[k] - mean; q += d * d; }
    q = warp_sum(q);
    float rstd = rsqrtf(q * (1.f / 384.f) + EPSf);
    bf16* o = xw + (size_t)t * Cc;
#pragma unroll
    for (int k = 0; k < 12; k++) {
        int idx = lane + 32 * k;
        o[idx] = __float2bfloat16((v[k] - mean) * rstd * g[idx] + b[idx]);
    }
}

// ---------------- 5) un-window + roll(+4,+4) + residual + LN2 (no x1 store) ----------------
__global__ void __launch_bounds__(256) resid_ln2(
        const float* __restrict__ x, const bf16* __restrict__ proj,
        const float* __restrict__ g, const float* __restrict__ b,
        bf16* __restrict__ h) {
    int warp = threadIdx.x >> 5, lane = threadIdx.x & 31;
    int t = blockIdx.x * 8 + warp;
    int bi = t >> 12, l = t & 4095;
    int r = l >> 6, c = l & 63;
    int sr = (r - 4) & 63, sc = (c - 4) & 63;
    int win = bi * 64 + ((sr >> 3) << 3) + (sc >> 3);
    int nn = ((sr & 7) << 3) + (sc & 7);
    const bf16* pr = proj + ((size_t)win * 64 + nn) * Cc;
    const float* xr = x + (size_t)t * Cc;
    float v[12]; float s = 0.f;
#pragma unroll
    for (int k = 0; k < 12; k++) {
        int idx = lane + 32 * k;
        v[k] = xr[idx] + __bfloat162float(pr[idx]);
        s += v[k];
    }
    s = warp_sum(s);
    float mean = s * (1.f / 384.f);
    float q = 0.f;
#pragma unroll
    for (int k = 0; k < 12; k++) { float d = v[k] - mean; q += d * d; }
    q = warp_sum(q);
    float rstd = rsqrtf(q * (1.f / 384.f) + EPSf);
    bf16* o = h + (size_t)t * Cc;
#pragma unroll
    for (int k = 0; k < 12; k++) {
        int idx = lane + 32 * k;
        o[idx] = __float2bfloat16((v[k] - mean) * rstd * g[idx] + b[idx]);
    }
}

// ---------------- 3) windowed attention: one (window, head) per block ----------------
// 128 thr = 4 warps; smem 32 KB: Q[64][40] bf16 @0 | K @5120 | V @10240 | S[64][68] f32 @15360.
#define ATT_SMEM 32768
__global__ void __launch_bounds__(128) attn_win(
        const bf16* __restrict__ qkv, const float* __restrict__ rpb,
        bf16* __restrict__ outp) {
    extern __shared__ char asm_[];
    __shared__ float rps[232];
    __shared__ int labs[64];
    int win = blockIdx.x;
    int head = blockIdx.y;
    int tid = threadIdx.x;
    int warp = tid >> 5;

    bf16* Q = (bf16*)(asm_);
    bf16* K = (bf16*)(asm_ + 5120);
    bf16* V = (bf16*)(asm_ + 10240);
    float* S = (float*)(asm_ + 15360);

#pragma unroll
    for (int i = 0; i < 4; i++) {
        int id = tid + 128 * i;
        int row = id >> 3, c4 = (id & 7) * 4;
        const bf16* src = qkv + ((size_t)win * 64 + row) * (3 * Cc) + head * 32 + c4;
        *(uint2*)(Q + row * 40 + c4) = *(const uint2*)(src);
        *(uint2*)(K + row * 40 + c4) = *(const uint2*)(src + Cc);
        *(uint2*)(V + row * 40 + c4) = *(const uint2*)(src + 2 * Cc);
    }
    for (int i = tid; i < 225; i += 128) rps[i] = rpb[i * HEADS + head];
    if (tid < 64) {
        int n = tid;
        int wim = win & 63;
        int gr = ((wim >> 3) << 3) + (n >> 3);
        int gc = ((wim & 7) << 3) + (n & 7);
        labs[n] = (gr < 56 ? 0 : (gr < 60 ? 1 : 2)) * 3 + (gc < 56 ? 0 : (gc < 60 ? 1 : 2));
    }
    __syncthreads();

    // --- S = Q @ K^T (64x64x32): warp w does rows w*16..+15 ---
    {
        wmma::fragment<wmma::accumulator, 16, 16, 16, float> acc[4];
#pragma unroll
        for (int j = 0; j < 4; j++) wmma::fill_fragment(acc[j], 0.f);
#pragma unroll
        for (int kk = 0; kk < 32; kk += 16) {
            wmma::fragment<wmma::matrix_a, 16, 16, 16, bf16, wmma::row_major> fa;
            wmma::fragment<wmma::matrix_b, 16, 16, 16, bf16, wmma::col_major> fb[4];
            wmma::load_matrix_sync(fa, Q + (warp * 16) * 40 + kk, 40);
#pragma unroll
            for (int j = 0; j < 4; j++)
                wmma::load_matrix_sync(fb[j], K + (j * 16) * 40 + kk, 40);
#pragma unroll
            for (int j = 0; j < 4; j++)
                wmma::mma_sync(acc[j], fa, fb[j], acc[j]);
        }
#pragma unroll
        for (int j = 0; j < 4; j++)
            wmma::store_matrix_sync(S + (warp * 16) * 68 + j * 16, acc[j], 68,
                                    wmma::mem_row_major);
    }
    __syncthreads();

    // --- softmax: threads 0..63, one row each; float4 LDS; write P (bf16) over Q/K ---
    if (tid < 64) {
        int n = tid;
        bf16* P = (bf16*)asm_;
        const float SC = 0.17677669529663687f;   // 1/sqrt(32)
        int cvn = 15 * (n >> 3) + (n & 7);
        int myl = labs[n];
        float s[64];
        float mx = -1e30f;
#pragma unroll
        for (int m = 0; m < 64; m += 4) {
            float4 sv = *(const float4*)(S + n * 68 + m);
#pragma unroll
            for (int u = 0; u < 4; u++) {
                int mm = 63 - (m + u);
                int cvm = 15 * (mm >> 3) + (mm & 7);
                float a = (u == 0 ? sv.x : u == 1 ? sv.y : u == 2 ? sv.z : sv.w);
                a = a * SC + rps[cvn + cvm];
                a += (labs[m + u] != myl) ? -100.f : 0.f;
                s[m + u] = a;
                mx = fmaxf(mx, a);
            }
        }
        float sum = 0.f;
#pragma unroll
        for (int m = 0; m < 64; m++) { float e = __expf(s[m] - mx); s[m] = e; sum += e; }
        float inv = 1.f / sum;
#pragma unroll
        for (int m = 0; m < 64; m += 2) {
            __nv_bfloat162 pr2 = __floats2bfloat162_rn(s[m] * inv, s[m + 1] * inv);
            *(__nv_bfloat162*)(P + n * 72 + m) = pr2;
        }
    }
    __syncthreads();

    // --- O = P @ V (64x32x64): warp w rows w*16..+15; result into S ---
    {
        bf16* P = (bf16*)asm_;
        wmma::fragment<wmma::accumulator, 16, 16, 16, float> acc[2];
#pragma unroll
        for (int j = 0; j < 2; j++) wmma::fill_fragment(acc[j], 0.f);
#pragma unroll
        for (int kk = 0; kk < 64; kk += 16) {
            wmma::fragment<wmma::matrix_a, 16, 16, 16, bf16, wmma::row_major> fa;
            wmma::fragment<wmma::matrix_b, 16, 16, 16, bf16, wmma::row_major> fb[2];
            wmma::load_matrix_sync(fa, P + (warp * 16) * 72 + kk, 72);
#pragma unroll
            for (int j = 0; j < 2; j++)
                wmma::load_matrix_sync(fb[j], V + kk * 40 + j * 16, 40);
#pragma unroll
            for (int j = 0; j < 2; j++)
                wmma::mma_sync(acc[j], fa, fb[j], acc[j]);
        }
#pragma unroll
        for (int j = 0; j < 2; j++)
            wmma::store_matrix_sync(S + (warp * 16) * 68 + j * 16, acc[j], 68,
                                    wmma::mem_row_major);
    }
    __syncthreads();

#pragma unroll
    for (int i = 0; i < 4; i++) {
        int id = tid + 128 * i;
        int row = id >> 3, c4 = (id & 7) * 4;
        float4 v = *(const float4*)(S + row * 68 + c4);
        store4(outp + ((size_t)win * 64 + row) * Cc + head * 32 + c4, v);
    }
}

// ---------------- bf16 tensor-core GEMM, 2-stage cp.async, 3 CTAs/SM ----------------
// MODE 0: +bias  1: gelu(bn(+bias))
// MODE 2: gelu(bn(+bias)) + (x + unwindow(pj))  — recomputes the residual in-epilogue
template <int MODE, typename OUTT>
__global__ void __launch_bounds__(128, 3) hgemm(
        const bf16* __restrict__ A, const bf16* __restrict__ Wt,
        OUTT* __restrict__ Co, const float* __restrict__ bias,
        const float* __restrict__ bng, const float* __restrict__ bnb,
        const float* __restrict__ resx, const bf16* __restrict__ respj,
        int M, int Nn, int K) {
    extern __shared__ char smraw[];
    bf16* smh = (bf16*)smraw;
    bf16* Abuf[2] = { smh, smh + 2 * 128 * LDAH };
    bf16* Bbuf[2] = { smh + 128 * LDAH, smh + 3 * 128 * LDAH };

    int tid = threadIdx.x;
    int warp = tid >> 5;
    int wm = warp >> 1;
    int wn = warp & 1;
    int rowA = blockIdx.y * 128;
    int rowB = blockIdx.x * 128;

    wmma::fragment<wmma::accumulator, 16, 16, 16, float> acc[4][4];
#pragma unroll
    for (int i = 0; i < 4; i++)
#pragma unroll
        for (int j = 0; j < 4; j++) wmma::fill_fragment(acc[i][j], 0.f);

    int lrow = tid >> 3, lc = (tid & 7) * 8;
    const bf16* Ag = A  + (size_t)(rowA + lrow) * K + lc;
    const bf16* Bg = Wt + (size_t)(rowB + lrow) * K + lc;
    int nk = K >> 6;

    // prologue: stage 0
#pragma unroll
    for (int r = 0; r < 8; r++) {
        cpa16(Abuf[0] + (lrow + 16 * r) * LDAH + lc, Ag + (size_t)(16 * r) * K);
        cpa16(Bbuf[0] + (lrow + 16 * r) * LDAH + lc, Bg + (size_t)(16 * r) * K);
    }
    cpa_commit();

    for (int s = 0; s < nk; s++) {
        int cur = s & 1;
        if (s + 1 < nk) {
            int nb = cur ^ 1;
            int k0 = (s + 1) << 6;
#pragma unroll
            for (int r = 0; r < 8; r++) {
                cpa16(Abuf[nb] + (lrow + 16 * r) * LDAH + lc, Ag + (size_t)(16 * r) * K + k0);
                cpa16(Bbuf[nb] + (lrow + 16 * r) * LDAH + lc, Bg + (size_t)(16 * r) * K + k0);
            }
            cpa_commit();
            cpa_wait<1>();
        } else {
            cpa_wait<0>();
        }
        __syncthreads();
#pragma unroll
        for (int kk = 0; kk < 64; kk += 16) {
            wmma::fragment<wmma::matrix_a, 16, 16, 16, bf16, wmma::row_major> fa[4];
            wmma::fragment<wmma::matrix_b, 16, 16, 16, bf16, wmma::col_major> fb[4];
#pragma unroll
            for (int i = 0; i < 4; i++)
                wmma::load_matrix_sync(fa[i], Abuf[cur] + (wm * 64 + i * 16) * LDAH + kk, LDAH);
#pragma unroll
            for (int j = 0; j < 4; j++)
                wmma::load_matrix_sync(fb[j], Bbuf[cur] + (wn * 64 + j * 16) * LDAH + kk, LDAH);
#pragma unroll
            for (int i = 0; i < 4; i++)
#pragma unroll
                for (int j = 0; j < 4; j++)
                    wmma::mma_sync(acc[i][j], fa[i], fb[j], acc[i][j]);
        }
        __syncthreads();
    }

    // epilogue through fp32 smem C tile (reuses stage buffers)
    float* Cs = (float*)smraw;
#pragma unroll
    for (int i = 0; i < 4; i++)
#pragma unroll
        for (int j = 0; j < 4; j++)
            wmma::store_matrix_sync(Cs + (wm * 64 + i * 16) * LDC + wn * 64 + j * 16,
                                    acc[i][j], LDC, wmma::mem_row_major);
    __syncthreads();

    const float IS = rsqrtf(1.0f + EPSf);
    int q = tid & 31;
    int r0 = tid >> 5;
    int ncol = rowB + q * 4;
    float4 bv = *(const float4*)(bias + ncol);
    float4 gv = make_float4(0.f, 0.f, 0.f, 0.f), bb = gv;
    if (MODE >= 1) {
        gv = *(const float4*)(bng + ncol);
        bb = *(const float4*)(bnb + ncol);
        gv.x *= IS; gv.y *= IS; gv.z *= IS; gv.w *= IS;
    }
#pragma unroll
    for (int it = 0; it < 32; it++) {
        int r = r0 + it * 4;
        float4 v = *(const float4*)(Cs + r * LDC + q * 4);
        v.x += bv.x; v.y += bv.y; v.z += bv.z; v.w += bv.w;
        if (MODE >= 1) {
            v.x = gelu_fast(v.x * gv.x + bb.x);
            v.y = gelu_fast(v.y * gv.y + bb.y);
            v.z = gelu_fast(v.z * gv.z + bb.z);
            v.w = gelu_fast(v.w * gv.w + bb.w);
        }
        size_t off = (size_t)(rowA + r) * Nn + ncol;
        if (MODE == 2) {
            int t = rowA + r;
            int bi = t >> 12, l = t & 4095;
            int rr = l >> 6, cc = l & 63;
            int sr = (rr - 4) & 63, sc = (cc - 4) & 63;
            int win = bi * 64 + ((sr >> 3) << 3) + (sc >> 3);
            int nn = ((sr & 7) << 3) + (sc & 7);
            float4 xv = *(const float4*)(resx + off);
            float4 pv = load4bf(respj + ((size_t)win * 64 + nn) * Cc + ncol);
            v.x += xv.x + pv.x; v.y += xv.y + pv.y;
            v.z += xv.z + pv.z; v.w += xv.w + pv.w;
        }
        store4(Co + off, v);
    }
}

// ---------------- 7) NHWC depthwise 3x3 + BN + GELU, 4 pixels/thread ----------------
__global__ void __launch_bounds__(256) dwconv_bn_gelu(
        const bf16* __restrict__ z1, const float* __restrict__ wt,
        const float* __restrict__ wb, const float* __restrict__ bng,
        const float* __restrict__ bnb, bf16* __restrict__ z2) {
    __shared__ float ws[9][4][32];
    int c4l = threadIdx.x & 31;
    int p   = threadIdx.x >> 5;              // 0..7
    int ch  = (blockIdx.y * 32 + c4l) * 4;
    for (int i = threadIdx.x; i < 1152; i += 256) {
        int cc = i & 31;
        int l  = (i >> 5) & 3;
        int k  = i >> 7;
        ws[k][l][cc] = wt[(((blockIdx.y * 32 + cc) * 4) + l) * 9 + k];
    }
    __syncthreads();

    int pixbase = blockIdx.x * 32 + p * 4;
    int bi = pixbase >> 12; int rc = pixbase & 4095;
    int r = rc >> 6, c = rc & 63;
    float4 acc[4];
#pragma unroll
    for (int i = 0; i < 4; i++) acc[i] = make_float4(0.f, 0.f, 0.f, 0.f);

#pragma unroll
    for (int dr = -1; dr <= 1; dr++) {
        int rr = r + dr;
        if (rr < 0 || rr > 63) continue;
        const bf16* rowp = z1 + ((size_t)(bi * 4096 + rr * 64)) * HIDc + ch;
        int kb = (dr + 1) * 3;
#pragma unroll
        for (int j = -1; j <= 4; j++) {
            int cc = c + j;
            if (cc < 0 || cc > 63) continue;
            float4 v = load4bf(rowp + (size_t)cc * HIDc);
#pragma unroll
            for (int i = 0; i < 4; i++) {
                int d = j - i;
                if (d < -1 || d > 1) continue;
                int k = kb + d + 1;
                acc[i].x += v.x * ws[k][0][c4l];
                acc[i].y += v.y * ws[k][1][c4l];
                acc[i].z += v.z * ws[k][2][c4l];
                acc[i].w += v.w * ws[k][3][c4l];
            }
        }
    }
    const float IS = rsqrtf(1.0f + EPSf);
    float b0 = wb[ch + 0], b1 = wb[ch + 1], b2 = wb[ch + 2], b3 = wb[ch + 3];
    float g0 = bng[ch + 0] * IS, g1 = bng[ch + 1] * IS, g2 = bng[ch + 2] * IS, g3 = bng[ch + 3] * IS;
    float c0 = bnb[ch + 0], c1 = bnb[ch + 1], c2 = bnb[ch + 2], c3 = bnb[ch + 3];
#pragma unroll
    for (int i = 0; i < 4; i++) {
        float4 o;
        o.x = gelu_fast((acc[i].x + b0) * g0 + c0);
        o.y = gelu_fast((acc[i].y + b1) * g1 + c1);
        o.z = gelu_fast((acc[i].z + b2) * g2 + c2);
        o.w = gelu_fast((acc[i].w + b3) * g3 + c3);
        store4(z2 + (size_t)(pixbase + i) * HIDc + ch, o);
    }
}

// ---------------- launcher ----------------
extern "C" void kernel_launch(void* const* d_in, const int* in_sizes, int n_in,
                              void* d_out, int out_size) {
    (void)in_sizes; (void)n_in; (void)out_size;
    const float* x      = (const float*)d_in[0];
    const float* ln1_g  = (const float*)d_in[3];
    const float* ln1_b  = (const float*)d_in[4];
    const float* qkv_w  = (const float*)d_in[5];
    const float* qkv_b  = (const float*)d_in[6];
    const float* rpb    = (const float*)d_in[7];
    const float* proj_w = (const float*)d_in[8];
    const float* proj_b = (const float*)d_in[9];
    const float* ln2_g  = (const float*)d_in[10];
    const float* ln2_b  = (const float*)d_in[11];
    const float* fc1_w  = (const float*)d_in[12];
    const float* fc1_b  = (const float*)d_in[13];
    const float* bn1_g  = (const float*)d_in[14];
    const float* bn1_b  = (const float*)d_in[15];
    const float* dw_w   = (const float*)d_in[16];
    const float* dw_b   = (const float*)d_in[17];
    const float* bn2_g  = (const float*)d_in[18];
    const float* bn2_b  = (const float*)d_in[19];
    const float* fc2_w  = (const float*)d_in[20];
    const float* fc2_b  = (const float*)d_in[21];
    const float* bn3_g  = (const float*)d_in[22];
    const float* bn3_b  = (const float*)d_in[23];
    float* out = (float*)d_out;

    bf16 *xw, *qkvb, *at, *pj, *h, *z1, *z2, *wq, *wp, *w1, *w2;
    cudaGetSymbolAddress((void**)&xw,   g_xw);
    cudaGetSymbolAddress((void**)&qkvb, g_qkv);
    cudaGetSymbolAddress((void**)&at,   g_at);
    cudaGetSymbolAddress((void**)&pj,   g_pj);
    cudaGetSymbolAddress((void**)&h,    g_h);
    cudaGetSymbolAddress((void**)&z1,   g_z1);
    cudaGetSymbolAddress((void**)&z2,   g_z2);
    cudaGetSymbolAddress((void**)&wq,   g_wq);
    cudaGetSymbolAddress((void**)&wp,   g_wp);
    cudaGetSymbolAddress((void**)&w1,   g_w1);
    cudaGetSymbolAddress((void**)&w2,   g_w2);

    cudaFuncSetAttribute((const void*)hgemm<0, bf16>,  cudaFuncAttributeMaxDynamicSharedMemorySize, SMEMB);
    cudaFuncSetAttribute((const void*)hgemm<1, bf16>,  cudaFuncAttributeMaxDynamicSharedMemorySize, SMEMB);
    cudaFuncSetAttribute((const void*)hgemm<2, float>, cudaFuncAttributeMaxDynamicSharedMemorySize, SMEMB);
    cudaFuncSetAttribute((const void*)attn_win, cudaFuncAttributeMaxDynamicSharedMemorySize, ATT_SMEM);

    f2bf_all<<<(WQ4 + WP4 + W14 + W24 + 255) / 256, 256>>>(qkv_w, proj_w, fc1_w, fc2_w,
                                                           wq, wp, w1, w2);

    ln1_shift_win<<<Tt / 8, 256>>>(x, ln1_g, ln1_b, xw);
    hgemm<0, bf16><<<dim3(1152 / 128, Tt / 128), 128, SMEMB>>>(xw, wq, qkvb, qkv_b,
                                                  nullptr, nullptr, nullptr, nullptr, Tt, 1152, Cc);
    attn_win<<<dim3(1024, HEADS), 128, ATT_SMEM>>>(qkvb, rpb, at);
    hgemm<0, bf16><<<dim3(384 / 128, Tt / 128), 128, SMEMB>>>(at, wp, pj, proj_b,
                                                 nullptr, nullptr, nullptr, nullptr, Tt, Cc, Cc);
    resid_ln2<<<Tt / 8, 256>>>(x, pj, ln2_g, ln2_b, h);
    hgemm<1, bf16><<<dim3(HIDc / 128, Tt / 128), 128, SMEMB>>>(h, w1, z1, fc1_b,
                                                  bn1_g, bn1_b, nullptr, nullptr, Tt, HIDc, Cc);
    dwconv_bn_gelu<<<dim3(Tt / 32, HIDc / 4 / 32), 256>>>(z1, dw_w, dw_b, bn2_g, bn2_b, z2);
    hgemm<2, float><<<dim3(384 / 128, Tt / 128), 128, SMEMB>>>(z2, w2, out, fc2_b,
                                                 bn3_g, bn3_b, x, pj, Tt, Cc, HIDc);
}